// round 11
// baseline (speedup 1.0000x reference)
#include <cuda_runtime.h>
#include <math.h>
#include <stdint.h>

#define NB 4
#define SEQ 128
#define DL 128
#define DM 16
#define SO 120
#define ROWS (NB*SEQ)        // 512

// ---------------- scratch ----------------------------------------------------
__device__ float g_Q[ROWS*DL];
__device__ float g_K[ROWS*DL];
__device__ float g_U[ROWS*256];
__device__ float g_attn[NB*SEQ*SEQ];
__device__ float g_lie[(size_t)NB*SEQ*SEQ*SO];   // 31.5 MB
__device__ float g_settled[ROWS*DM];
__device__ float g_W2h[256*128];                 // W2^T tf32 hi, [k][c]
__device__ float g_W2l[256*128];                 // W2^T tf32 lo, [k][c]

__constant__ int c_tri_r[120] = {
 0,0,0,0,0,0,0,0,0,0,0,0,0,0,0,
 1,1,1,1,1,1,1,1,1,1,1,1,1,1,
 2,2,2,2,2,2,2,2,2,2,2,2,2,
 3,3,3,3,3,3,3,3,3,3,3,3,
 4,4,4,4,4,4,4,4,4,4,4,
 5,5,5,5,5,5,5,5,5,5,
 6,6,6,6,6,6,6,6,6,
 7,7,7,7,7,7,7,7,
 8,8,8,8,8,8,8,
 9,9,9,9,9,9,
 10,10,10,10,10,
 11,11,11,11,
 12,12,12,
 13,13,
 14};
__constant__ int c_tri_c[120] = {
 1,2,3,4,5,6,7,8,9,10,11,12,13,14,15,
 2,3,4,5,6,7,8,9,10,11,12,13,14,15,
 3,4,5,6,7,8,9,10,11,12,13,14,15,
 4,5,6,7,8,9,10,11,12,13,14,15,
 5,6,7,8,9,10,11,12,13,14,15,
 6,7,8,9,10,11,12,13,14,15,
 7,8,9,10,11,12,13,14,15,
 8,9,10,11,12,13,14,15,
 9,10,11,12,13,14,15,
 10,11,12,13,14,15,
 11,12,13,14,15,
 12,13,14,15,
 13,14,15,
 14,15,
 15};

__device__ __forceinline__ float ftanh(float x) {
    float y;
    asm("tanh.approx.f32 %0, %1;" : "=f"(y) : "f"(x));
    return y;
}

__device__ __forceinline__ unsigned f2tf(float x) {
    unsigned r; asm("cvt.rna.tf32.f32 %0, %1;" : "=r"(r) : "f"(x)); return r;
}

__device__ __forceinline__ void mma8(float* d, const unsigned* a, const unsigned* b) {
    asm("mma.sync.aligned.m16n8k8.row.col.f32.tf32.tf32.f32 "
        "{%0,%1,%2,%3}, {%4,%5,%6,%7}, {%8,%9}, {%0,%1,%2,%3};"
        : "+f"(d[0]), "+f"(d[1]), "+f"(d[2]), "+f"(d[3])
        : "r"(a[0]), "r"(a[1]), "r"(a[2]), "r"(a[3]), "r"(b[0]), "r"(b[1]));
}

// ---------------- kernel A: tiled GEMM  C[512 x 512] = X @ [Wq;Wk;W1]^T ----
__global__ void __launch_bounds__(256)
prep_kernel(const float* __restrict__ xl,
            const float* __restrict__ Wq, const float* __restrict__ bq,
            const float* __restrict__ Wk, const float* __restrict__ bk,
            const float* __restrict__ W1)
{
    __shared__ __align__(16) float Xs[64*64];
    __shared__ __align__(16) float Wt[64*68];

    int bx = blockIdx.x, by = blockIdx.y;
    int t  = threadIdx.x;
    int tx = t & 15, ty = t >> 4;

    const float* src;
    if      (by < 2) src = Wq + (by    )*64*DL;
    else if (by < 4) src = Wk + (by - 2)*64*DL;
    else             src = W1 + (by - 4)*64*DL;

    float acc[4][4];
    #pragma unroll
    for (int i = 0; i < 4; i++)
        #pragma unroll
        for (int j = 0; j < 4; j++) acc[i][j] = 0.f;

    for (int k0 = 0; k0 < DL; k0 += 64) {
        __syncthreads();
        #pragma unroll
        for (int s = 0; s < 16; s++) {
            int idx = t + 256*s;
            int r = idx >> 6, k = idx & 63;
            Xs[r*64 + k] = xl[(bx*64 + r)*DL + k0 + k];
            Wt[k*68 + r] = src[r*DL + k0 + k];
        }
        __syncthreads();

        #pragma unroll 8
        for (int k = 0; k < 64; k++) {
            float4 bv = *(const float4*)&Wt[k*68 + tx*4];
            #pragma unroll
            for (int i = 0; i < 4; i++) {
                float a = Xs[(ty*4 + i)*64 + k];
                acc[i][0] = fmaf(a, bv.x, acc[i][0]);
                acc[i][1] = fmaf(a, bv.y, acc[i][1]);
                acc[i][2] = fmaf(a, bv.z, acc[i][2]);
                acc[i][3] = fmaf(a, bv.w, acc[i][3]);
            }
        }
    }

    #pragma unroll
    for (int i = 0; i < 4; i++) {
        int rowg = bx*64 + ty*4 + i;
        int c0   = tx*4;
        if (by < 2) {
            int col = by*64 + c0;
            *(float4*)&g_Q[rowg*DL + col] =
                make_float4(acc[i][0]+bq[col], acc[i][1]+bq[col+1],
                            acc[i][2]+bq[col+2], acc[i][3]+bq[col+3]);
        } else if (by < 4) {
            int col = (by-2)*64 + c0;
            *(float4*)&g_K[rowg*DL + col] =
                make_float4(acc[i][0]+bk[col], acc[i][1]+bk[col+1],
                            acc[i][2]+bk[col+2], acc[i][3]+bk[col+3]);
        } else {
            int col = (by-4)*64 + c0;
            *(float4*)&g_U[rowg*256 + col] =
                make_float4(acc[i][0], acc[i][1], acc[i][2], acc[i][3]);
        }
    }
}

// ---------------- kernel A2: split W2^T into tf32 hi/lo, [k][c] layout -----
__global__ void __launch_bounds__(256)
w2split_kernel(const float* __restrict__ W2)
{
    int idx = blockIdx.x*256 + threadIdx.x;   // 32768 = 256 k x 128 c
    int k = idx >> 7, c = idx & 127;
    float v = (c < SO) ? W2[c*256 + k] : 0.f;
    unsigned h = f2tf(v);
    g_W2h[idx] = __uint_as_float(h);
    g_W2l[idx] = __uint_as_float(f2tf(v - __uint_as_float(h)));
}

// ---------------- kernel B: attention softmax (+ zero g_settled) -----------
#define AT_QS 0
#define AT_KT (AT_QS + 32*128)
#define AT_S  (AT_KT + 128*132)
#define AT_FLOATS (AT_S + 32*132)
#define AT_BYTES  (AT_FLOATS*4)

__global__ void __launch_bounds__(256)
attn_kernel()
{
    extern __shared__ float sm[];
    float* Qs = sm + AT_QS;
    float* Kt = sm + AT_KT;
    float* S  = sm + AT_S;

    int b  = blockIdx.x >> 2;
    int jt = (blockIdx.x & 3) * 32;
    int t  = threadIdx.x;
    int tx = t & 15, ty = t >> 4;

    for (int z = t; z < 512; z += 256) g_settled[blockIdx.x*512 + z] = 0.f;

    for (int idx = t; idx < 32*128; idx += 256) {
        int j = idx >> 7, k = idx & 127;
        Qs[j*128 + k] = g_Q[(b*SEQ + jt + j)*DL + k];
    }
    for (int idx = t; idx < 128*128; idx += 256) {
        int i = idx >> 7, k = idx & 127;
        Kt[k*132 + i] = g_K[(b*SEQ + i)*DL + k];
    }
    __syncthreads();

    float acc[2][8];
    #pragma unroll
    for (int i = 0; i < 2; i++)
        #pragma unroll
        for (int j = 0; j < 8; j++) acc[i][j] = 0.f;

    int j0 = ty*2, i0 = tx*8;
    #pragma unroll 4
    for (int k = 0; k < 128; k++) {
        float q0 = Qs[(j0  )*128 + k];
        float q1 = Qs[(j0+1)*128 + k];
        float4 k0v = *(const float4*)&Kt[k*132 + i0];
        float4 k1v = *(const float4*)&Kt[k*132 + i0 + 4];
        acc[0][0]=fmaf(q0,k0v.x,acc[0][0]); acc[0][1]=fmaf(q0,k0v.y,acc[0][1]);
        acc[0][2]=fmaf(q0,k0v.z,acc[0][2]); acc[0][3]=fmaf(q0,k0v.w,acc[0][3]);
        acc[0][4]=fmaf(q0,k1v.x,acc[0][4]); acc[0][5]=fmaf(q0,k1v.y,acc[0][5]);
        acc[0][6]=fmaf(q0,k1v.z,acc[0][6]); acc[0][7]=fmaf(q0,k1v.w,acc[0][7]);
        acc[1][0]=fmaf(q1,k0v.x,acc[1][0]); acc[1][1]=fmaf(q1,k0v.y,acc[1][1]);
        acc[1][2]=fmaf(q1,k0v.z,acc[1][2]); acc[1][3]=fmaf(q1,k0v.w,acc[1][3]);
        acc[1][4]=fmaf(q1,k1v.x,acc[1][4]); acc[1][5]=fmaf(q1,k1v.y,acc[1][5]);
        acc[1][6]=fmaf(q1,k1v.z,acc[1][6]); acc[1][7]=fmaf(q1,k1v.w,acc[1][7]);
    }
    const float sc = 0.08838834764831845f;
    #pragma unroll
    for (int i = 0; i < 2; i++) {
        *(float4*)&S[(j0+i)*132 + i0] =
            make_float4(acc[i][0]*sc, acc[i][1]*sc, acc[i][2]*sc, acc[i][3]*sc);
        *(float4*)&S[(j0+i)*132 + i0 + 4] =
            make_float4(acc[i][4]*sc, acc[i][5]*sc, acc[i][6]*sc, acc[i][7]*sc);
    }
    __syncthreads();

    int w = t >> 5, lane = t & 31;
    for (int q = 0; q < 4; q++) {
        int r = w*4 + q;
        float v0 = S[r*132 + lane      ];
        float v1 = S[r*132 + lane + 32 ];
        float v2 = S[r*132 + lane + 64 ];
        float v3 = S[r*132 + lane + 96 ];
        float mx = fmaxf(fmaxf(v0,v1), fmaxf(v2,v3));
        #pragma unroll
        for (int off = 16; off; off >>= 1)
            mx = fmaxf(mx, __shfl_xor_sync(0xffffffffu, mx, off));
        float e0 = expf(v0-mx), e1 = expf(v1-mx), e2 = expf(v2-mx), e3 = expf(v3-mx);
        float sum = e0+e1+e2+e3;
        #pragma unroll
        for (int off = 16; off; off >>= 1)
            sum += __shfl_xor_sync(0xffffffffu, sum, off);
        float inv = 1.f/sum;
        float* dst = g_attn + (b*SEQ + jt + r)*SEQ;
        dst[lane     ] = e0*inv;
        dst[lane + 32] = e1*inv;
        dst[lane + 64] = e2*inv;
        dst[lane + 96] = e3*inv;
    }
}

// ---------------- kernel C: pairwise MLP GEMM via 3xTF32 MMA (v2) ----------
// Block = (b, j, i-half): C[64 i x 120 c]. Grid 1024.
// 8 warps: warp w -> i-tile (w>>1) of 4, n-half (w&1).
// smem floats: Ujb[256] | b2s[128] | Hs[64*36] | Bp[32*132 float2 interleaved hi/lo]
#define PK_UJB 0
#define PK_B2  (PK_UJB + 256)
#define PK_H   (PK_B2 + 128)
#define PK_BP  (PK_H + 64*36)          // float2 region starts here
#define PK_FLOATS (PK_BP + 32*132*2)
#define PK_BYTES  (PK_FLOATS*4)

__global__ void __launch_bounds__(256, 3)
pair_kernel(const float* __restrict__ b1, const float* __restrict__ b2)
{
    extern __shared__ float psm[];
    float*  Ujb = psm + PK_UJB;
    float*  b2s = psm + PK_B2;
    float*  Hs  = psm + PK_H;
    float2* Bp  = (float2*)(psm + PK_BP);

    int bi  = blockIdx.x;
    int row = bi >> 1;             // b*128 + j
    int ih  = bi & 1;              // i-half
    int b   = row >> 7;
    int t   = threadIdx.x;
    int lane = t & 31, w = t >> 5;
    int g = lane >> 2, tt = lane & 3;
    int it = w >> 1;               // i-tile 0..3 (16 rows each)
    int nh = w & 1;                // n-half
    int ibase = it * 16;
    int irow0 = ih * 64;
    int ntiles = nh ? 7 : 8;
    int nbase  = nh * 8;

    Ujb[t] = g_U[row*256 + t] + b1[t];
    if (t < 128) b2s[t] = (t < SO) ? b2[t] : 0.f;

    float acc[8][4];
    #pragma unroll
    for (int n = 0; n < 8; n++)
        #pragma unroll
        for (int q = 0; q < 4; q++) acc[n][q] = 0.f;

    for (int k0 = 0; k0 < 256; k0 += 32) {
        __syncthreads();
        #pragma unroll
        for (int s = 0; s < 8; s++) {        // 2048 H elems
            int idx = t + 256*s;
            int i = idx >> 5, k = idx & 31;
            Hs[i*36 + k] = ftanh(Ujb[k0 + k] - g_U[(b*SEQ + irow0 + i)*256 + k0 + k]);
        }
        #pragma unroll
        for (int s = 0; s < 16; s++) {       // 4096 float2 B elems
            int idx = t + 256*s;
            int k = idx >> 7, c = idx & 127;
            Bp[k*132 + c] = make_float2(g_W2h[(k0 + k)*128 + c],
                                        g_W2l[(k0 + k)*128 + c]);
        }
        __syncthreads();

        #pragma unroll
        for (int s = 0; s < 4; s++) {
            float v0 = Hs[(ibase+g  )*36 + 8*s + tt];
            float v1 = Hs[(ibase+g+8)*36 + 8*s + tt];
            float v2 = Hs[(ibase+g  )*36 + 8*s + tt + 4];
            float v3 = Hs[(ibase+g+8)*36 + 8*s + tt + 4];
            unsigned ah[4], al[4];
            ah[0]=f2tf(v0); al[0]=f2tf(v0-__uint_as_float(ah[0]));
            ah[1]=f2tf(v1); al[1]=f2tf(v1-__uint_as_float(ah[1]));
            ah[2]=f2tf(v2); al[2]=f2tf(v2-__uint_as_float(ah[2]));
            ah[3]=f2tf(v3); al[3]=f2tf(v3-__uint_as_float(ah[3]));
            int kr0 = (8*s + tt    )*132;
            int kr1 = (8*s + tt + 4)*132;
            #pragma unroll
            for (int n = 0; n < 8; n++) {
                if (nh && n == 7) break;
                int c = (nbase + n)*8 + g;
                float2 p0 = Bp[kr0 + c];
                float2 p1 = Bp[kr1 + c];
                unsigned bh[2] = { __float_as_uint(p0.x), __float_as_uint(p1.x) };
                unsigned bl[2] = { __float_as_uint(p0.y), __float_as_uint(p1.y) };
                mma8(acc[n], ah, bl);
                mma8(acc[n], al, bh);
                mma8(acc[n], ah, bh);
            }
        }
    }

    // epilogue: bias + store
    size_t p0 = (size_t)row*SEQ + irow0 + ibase + g;
    size_t p1 = p0 + 8;
    #pragma unroll
    for (int n = 0; n < 8; n++) {
        if (nh && n == 7) break;
        int c = (nbase + n)*8 + 2*tt;
        float bb0 = b2s[c], bb1 = b2s[c+1];
        *(float2*)&g_lie[p0*SO + c] = make_float2(acc[n][0] + bb0, acc[n][1] + bb1);
        *(float2*)&g_lie[p1*SO + c] = make_float2(acc[n][2] + bb0, acc[n][3] + bb1);
    }
}

// ---------------- expm helpers: pre-split hi/lo buffers --------------------
struct AFrag { unsigned h[2][4]; unsigned l[2][4]; };

// load A-fragment from split buffers (no cvt)
__device__ __forceinline__ void load_af2(const float* Mh, const float* Ml,
                                         int g, int t, AFrag& f) {
    #pragma unroll
    for (int s = 0; s < 2; s++) {
        f.h[s][0] = __float_as_uint(Mh[(g  )*20 + t     + 8*s]);
        f.h[s][1] = __float_as_uint(Mh[(g+8)*20 + t     + 8*s]);
        f.h[s][2] = __float_as_uint(Mh[(g  )*20 + t + 4 + 8*s]);
        f.h[s][3] = __float_as_uint(Mh[(g+8)*20 + t + 4 + 8*s]);
        f.l[s][0] = __float_as_uint(Ml[(g  )*20 + t     + 8*s]);
        f.l[s][1] = __float_as_uint(Ml[(g+8)*20 + t     + 8*s]);
        f.l[s][2] = __float_as_uint(Ml[(g  )*20 + t + 4 + 8*s]);
        f.l[s][3] = __float_as_uint(Ml[(g+8)*20 + t + 4 + 8*s]);
    }
}

// D += Afrag * Y, Y given as split hi/lo buffers (no cvt in loop)
__device__ __forceinline__ void mm16v2(float D[2][4], const AFrag& a,
                                       const float* Yh, const float* Yl,
                                       int g, int t) {
    #pragma unroll
    for (int j = 0; j < 2; j++)
        #pragma unroll
        for (int s = 0; s < 2; s++) {
            int r0 = (t     + 8*s)*20 + g + 8*j;
            int r1 = (t + 4 + 8*s)*20 + g + 8*j;
            unsigned bh[2] = { __float_as_uint(Yh[r0]), __float_as_uint(Yh[r1]) };
            unsigned bl[2] = { __float_as_uint(Yl[r0]), __float_as_uint(Yl[r1]) };
            mma8(D[j], a.h[s], bl);
            mma8(D[j], a.l[s], bh);
            mma8(D[j], a.h[s], bh);
        }
}

// split-store C-layout regs -> hi/lo stride-20 buffers
__device__ __forceinline__ void st2_cr(float* Mh, float* Ml, const float D[2][4],
                                       int g, int t) {
    float h[2][4], l[2][4];
    #pragma unroll
    for (int j = 0; j < 2; j++)
        #pragma unroll
        for (int q = 0; q < 4; q++) {
            unsigned hh = f2tf(D[j][q]);
            h[j][q] = __uint_as_float(hh);
            l[j][q] = __uint_as_float(f2tf(D[j][q] - __uint_as_float(hh)));
        }
    *(float2*)&Mh[(g  )*20 + 2*t    ] = make_float2(h[0][0], h[0][1]);
    *(float2*)&Mh[(g  )*20 + 2*t + 8] = make_float2(h[1][0], h[1][1]);
    *(float2*)&Mh[(g+8)*20 + 2*t    ] = make_float2(h[0][2], h[0][3]);
    *(float2*)&Mh[(g+8)*20 + 2*t + 8] = make_float2(h[1][2], h[1][3]);
    *(float2*)&Ml[(g  )*20 + 2*t    ] = make_float2(l[0][0], l[0][1]);
    *(float2*)&Ml[(g  )*20 + 2*t + 8] = make_float2(l[1][0], l[1][1]);
    *(float2*)&Ml[(g+8)*20 + 2*t    ] = make_float2(l[0][2], l[0][3]);
    *(float2*)&Ml[(g+8)*20 + 2*t + 8] = make_float2(l[1][2], l[1][3]);
}

// ---------------- kernel D: expm via 3xTF32 MMA, pre-split operands --------
#define EXPM_BLOCKS 1024
#define NPAIRS (NB*SEQ*SEQ)      // 65536

__global__ void __launch_bounds__(128)
expm_kernel(const float* __restrict__ xm_g, float* __restrict__ Tout)
{
    __shared__ __align__(16) float mm[4*8*320];   // 4 warps x 8 split-bufs x 320
    int tid = threadIdx.x, lane = tid & 31, w = tid >> 5;
    float* base = mm + w*2560;
    float* Ah  = base;         float* Al  = base + 320;
    float* A2h = base + 640;   float* A2l = base + 960;
    float* A3h = base + 1280;  float* A3l = base + 1600;
    float* Th  = base + 1920;  float* Tl  = base + 2240;

    int g = lane >> 2;       // row group 0..7 (rows g, g+8)
    int t = lane & 3;        // col group

    const float c3=1.f/6.f, c4=1.f/24.f, c5=1.f/120.f;
    const float c6=1.f/720.f, c7=1.f/5040.f, c8=1.f/40320.f, c9=1.f/362880.f;

    float dg[2][4];
    #pragma unroll
    for (int j = 0; j < 2; j++)
        #pragma unroll
        for (int q = 0; q < 4; q++)
            dg[j][q] = ((g + 8*(q>>1)) == (2*t + (q&1) + 8*j)) ? 1.f : 0.f;

    for (int p = blockIdx.x*4 + w; p < NPAIRS; p += EXPM_BLOCKS*4) {
        int row = p >> 7;
        int i   = p & 127;
        int b   = row >> 7;

        // ---- scatter lie -> skew A into scratch (Th) ----
        const float* lr = g_lie + (size_t)p*SO;
        if (lane < 16) Th[lane*20 + lane] = 0.f;
        #pragma unroll
        for (int q = 0; q < 4; q++) {
            int l = lane + 32*q;
            if (l < SO) {
                float v = lr[l];
                int rI = c_tri_r[l], cI = c_tri_c[l];
                Th[rI*20 + cI] =  v;
                Th[cI*20 + rI] = -v;
            }
        }
        __syncwarp();

        // ---- load A C-layout tiles from scratch, norm, scale ----
        float Acr[2][4];
        {
            float2 v;
            v = *(float2*)&Th[(g  )*20 + 2*t    ]; Acr[0][0]=v.x; Acr[0][1]=v.y;
            v = *(float2*)&Th[(g  )*20 + 2*t + 8]; Acr[1][0]=v.x; Acr[1][1]=v.y;
            v = *(float2*)&Th[(g+8)*20 + 2*t    ]; Acr[0][2]=v.x; Acr[0][3]=v.y;
            v = *(float2*)&Th[(g+8)*20 + 2*t + 8]; Acr[1][2]=v.x; Acr[1][3]=v.y;
        }
        float rs0 = fabsf(Acr[0][0])+fabsf(Acr[0][1])+fabsf(Acr[1][0])+fabsf(Acr[1][1]);
        float rs1 = fabsf(Acr[0][2])+fabsf(Acr[0][3])+fabsf(Acr[1][2])+fabsf(Acr[1][3]);
        #pragma unroll
        for (int off = 1; off <= 2; off <<= 1) {
            rs0 += __shfl_xor_sync(0xffffffffu, rs0, off);
            rs1 += __shfl_xor_sync(0xffffffffu, rs1, off);
        }
        float mx = fmaxf(rs0, rs1);
        #pragma unroll
        for (int off = 4; off <= 16; off <<= 1)
            mx = fmaxf(mx, __shfl_xor_sync(0xffffffffu, mx, off));
        int sct = 0;
        if (mx > 1.f) { sct = (int)ceilf(log2f(mx)); if (sct > 12) sct = 12; }
        float scale = __uint_as_float((uint32_t)(127 - sct) << 23);
        #pragma unroll
        for (int j = 0; j < 2; j++)
            #pragma unroll
            for (int q = 0; q < 4; q++) Acr[j][q] *= scale;
        st2_cr(Ah, Al, Acr, g, t);
        __syncwarp();

        // ---- A2 = A*A ----
        AFrag fA;
        load_af2(Ah, Al, g, t, fA);
        float A2cr[2][4] = {{0.f,0.f,0.f,0.f},{0.f,0.f,0.f,0.f}};
        mm16v2(A2cr, fA, Ah, Al, g, t);
        st2_cr(A2h, A2l, A2cr, g, t);
        __syncwarp();

        // ---- A3 = A*A2 (A-frag reuse) ----
        float A3cr[2][4] = {{0.f,0.f,0.f,0.f},{0.f,0.f,0.f,0.f}};
        mm16v2(A3cr, fA, A2h, A2l, g, t);

        // ---- B2 = c6 I + c7 A + c8 A2 + c9 A3 -> T (split) ; A3 -> split ----
        {
            float E[2][4];
            #pragma unroll
            for (int j = 0; j < 2; j++)
                #pragma unroll
                for (int q = 0; q < 4; q++)
                    E[j][q] = fmaf(c6, dg[j][q],
                              fmaf(c7, Acr[j][q],
                              fmaf(c8, A2cr[j][q], c9 * A3cr[j][q])));
            st2_cr(Th, Tl, E, g, t);
        }
        st2_cr(A3h, A3l, A3cr, g, t);
        __syncwarp();

        // ---- M = A3*B2 + (c3 I + c4 A + c5 A2) ----
        AFrag f3;
        load_af2(A3h, A3l, g, t, f3);
        float R[2][4];
        #pragma unroll
        for (int j = 0; j < 2; j++)
            #pragma unroll
            for (int q = 0; q < 4; q++)
                R[j][q] = fmaf(c3, dg[j][q],
                          fmaf(c4, Acr[j][q], c5 * A2cr[j][q]));
        mm16v2(R, f3, Th, Tl, g, t);
        __syncwarp();
        st2_cr(Th, Tl, R, g, t);
        __syncwarp();

        // ---- R = A3*M + (I + A + A2/2) ----
        #pragma unroll
        for (int j = 0; j < 2; j++)
            #pragma unroll
            for (int q = 0; q < 4; q++)
                R[j][q] = fmaf(0.5f, A2cr[j][q], Acr[j][q]) + dg[j][q];
        mm16v2(R, f3, Th, Tl, g, t);

        // ---- squarings ----
        for (int q = 0; q < sct; q++) {
            __syncwarp();
            st2_cr(Th, Tl, R, g, t);
            __syncwarp();
            AFrag fR;
            load_af2(Th, Tl, g, t, fR);
            float R2[2][4] = {{0.f,0.f,0.f,0.f},{0.f,0.f,0.f,0.f}};
            mm16v2(R2, fR, Th, Tl, g, t);
            #pragma unroll
            for (int j = 0; j < 2; j++)
                #pragma unroll
                for (int qq = 0; qq < 4; qq++) R[j][qq] = R2[j][qq];
        }

        // ---- write T_all ----
        float* dst = Tout + (size_t)p*256;
        *(float2*)&dst[(g  )*16 + 2*t    ] = make_float2(R[0][0], R[0][1]);
        *(float2*)&dst[(g  )*16 + 2*t + 8] = make_float2(R[1][0], R[1][1]);
        *(float2*)&dst[(g+8)*16 + 2*t    ] = make_float2(R[0][2], R[0][3]);
        *(float2*)&dst[(g+8)*16 + 2*t + 8] = make_float2(R[1][2], R[1][3]);

        // ---- transported & settled ----
        const float* xv = xm_g + ((size_t)b*SEQ + i)*DM;
        float x0 = xv[2*t], x1 = xv[2*t+1], x2 = xv[2*t+8], x3 = xv[2*t+9];
        float pg  = R[0][0]*x0 + R[0][1]*x1 + R[1][0]*x2 + R[1][1]*x3;
        float pg8 = R[0][2]*x0 + R[0][3]*x1 + R[1][2]*x2 + R[1][3]*x3;
        #pragma unroll
        for (int off = 1; off <= 2; off <<= 1) {
            pg  += __shfl_xor_sync(0xffffffffu, pg,  off);
            pg8 += __shfl_xor_sync(0xffffffffu, pg8, off);
        }
        if (t == 0) {
            float wgt = g_attn[row*SEQ + i];
            atomicAdd(&g_settled[row*DM + g    ], wgt * pg);
            atomicAdd(&g_settled[row*DM + g + 8], wgt * pg8);
        }
        __syncwarp();
    }
}

// ---------------- kernel E: out projection ---------------------------------
__global__ void __launch_bounds__(256)
out_kernel(const float* __restrict__ Wo, const float* __restrict__ bo,
           float* __restrict__ out)
{
    int gid = blockIdx.x*256 + threadIdx.x;    // 8192
    int row = gid >> 4, d = gid & 15;
    float acc = bo[d];
    #pragma unroll
    for (int e = 0; e < DM; e++)
        acc = fmaf(Wo[d*DM + e], g_settled[row*DM + e], acc);
    out[gid] = acc;
}

// ---------------- launch ----------------------------------------------------
extern "C" void kernel_launch(void* const* d_in, const int* in_sizes, int n_in,
                              void* d_out, int out_size)
{
    const float* xl  = (const float*)d_in[0];
    const float* xmm = (const float*)d_in[1];
    const float* Wq  = (const float*)d_in[2];
    const float* bq  = (const float*)d_in[3];
    const float* Wk  = (const float*)d_in[4];
    const float* bk  = (const float*)d_in[5];
    const float* W1  = (const float*)d_in[6];
    const float* b1  = (const float*)d_in[7];
    const float* W2  = (const float*)d_in[8];
    const float* b2  = (const float*)d_in[9];
    const float* Wo  = (const float*)d_in[10];
    const float* bo  = (const float*)d_in[11];

    float* out  = (float*)d_out;
    float* Tout = out + NB*SEQ*DM;      // T_all follows out

    static bool attr_set = false;
    if (!attr_set) {
        cudaFuncSetAttribute(attn_kernel, cudaFuncAttributeMaxDynamicSharedMemorySize, AT_BYTES);
        cudaFuncSetAttribute(pair_kernel, cudaFuncAttributeMaxDynamicSharedMemorySize, PK_BYTES);
        attr_set = true;
    }

    prep_kernel<<<dim3(8,8), 256>>>(xl, Wq, bq, Wk, bk, W1);
    w2split_kernel<<<128, 256>>>(W2);
    attn_kernel<<<16, 256, AT_BYTES>>>();
    pair_kernel<<<2*ROWS, 256, PK_BYTES>>>(b1, b2);
    expm_kernel<<<EXPM_BLOCKS, 128>>>(xmm, Tout);
    out_kernel<<<32, 256>>>(Wo, bo, out);
}

// round 12
// speedup vs baseline: 1.1426x; 1.1426x over previous
#include <cuda_runtime.h>
#include <math.h>
#include <stdint.h>

#define NB 4
#define SEQ 128
#define DL 128
#define DM 16
#define SO 120
#define ROWS (NB*SEQ)        // 512

// ---------------- scratch ----------------------------------------------------
__device__ float g_Q[ROWS*DL];
__device__ float g_K[ROWS*DL];
__device__ float g_U[ROWS*256];
__device__ float g_attn[NB*SEQ*SEQ];
__device__ float g_lie[(size_t)NB*SEQ*SEQ*SO];   // 31.5 MB
__device__ float g_settled[ROWS*DM];
__device__ float g_W2h[256*128];                 // W2^T tf32 hi, [k][c]
__device__ float g_W2l[256*128];                 // W2^T tf32 lo, [k][c]

__constant__ int c_tri_r[120] = {
 0,0,0,0,0,0,0,0,0,0,0,0,0,0,0,
 1,1,1,1,1,1,1,1,1,1,1,1,1,1,
 2,2,2,2,2,2,2,2,2,2,2,2,2,
 3,3,3,3,3,3,3,3,3,3,3,3,
 4,4,4,4,4,4,4,4,4,4,4,
 5,5,5,5,5,5,5,5,5,5,
 6,6,6,6,6,6,6,6,6,
 7,7,7,7,7,7,7,7,
 8,8,8,8,8,8,8,
 9,9,9,9,9,9,
 10,10,10,10,10,
 11,11,11,11,
 12,12,12,
 13,13,
 14};
__constant__ int c_tri_c[120] = {
 1,2,3,4,5,6,7,8,9,10,11,12,13,14,15,
 2,3,4,5,6,7,8,9,10,11,12,13,14,15,
 3,4,5,6,7,8,9,10,11,12,13,14,15,
 4,5,6,7,8,9,10,11,12,13,14,15,
 5,6,7,8,9,10,11,12,13,14,15,
 6,7,8,9,10,11,12,13,14,15,
 7,8,9,10,11,12,13,14,15,
 8,9,10,11,12,13,14,15,
 9,10,11,12,13,14,15,
 10,11,12,13,14,15,
 11,12,13,14,15,
 12,13,14,15,
 13,14,15,
 14,15,
 15};

__device__ __forceinline__ float ftanh(float x) {
    float y;
    asm("tanh.approx.f32 %0, %1;" : "=f"(y) : "f"(x));
    return y;
}

__device__ __forceinline__ unsigned f2tf(float x) {
    unsigned r; asm("cvt.rna.tf32.f32 %0, %1;" : "=r"(r) : "f"(x)); return r;
}

__device__ __forceinline__ void mma8(float* d, const unsigned* a, const unsigned* b) {
    asm("mma.sync.aligned.m16n8k8.row.col.f32.tf32.tf32.f32 "
        "{%0,%1,%2,%3}, {%4,%5,%6,%7}, {%8,%9}, {%0,%1,%2,%3};"
        : "+f"(d[0]), "+f"(d[1]), "+f"(d[2]), "+f"(d[3])
        : "r"(a[0]), "r"(a[1]), "r"(a[2]), "r"(a[3]), "r"(b[0]), "r"(b[1]));
}

// ---------------- kernel A: tiled GEMM  C[512 x 512] = X @ [Wq;Wk;W1]^T ----
__global__ void __launch_bounds__(256)
prep_kernel(const float* __restrict__ xl,
            const float* __restrict__ Wq, const float* __restrict__ bq,
            const float* __restrict__ Wk, const float* __restrict__ bk,
            const float* __restrict__ W1)
{
    __shared__ __align__(16) float Xs[64*64];
    __shared__ __align__(16) float Wt[64*68];

    int bx = blockIdx.x, by = blockIdx.y;
    int t  = threadIdx.x;
    int tx = t & 15, ty = t >> 4;

    const float* src;
    if      (by < 2) src = Wq + (by    )*64*DL;
    else if (by < 4) src = Wk + (by - 2)*64*DL;
    else             src = W1 + (by - 4)*64*DL;

    float acc[4][4];
    #pragma unroll
    for (int i = 0; i < 4; i++)
        #pragma unroll
        for (int j = 0; j < 4; j++) acc[i][j] = 0.f;

    for (int k0 = 0; k0 < DL; k0 += 64) {
        __syncthreads();
        #pragma unroll
        for (int s = 0; s < 16; s++) {
            int idx = t + 256*s;
            int r = idx >> 6, k = idx & 63;
            Xs[r*64 + k] = xl[(bx*64 + r)*DL + k0 + k];
            Wt[k*68 + r] = src[r*DL + k0 + k];
        }
        __syncthreads();

        #pragma unroll 8
        for (int k = 0; k < 64; k++) {
            float4 bv = *(const float4*)&Wt[k*68 + tx*4];
            #pragma unroll
            for (int i = 0; i < 4; i++) {
                float a = Xs[(ty*4 + i)*64 + k];
                acc[i][0] = fmaf(a, bv.x, acc[i][0]);
                acc[i][1] = fmaf(a, bv.y, acc[i][1]);
                acc[i][2] = fmaf(a, bv.z, acc[i][2]);
                acc[i][3] = fmaf(a, bv.w, acc[i][3]);
            }
        }
    }

    #pragma unroll
    for (int i = 0; i < 4; i++) {
        int rowg = bx*64 + ty*4 + i;
        int c0   = tx*4;
        if (by < 2) {
            int col = by*64 + c0;
            *(float4*)&g_Q[rowg*DL + col] =
                make_float4(acc[i][0]+bq[col], acc[i][1]+bq[col+1],
                            acc[i][2]+bq[col+2], acc[i][3]+bq[col+3]);
        } else if (by < 4) {
            int col = (by-2)*64 + c0;
            *(float4*)&g_K[rowg*DL + col] =
                make_float4(acc[i][0]+bk[col], acc[i][1]+bk[col+1],
                            acc[i][2]+bk[col+2], acc[i][3]+bk[col+3]);
        } else {
            int col = (by-4)*64 + c0;
            *(float4*)&g_U[rowg*256 + col] =
                make_float4(acc[i][0], acc[i][1], acc[i][2], acc[i][3]);
        }
    }
}

// ---------------- kernel A2: split W2^T into tf32 hi/lo, [k][c] layout -----
__global__ void __launch_bounds__(256)
w2split_kernel(const float* __restrict__ W2)
{
    int idx = blockIdx.x*256 + threadIdx.x;   // 32768 = 256 k x 128 c
    int k = idx >> 7, c = idx & 127;
    float v = (c < SO) ? W2[c*256 + k] : 0.f;
    unsigned h = f2tf(v);
    g_W2h[idx] = __uint_as_float(h);
    g_W2l[idx] = __uint_as_float(f2tf(v - __uint_as_float(h)));
}

// ---------------- kernel B: attention softmax (+ zero g_settled) -----------
#define AT_QS 0
#define AT_KT (AT_QS + 32*128)
#define AT_S  (AT_KT + 128*132)
#define AT_FLOATS (AT_S + 32*132)
#define AT_BYTES  (AT_FLOATS*4)

__global__ void __launch_bounds__(256)
attn_kernel()
{
    extern __shared__ float sm[];
    float* Qs = sm + AT_QS;
    float* Kt = sm + AT_KT;
    float* S  = sm + AT_S;

    int b  = blockIdx.x >> 2;
    int jt = (blockIdx.x & 3) * 32;
    int t  = threadIdx.x;
    int tx = t & 15, ty = t >> 4;

    for (int z = t; z < 512; z += 256) g_settled[blockIdx.x*512 + z] = 0.f;

    for (int idx = t; idx < 32*128; idx += 256) {
        int j = idx >> 7, k = idx & 127;
        Qs[j*128 + k] = g_Q[(b*SEQ + jt + j)*DL + k];
    }
    for (int idx = t; idx < 128*128; idx += 256) {
        int i = idx >> 7, k = idx & 127;
        Kt[k*132 + i] = g_K[(b*SEQ + i)*DL + k];
    }
    __syncthreads();

    float acc[2][8];
    #pragma unroll
    for (int i = 0; i < 2; i++)
        #pragma unroll
        for (int j = 0; j < 8; j++) acc[i][j] = 0.f;

    int j0 = ty*2, i0 = tx*8;
    #pragma unroll 4
    for (int k = 0; k < 128; k++) {
        float q0 = Qs[(j0  )*128 + k];
        float q1 = Qs[(j0+1)*128 + k];
        float4 k0v = *(const float4*)&Kt[k*132 + i0];
        float4 k1v = *(const float4*)&Kt[k*132 + i0 + 4];
        acc[0][0]=fmaf(q0,k0v.x,acc[0][0]); acc[0][1]=fmaf(q0,k0v.y,acc[0][1]);
        acc[0][2]=fmaf(q0,k0v.z,acc[0][2]); acc[0][3]=fmaf(q0,k0v.w,acc[0][3]);
        acc[0][4]=fmaf(q0,k1v.x,acc[0][4]); acc[0][5]=fmaf(q0,k1v.y,acc[0][5]);
        acc[0][6]=fmaf(q0,k1v.z,acc[0][6]); acc[0][7]=fmaf(q0,k1v.w,acc[0][7]);
        acc[1][0]=fmaf(q1,k0v.x,acc[1][0]); acc[1][1]=fmaf(q1,k0v.y,acc[1][1]);
        acc[1][2]=fmaf(q1,k0v.z,acc[1][2]); acc[1][3]=fmaf(q1,k0v.w,acc[1][3]);
        acc[1][4]=fmaf(q1,k1v.x,acc[1][4]); acc[1][5]=fmaf(q1,k1v.y,acc[1][5]);
        acc[1][6]=fmaf(q1,k1v.z,acc[1][6]); acc[1][7]=fmaf(q1,k1v.w,acc[1][7]);
    }
    const float sc = 0.08838834764831845f;
    #pragma unroll
    for (int i = 0; i < 2; i++) {
        *(float4*)&S[(j0+i)*132 + i0] =
            make_float4(acc[i][0]*sc, acc[i][1]*sc, acc[i][2]*sc, acc[i][3]*sc);
        *(float4*)&S[(j0+i)*132 + i0 + 4] =
            make_float4(acc[i][4]*sc, acc[i][5]*sc, acc[i][6]*sc, acc[i][7]*sc);
    }
    __syncthreads();

    int w = t >> 5, lane = t & 31;
    for (int q = 0; q < 4; q++) {
        int r = w*4 + q;
        float v0 = S[r*132 + lane      ];
        float v1 = S[r*132 + lane + 32 ];
        float v2 = S[r*132 + lane + 64 ];
        float v3 = S[r*132 + lane + 96 ];
        float mx = fmaxf(fmaxf(v0,v1), fmaxf(v2,v3));
        #pragma unroll
        for (int off = 16; off; off >>= 1)
            mx = fmaxf(mx, __shfl_xor_sync(0xffffffffu, mx, off));
        float e0 = expf(v0-mx), e1 = expf(v1-mx), e2 = expf(v2-mx), e3 = expf(v3-mx);
        float sum = e0+e1+e2+e3;
        #pragma unroll
        for (int off = 16; off; off >>= 1)
            sum += __shfl_xor_sync(0xffffffffu, sum, off);
        float inv = 1.f/sum;
        float* dst = g_attn + (b*SEQ + jt + r)*SEQ;
        dst[lane     ] = e0*inv;
        dst[lane + 32] = e1*inv;
        dst[lane + 64] = e2*inv;
        dst[lane + 96] = e3*inv;
    }
}

// ---------------- kernel C: pairwise MLP GEMM via 3xTF32 MMA (v3) ----------
// Block = (b,j): C[128 i x 120 c]. Grid 512, 512 threads = 16 warps.
// Warp w: i-tile (w & 7) of 16 rows, n-half (w >> 3).
// Staging identical to R10 (amortized over whole block), acc 32 regs/thread.
// smem floats: Ujb[256] | b2s[128] | Hs[128*36] | Bp[32*132 float2]
#define PK_UJB 0
#define PK_B2  (PK_UJB + 256)
#define PK_H   (PK_B2 + 128)
#define PK_BP  (PK_H + 128*36)
#define PK_FLOATS (PK_BP + 32*132*2)
#define PK_BYTES  (PK_FLOATS*4)

__global__ void __launch_bounds__(512, 2)
pair_kernel(const float* __restrict__ b1, const float* __restrict__ b2)
{
    extern __shared__ float psm[];
    float*  Ujb = psm + PK_UJB;
    float*  b2s = psm + PK_B2;
    float*  Hs  = psm + PK_H;
    float2* Bp  = (float2*)(psm + PK_BP);

    int row = blockIdx.x;          // b*128 + j
    int b   = row >> 7;
    int t   = threadIdx.x;
    int lane = t & 31, w = t >> 5;
    int g = lane >> 2, tt = lane & 3;
    int it = w & 7;                // i-tile 0..7
    int nh = w >> 3;               // n-half 0/1
    int ibase = it * 16;
    int nbase = nh * 8;

    if (t < 256) Ujb[t] = g_U[row*256 + t] + b1[t];
    if (t >= 256 && t < 384) { int c = t - 256; b2s[c] = (c < SO) ? b2[c] : 0.f; }

    float acc[8][4];
    #pragma unroll
    for (int n = 0; n < 8; n++)
        #pragma unroll
        for (int q = 0; q < 4; q++) acc[n][q] = 0.f;

    for (int k0 = 0; k0 < 256; k0 += 32) {
        __syncthreads();
        #pragma unroll
        for (int s = 0; s < 8; s++) {        // 4096 H elems
            int idx = t + 512*s;
            int i = idx >> 5, k = idx & 31;
            Hs[i*36 + k] = ftanh(Ujb[k0 + k] - g_U[(b*SEQ + i)*256 + k0 + k]);
        }
        #pragma unroll
        for (int s = 0; s < 8; s++) {        // 4096 float2 B elems
            int idx = t + 512*s;
            int k = idx >> 7, c = idx & 127;
            Bp[k*132 + c] = make_float2(g_W2h[(k0 + k)*128 + c],
                                        g_W2l[(k0 + k)*128 + c]);
        }
        __syncthreads();

        #pragma unroll
        for (int s = 0; s < 4; s++) {
            float v0 = Hs[(ibase+g  )*36 + 8*s + tt];
            float v1 = Hs[(ibase+g+8)*36 + 8*s + tt];
            float v2 = Hs[(ibase+g  )*36 + 8*s + tt + 4];
            float v3 = Hs[(ibase+g+8)*36 + 8*s + tt + 4];
            unsigned ah[4], al[4];
            ah[0]=f2tf(v0); al[0]=f2tf(v0-__uint_as_float(ah[0]));
            ah[1]=f2tf(v1); al[1]=f2tf(v1-__uint_as_float(ah[1]));
            ah[2]=f2tf(v2); al[2]=f2tf(v2-__uint_as_float(ah[2]));
            ah[3]=f2tf(v3); al[3]=f2tf(v3-__uint_as_float(ah[3]));
            int kr0 = (8*s + tt    )*132;
            int kr1 = (8*s + tt + 4)*132;
            #pragma unroll
            for (int n = 0; n < 8; n++) {
                if (nh && n == 7) break;
                int c = (nbase + n)*8 + g;
                float2 p0 = Bp[kr0 + c];
                float2 p1 = Bp[kr1 + c];
                unsigned bh[2] = { __float_as_uint(p0.x), __float_as_uint(p1.x) };
                unsigned bl[2] = { __float_as_uint(p0.y), __float_as_uint(p1.y) };
                mma8(acc[n], ah, bl);
                mma8(acc[n], al, bh);
                mma8(acc[n], ah, bh);
            }
        }
    }

    // epilogue: bias + store
    size_t p0 = (size_t)row*SEQ + ibase + g;
    size_t p1 = p0 + 8;
    #pragma unroll
    for (int n = 0; n < 8; n++) {
        if (nh && n == 7) break;
        int c = (nbase + n)*8 + 2*tt;
        float bb0 = b2s[c], bb1 = b2s[c+1];
        *(float2*)&g_lie[p0*SO + c] = make_float2(acc[n][0] + bb0, acc[n][1] + bb1);
        *(float2*)&g_lie[p1*SO + c] = make_float2(acc[n][2] + bb0, acc[n][3] + bb1);
    }
}

// ---------------- tf32 3x-split MMA helpers for expm (R10 proven) ----------
struct AFrag { unsigned h[2][4]; unsigned l[2][4]; };

__device__ __forceinline__ void load_af(const float* M, int g, int t, AFrag& f) {
    #pragma unroll
    for (int s = 0; s < 2; s++) {
        float v[4];
        v[0] = M[(g  )*20 + t     + 8*s];
        v[1] = M[(g+8)*20 + t     + 8*s];
        v[2] = M[(g  )*20 + t + 4 + 8*s];
        v[3] = M[(g+8)*20 + t + 4 + 8*s];
        #pragma unroll
        for (int q = 0; q < 4; q++) {
            unsigned h = f2tf(v[q]);
            f.h[s][q] = h;
            f.l[s][q] = f2tf(v[q] - __uint_as_float(h));
        }
    }
}

__device__ __forceinline__ void mm16(float D[2][4], const AFrag& a,
                                     const float* Y, int g, int t) {
    #pragma unroll
    for (int j = 0; j < 2; j++)
        #pragma unroll
        for (int s = 0; s < 2; s++) {
            float v0 = Y[(t     + 8*s)*20 + g + 8*j];
            float v1 = Y[(t + 4 + 8*s)*20 + g + 8*j];
            unsigned bh[2], bl[2];
            bh[0] = f2tf(v0); bh[1] = f2tf(v1);
            bl[0] = f2tf(v0 - __uint_as_float(bh[0]));
            bl[1] = f2tf(v1 - __uint_as_float(bh[1]));
            mma8(D[j], a.h[s], bl);
            mma8(D[j], a.l[s], bh);
            mma8(D[j], a.h[s], bh);
        }
}

__device__ __forceinline__ void st_cr(float* M, const float D[2][4], int g, int t) {
    *(float2*)&M[(g  )*20 + 2*t    ] = make_float2(D[0][0], D[0][1]);
    *(float2*)&M[(g  )*20 + 2*t + 8] = make_float2(D[1][0], D[1][1]);
    *(float2*)&M[(g+8)*20 + 2*t    ] = make_float2(D[0][2], D[0][3]);
    *(float2*)&M[(g+8)*20 + 2*t + 8] = make_float2(D[1][2], D[1][3]);
}

// ---------------- kernel D: expm via 3xTF32 tensor-core matmuls (R10) ------
#define EXPM_BLOCKS 1024
#define NPAIRS (NB*SEQ*SEQ)      // 65536

__global__ void __launch_bounds__(128)
expm_kernel(const float* __restrict__ xm_g, float* __restrict__ Tout)
{
    __shared__ __align__(16) float mm[4*4*320];   // 4 warps x (A,A2,A3,T) x 320
    int tid = threadIdx.x, lane = tid & 31, w = tid >> 5;
    float* Ab  = mm + w*1280;
    float* A2b = Ab + 320;
    float* A3b = Ab + 640;
    float* Tb  = Ab + 960;

    int g = lane >> 2;       // row group 0..7 (rows g, g+8)
    int t = lane & 3;        // col group

    const float c3=1.f/6.f, c4=1.f/24.f, c5=1.f/120.f;
    const float c6=1.f/720.f, c7=1.f/5040.f, c8=1.f/40320.f, c9=1.f/362880.f;

    float dg[2][4];
    #pragma unroll
    for (int j = 0; j < 2; j++)
        #pragma unroll
        for (int q = 0; q < 4; q++)
            dg[j][q] = ((g + 8*(q>>1)) == (2*t + (q&1) + 8*j)) ? 1.f : 0.f;

    for (int p = blockIdx.x*4 + w; p < NPAIRS; p += EXPM_BLOCKS*4) {
        int row = p >> 7;
        int i   = p & 127;
        int b   = row >> 7;

        // ---- scatter lie -> skew A ----
        const float* lr = g_lie + (size_t)p*SO;
        if (lane < 16) Ab[lane*20 + lane] = 0.f;
        #pragma unroll
        for (int q = 0; q < 4; q++) {
            int l = lane + 32*q;
            if (l < SO) {
                float v = lr[l];
                int rI = c_tri_r[l], cI = c_tri_c[l];
                Ab[rI*20 + cI] =  v;
                Ab[cI*20 + rI] = -v;
            }
        }
        __syncwarp();

        // ---- load A C-layout, norm, scale ----
        float Acr[2][4];
        {
            float2 v;
            v = *(float2*)&Ab[(g  )*20 + 2*t    ]; Acr[0][0]=v.x; Acr[0][1]=v.y;
            v = *(float2*)&Ab[(g  )*20 + 2*t + 8]; Acr[1][0]=v.x; Acr[1][1]=v.y;
            v = *(float2*)&Ab[(g+8)*20 + 2*t    ]; Acr[0][2]=v.x; Acr[0][3]=v.y;
            v = *(float2*)&Ab[(g+8)*20 + 2*t + 8]; Acr[1][2]=v.x; Acr[1][3]=v.y;
        }
        float rs0 = fabsf(Acr[0][0])+fabsf(Acr[0][1])+fabsf(Acr[1][0])+fabsf(Acr[1][1]);
        float rs1 = fabsf(Acr[0][2])+fabsf(Acr[0][3])+fabsf(Acr[1][2])+fabsf(Acr[1][3]);
        #pragma unroll
        for (int off = 1; off <= 2; off <<= 1) {
            rs0 += __shfl_xor_sync(0xffffffffu, rs0, off);
            rs1 += __shfl_xor_sync(0xffffffffu, rs1, off);
        }
        float mx = fmaxf(rs0, rs1);
        #pragma unroll
        for (int off = 4; off <= 16; off <<= 1)
            mx = fmaxf(mx, __shfl_xor_sync(0xffffffffu, mx, off));
        int sct = 0;
        if (mx > 1.f) { sct = (int)ceilf(log2f(mx)); if (sct > 12) sct = 12; }
        float scale = __uint_as_float((uint32_t)(127 - sct) << 23);
        #pragma unroll
        for (int j = 0; j < 2; j++)
            #pragma unroll
            for (int q = 0; q < 4; q++) Acr[j][q] *= scale;
        st_cr(Ab, Acr, g, t);
        __syncwarp();

        // ---- A2 = A*A ----
        AFrag fA;
        load_af(Ab, g, t, fA);
        float A2cr[2][4] = {{0.f,0.f,0.f,0.f},{0.f,0.f,0.f,0.f}};
        mm16(A2cr, fA, Ab, g, t);
        st_cr(A2b, A2cr, g, t);
        __syncwarp();

        // ---- A3 = A*A2 (A-frag reuse) ----
        float A3cr[2][4] = {{0.f,0.f,0.f,0.f},{0.f,0.f,0.f,0.f}};
        mm16(A3cr, fA, A2b, g, t);

        // ---- B2 = c6 I + c7 A + c8 A2 + c9 A3 -> Tb; store A3 -> A3b ----
        {
            float E[2][4];
            #pragma unroll
            for (int j = 0; j < 2; j++)
                #pragma unroll
                for (int q = 0; q < 4; q++)
                    E[j][q] = fmaf(c6, dg[j][q],
                              fmaf(c7, Acr[j][q],
                              fmaf(c8, A2cr[j][q], c9 * A3cr[j][q])));
            st_cr(Tb, E, g, t);
        }
        st_cr(A3b, A3cr, g, t);
        __syncwarp();

        // ---- M = A3*B2 + (c3 I + c4 A + c5 A2) ----
        AFrag f3;
        load_af(A3b, g, t, f3);
        float R[2][4];
        #pragma unroll
        for (int j = 0; j < 2; j++)
            #pragma unroll
            for (int q = 0; q < 4; q++)
                R[j][q] = fmaf(c3, dg[j][q],
                          fmaf(c4, Acr[j][q], c5 * A2cr[j][q]));
        mm16(R, f3, Tb, g, t);
        __syncwarp();
        st_cr(Tb, R, g, t);
        __syncwarp();

        // ---- R = A3*M + (I + A + A2/2) ----
        #pragma unroll
        for (int j = 0; j < 2; j++)
            #pragma unroll
            for (int q = 0; q < 4; q++)
                R[j][q] = fmaf(0.5f, A2cr[j][q], Acr[j][q]) + dg[j][q];
        mm16(R, f3, Tb, g, t);

        // ---- squarings ----
        for (int q = 0; q < sct; q++) {
            __syncwarp();
            st_cr(Tb, R, g, t);
            __syncwarp();
            AFrag fR;
            load_af(Tb, g, t, fR);
            float R2[2][4] = {{0.f,0.f,0.f,0.f},{0.f,0.f,0.f,0.f}};
            mm16(R2, fR, Tb, g, t);
            #pragma unroll
            for (int j = 0; j < 2; j++)
                #pragma unroll
                for (int qq = 0; qq < 4; qq++) R[j][qq] = R2[j][qq];
        }

        // ---- write T_all ----
        float* dst = Tout + (size_t)p*256;
        *(float2*)&dst[(g  )*16 + 2*t    ] = make_float2(R[0][0], R[0][1]);
        *(float2*)&dst[(g  )*16 + 2*t + 8] = make_float2(R[1][0], R[1][1]);
        *(float2*)&dst[(g+8)*16 + 2*t    ] = make_float2(R[0][2], R[0][3]);
        *(float2*)&dst[(g+8)*16 + 2*t + 8] = make_float2(R[1][2], R[1][3]);

        // ---- transported & settled ----
        const float* xv = xm_g + ((size_t)b*SEQ + i)*DM;
        float x0 = xv[2*t], x1 = xv[2*t+1], x2 = xv[2*t+8], x3 = xv[2*t+9];
        float pg  = R[0][0]*x0 + R[0][1]*x1 + R[1][0]*x2 + R[1][1]*x3;
        float pg8 = R[0][2]*x0 + R[0][3]*x1 + R[1][2]*x2 + R[1][3]*x3;
        #pragma unroll
        for (int off = 1; off <= 2; off <<= 1) {
            pg  += __shfl_xor_sync(0xffffffffu, pg,  off);
            pg8 += __shfl_xor_sync(0xffffffffu, pg8, off);
        }
        if (t == 0) {
            float wgt = g_attn[row*SEQ + i];
            atomicAdd(&g_settled[row*DM + g    ], wgt * pg);
            atomicAdd(&g_settled[row*DM + g + 8], wgt * pg8);
        }
        __syncwarp();
    }
}

// ---------------- kernel E: out projection ---------------------------------
__global__ void __launch_bounds__(256)
out_kernel(const float* __restrict__ Wo, const float* __restrict__ bo,
           float* __restrict__ out)
{
    int gid = blockIdx.x*256 + threadIdx.x;    // 8192
    int row = gid >> 4, d = gid & 15;
    float acc = bo[d];
    #pragma unroll
    for (int e = 0; e < DM; e++)
        acc = fmaf(Wo[d*DM + e], g_settled[row*DM + e], acc);
    out[gid] = acc;
}

// ---------------- launch ----------------------------------------------------
extern "C" void kernel_launch(void* const* d_in, const int* in_sizes, int n_in,
                              void* d_out, int out_size)
{
    const float* xl  = (const float*)d_in[0];
    const float* xmm = (const float*)d_in[1];
    const float* Wq  = (const float*)d_in[2];
    const float* bq  = (const float*)d_in[3];
    const float* Wk  = (const float*)d_in[4];
    const float* bk  = (const float*)d_in[5];
    const float* W1  = (const float*)d_in[6];
    const float* b1  = (const float*)d_in[7];
    const float* W2  = (const float*)d_in[8];
    const float* b2  = (const float*)d_in[9];
    const float* Wo  = (const float*)d_in[10];
    const float* bo  = (const float*)d_in[11];

    float* out  = (float*)d_out;
    float* Tout = out + NB*SEQ*DM;      // T_all follows out

    static bool attr_set = false;
    if (!attr_set) {
        cudaFuncSetAttribute(attn_kernel, cudaFuncAttributeMaxDynamicSharedMemorySize, AT_BYTES);
        cudaFuncSetAttribute(pair_kernel, cudaFuncAttributeMaxDynamicSharedMemorySize, PK_BYTES);
        attr_set = true;
    }

    prep_kernel<<<dim3(8,8), 256>>>(xl, Wq, bq, Wk, bk, W1);
    w2split_kernel<<<128, 256>>>(W2);
    attn_kernel<<<16, 256, AT_BYTES>>>();
    pair_kernel<<<ROWS, 512, PK_BYTES>>>(b1, b2);
    expm_kernel<<<EXPM_BLOCKS, 128>>>(xmm, Tout);
    out_kernel<<<32, 256>>>(Wo, bo, out);
}

// round 13
// speedup vs baseline: 1.3389x; 1.1718x over previous
#include <cuda_runtime.h>
#include <math.h>
#include <stdint.h>

#define NB 4
#define SEQ 128
#define DL 128
#define DM 16
#define SO 120
#define ROWS (NB*SEQ)        // 512

// ---------------- scratch ----------------------------------------------------
__device__ float g_Q[ROWS*DL];
__device__ float g_K[ROWS*DL];
__device__ float g_U[ROWS*256];
__device__ float g_attn[NB*SEQ*SEQ];
__device__ float g_lie[(size_t)NB*SEQ*SEQ*SO];   // 31.5 MB
__device__ float g_settled[ROWS*DM];
__device__ float g_W2h[256*128];                 // W2^T tf32 hi, [k][c]
__device__ float g_W2l[256*128];                 // W2^T tf32 lo, [k][c]

__constant__ int c_tri_r[120] = {
 0,0,0,0,0,0,0,0,0,0,0,0,0,0,0,
 1,1,1,1,1,1,1,1,1,1,1,1,1,1,
 2,2,2,2,2,2,2,2,2,2,2,2,2,
 3,3,3,3,3,3,3,3,3,3,3,3,
 4,4,4,4,4,4,4,4,4,4,4,
 5,5,5,5,5,5,5,5,5,5,
 6,6,6,6,6,6,6,6,6,
 7,7,7,7,7,7,7,7,
 8,8,8,8,8,8,8,
 9,9,9,9,9,9,
 10,10,10,10,10,
 11,11,11,11,
 12,12,12,
 13,13,
 14};
__constant__ int c_tri_c[120] = {
 1,2,3,4,5,6,7,8,9,10,11,12,13,14,15,
 2,3,4,5,6,7,8,9,10,11,12,13,14,15,
 3,4,5,6,7,8,9,10,11,12,13,14,15,
 4,5,6,7,8,9,10,11,12,13,14,15,
 5,6,7,8,9,10,11,12,13,14,15,
 6,7,8,9,10,11,12,13,14,15,
 7,8,9,10,11,12,13,14,15,
 8,9,10,11,12,13,14,15,
 9,10,11,12,13,14,15,
 10,11,12,13,14,15,
 11,12,13,14,15,
 12,13,14,15,
 13,14,15,
 14,15,
 15};

__device__ __forceinline__ float ftanh(float x) {
    float y;
    asm("tanh.approx.f32 %0, %1;" : "=f"(y) : "f"(x));
    return y;
}

__device__ __forceinline__ unsigned f2tf(float x) {
    unsigned r; asm("cvt.rna.tf32.f32 %0, %1;" : "=r"(r) : "f"(x)); return r;
}

// mask-based tf32 split: hi = top 10 mantissa bits (valid tf32 encoding),
// lo = exact remainder (its own low bits truncate inside the MMA unit).
// 1 LOP3 (alu) + 1 FADD (fma) instead of 2 cvt + 1 sub (~40 cyc of alu latency).
__device__ __forceinline__ void tfsplit(float x, unsigned& hi, unsigned& lo) {
    hi = __float_as_uint(x) & 0xffffe000u;
    lo = __float_as_uint(x - __uint_as_float(hi));
}

__device__ __forceinline__ void mma8(float* d, const unsigned* a, const unsigned* b) {
    asm("mma.sync.aligned.m16n8k8.row.col.f32.tf32.tf32.f32 "
        "{%0,%1,%2,%3}, {%4,%5,%6,%7}, {%8,%9}, {%0,%1,%2,%3};"
        : "+f"(d[0]), "+f"(d[1]), "+f"(d[2]), "+f"(d[3])
        : "r"(a[0]), "r"(a[1]), "r"(a[2]), "r"(a[3]), "r"(b[0]), "r"(b[1]));
}

// ---------------- kernel A: tiled GEMM  C[512 x 512] = X @ [Wq;Wk;W1]^T ----
__global__ void __launch_bounds__(256)
prep_kernel(const float* __restrict__ xl,
            const float* __restrict__ Wq, const float* __restrict__ bq,
            const float* __restrict__ Wk, const float* __restrict__ bk,
            const float* __restrict__ W1)
{
    __shared__ __align__(16) float Xs[64*64];
    __shared__ __align__(16) float Wt[64*68];

    int bx = blockIdx.x, by = blockIdx.y;
    int t  = threadIdx.x;
    int tx = t & 15, ty = t >> 4;

    const float* src;
    if      (by < 2) src = Wq + (by    )*64*DL;
    else if (by < 4) src = Wk + (by - 2)*64*DL;
    else             src = W1 + (by - 4)*64*DL;

    float acc[4][4];
    #pragma unroll
    for (int i = 0; i < 4; i++)
        #pragma unroll
        for (int j = 0; j < 4; j++) acc[i][j] = 0.f;

    for (int k0 = 0; k0 < DL; k0 += 64) {
        __syncthreads();
        #pragma unroll
        for (int s = 0; s < 16; s++) {
            int idx = t + 256*s;
            int r = idx >> 6, k = idx & 63;
            Xs[r*64 + k] = xl[(bx*64 + r)*DL + k0 + k];
            Wt[k*68 + r] = src[r*DL + k0 + k];
        }
        __syncthreads();

        #pragma unroll 8
        for (int k = 0; k < 64; k++) {
            float4 bv = *(const float4*)&Wt[k*68 + tx*4];
            #pragma unroll
            for (int i = 0; i < 4; i++) {
                float a = Xs[(ty*4 + i)*64 + k];
                acc[i][0] = fmaf(a, bv.x, acc[i][0]);
                acc[i][1] = fmaf(a, bv.y, acc[i][1]);
                acc[i][2] = fmaf(a, bv.z, acc[i][2]);
                acc[i][3] = fmaf(a, bv.w, acc[i][3]);
            }
        }
    }

    #pragma unroll
    for (int i = 0; i < 4; i++) {
        int rowg = bx*64 + ty*4 + i;
        int c0   = tx*4;
        if (by < 2) {
            int col = by*64 + c0;
            *(float4*)&g_Q[rowg*DL + col] =
                make_float4(acc[i][0]+bq[col], acc[i][1]+bq[col+1],
                            acc[i][2]+bq[col+2], acc[i][3]+bq[col+3]);
        } else if (by < 4) {
            int col = (by-2)*64 + c0;
            *(float4*)&g_K[rowg*DL + col] =
                make_float4(acc[i][0]+bk[col], acc[i][1]+bk[col+1],
                            acc[i][2]+bk[col+2], acc[i][3]+bk[col+3]);
        } else {
            int col = (by-4)*64 + c0;
            *(float4*)&g_U[rowg*256 + col] =
                make_float4(acc[i][0], acc[i][1], acc[i][2], acc[i][3]);
        }
    }
}

// ---------------- kernel A2: split W2^T into tf32 hi/lo, [k][c] layout -----
__global__ void __launch_bounds__(256)
w2split_kernel(const float* __restrict__ W2)
{
    int idx = blockIdx.x*256 + threadIdx.x;   // 32768 = 256 k x 128 c
    int k = idx >> 7, c = idx & 127;
    float v = (c < SO) ? W2[c*256 + k] : 0.f;
    unsigned h, l;
    tfsplit(v, h, l);
    g_W2h[idx] = __uint_as_float(h);
    g_W2l[idx] = __uint_as_float(l);
}

// ---------------- kernel B: attention softmax (+ zero g_settled) -----------
#define AT_QS 0
#define AT_KT (AT_QS + 32*128)
#define AT_S  (AT_KT + 128*132)
#define AT_FLOATS (AT_S + 32*132)
#define AT_BYTES  (AT_FLOATS*4)

__global__ void __launch_bounds__(256)
attn_kernel()
{
    extern __shared__ float sm[];
    float* Qs = sm + AT_QS;
    float* Kt = sm + AT_KT;
    float* S  = sm + AT_S;

    int b  = blockIdx.x >> 2;
    int jt = (blockIdx.x & 3) * 32;
    int t  = threadIdx.x;
    int tx = t & 15, ty = t >> 4;

    for (int z = t; z < 512; z += 256) g_settled[blockIdx.x*512 + z] = 0.f;

    for (int idx = t; idx < 32*128; idx += 256) {
        int j = idx >> 7, k = idx & 127;
        Qs[j*128 + k] = g_Q[(b*SEQ + jt + j)*DL + k];
    }
    for (int idx = t; idx < 128*128; idx += 256) {
        int i = idx >> 7, k = idx & 127;
        Kt[k*132 + i] = g_K[(b*SEQ + i)*DL + k];
    }
    __syncthreads();

    float acc[2][8];
    #pragma unroll
    for (int i = 0; i < 2; i++)
        #pragma unroll
        for (int j = 0; j < 8; j++) acc[i][j] = 0.f;

    int j0 = ty*2, i0 = tx*8;
    #pragma unroll 4
    for (int k = 0; k < 128; k++) {
        float q0 = Qs[(j0  )*128 + k];
        float q1 = Qs[(j0+1)*128 + k];
        float4 k0v = *(const float4*)&Kt[k*132 + i0];
        float4 k1v = *(const float4*)&Kt[k*132 + i0 + 4];
        acc[0][0]=fmaf(q0,k0v.x,acc[0][0]); acc[0][1]=fmaf(q0,k0v.y,acc[0][1]);
        acc[0][2]=fmaf(q0,k0v.z,acc[0][2]); acc[0][3]=fmaf(q0,k0v.w,acc[0][3]);
        acc[0][4]=fmaf(q0,k1v.x,acc[0][4]); acc[0][5]=fmaf(q0,k1v.y,acc[0][5]);
        acc[0][6]=fmaf(q0,k1v.z,acc[0][6]); acc[0][7]=fmaf(q0,k1v.w,acc[0][7]);
        acc[1][0]=fmaf(q1,k0v.x,acc[1][0]); acc[1][1]=fmaf(q1,k0v.y,acc[1][1]);
        acc[1][2]=fmaf(q1,k0v.z,acc[1][2]); acc[1][3]=fmaf(q1,k0v.w,acc[1][3]);
        acc[1][4]=fmaf(q1,k1v.x,acc[1][4]); acc[1][5]=fmaf(q1,k1v.y,acc[1][5]);
        acc[1][6]=fmaf(q1,k1v.z,acc[1][6]); acc[1][7]=fmaf(q1,k1v.w,acc[1][7]);
    }
    const float sc = 0.08838834764831845f;
    #pragma unroll
    for (int i = 0; i < 2; i++) {
        *(float4*)&S[(j0+i)*132 + i0] =
            make_float4(acc[i][0]*sc, acc[i][1]*sc, acc[i][2]*sc, acc[i][3]*sc);
        *(float4*)&S[(j0+i)*132 + i0 + 4] =
            make_float4(acc[i][4]*sc, acc[i][5]*sc, acc[i][6]*sc, acc[i][7]*sc);
    }
    __syncthreads();

    int w = t >> 5, lane = t & 31;
    for (int q = 0; q < 4; q++) {
        int r = w*4 + q;
        float v0 = S[r*132 + lane      ];
        float v1 = S[r*132 + lane + 32 ];
        float v2 = S[r*132 + lane + 64 ];
        float v3 = S[r*132 + lane + 96 ];
        float mx = fmaxf(fmaxf(v0,v1), fmaxf(v2,v3));
        #pragma unroll
        for (int off = 16; off; off >>= 1)
            mx = fmaxf(mx, __shfl_xor_sync(0xffffffffu, mx, off));
        float e0 = expf(v0-mx), e1 = expf(v1-mx), e2 = expf(v2-mx), e3 = expf(v3-mx);
        float sum = e0+e1+e2+e3;
        #pragma unroll
        for (int off = 16; off; off >>= 1)
            sum += __shfl_xor_sync(0xffffffffu, sum, off);
        float inv = 1.f/sum;
        float* dst = g_attn + (b*SEQ + jt + r)*SEQ;
        dst[lane     ] = e0*inv;
        dst[lane + 32] = e1*inv;
        dst[lane + 64] = e2*inv;
        dst[lane + 96] = e3*inv;
    }
}

// ---------------- kernel C: pairwise MLP GEMM via 3xTF32 MMA (R10 + mask) --
// Block = (b,j): C[128 i x 120 c]. 8 warps; warp w -> i-rows [16w,16w+16).
#define PK_UJB 0
#define PK_B2  (PK_UJB + 256)
#define PK_H   (PK_B2 + 128)
#define PK_BH  (PK_H + 128*36)
#define PK_BL  (PK_BH + 32*136)
#define PK_FLOATS (PK_BL + 32*136)
#define PK_BYTES  (PK_FLOATS*4)

__global__ void __launch_bounds__(256, 2)
pair_kernel(const float* __restrict__ b1, const float* __restrict__ b2)
{
    extern __shared__ float psm[];
    float* Ujb = psm + PK_UJB;
    float* b2s = psm + PK_B2;
    float* Hs  = psm + PK_H;
    float* Bh  = psm + PK_BH;
    float* Bl  = psm + PK_BL;

    int row = blockIdx.x;          // b*128 + j
    int b   = row >> 7;
    int t   = threadIdx.x;
    int lane = t & 31, w = t >> 5;
    int g = lane >> 2, tt = lane & 3;
    int ibase = w * 16;

    Ujb[t] = g_U[row*256 + t] + b1[t];
    if (t < 128) b2s[t] = (t < SO) ? b2[t] : 0.f;

    float acc[15][4];
    #pragma unroll
    for (int n = 0; n < 15; n++)
        #pragma unroll
        for (int q = 0; q < 4; q++) acc[n][q] = 0.f;

    for (int k0 = 0; k0 < 256; k0 += 32) {
        __syncthreads();
        #pragma unroll
        for (int s = 0; s < 16; s++) {
            int idx = t + 256*s;                // 4096
            {   int i = idx >> 5, k = idx & 31;
                Hs[i*36 + k] = ftanh(Ujb[k0 + k] - g_U[(b*SEQ + i)*256 + k0 + k]); }
            {   int k = idx >> 7, c = idx & 127;
                Bh[k*136 + c] = g_W2h[(k0 + k)*128 + c];
                Bl[k*136 + c] = g_W2l[(k0 + k)*128 + c]; }
        }
        __syncthreads();

        #pragma unroll
        for (int s = 0; s < 4; s++) {
            float v0 = Hs[(ibase+g  )*36 + 8*s + tt];
            float v1 = Hs[(ibase+g+8)*36 + 8*s + tt];
            float v2 = Hs[(ibase+g  )*36 + 8*s + tt + 4];
            float v3 = Hs[(ibase+g+8)*36 + 8*s + tt + 4];
            unsigned ah[4], al[4];
            tfsplit(v0, ah[0], al[0]);
            tfsplit(v1, ah[1], al[1]);
            tfsplit(v2, ah[2], al[2]);
            tfsplit(v3, ah[3], al[3]);
            int kr0 = (8*s + tt    )*136 + g;
            int kr1 = (8*s + tt + 4)*136 + g;
            #pragma unroll
            for (int n = 0; n < 15; n++) {
                unsigned bh[2], bl_[2];
                bh[0]  = __float_as_uint(Bh[kr0 + 8*n]);
                bh[1]  = __float_as_uint(Bh[kr1 + 8*n]);
                bl_[0] = __float_as_uint(Bl[kr0 + 8*n]);
                bl_[1] = __float_as_uint(Bl[kr1 + 8*n]);
                mma8(acc[n], ah, bl_);
                mma8(acc[n], al, bh);
                mma8(acc[n], ah, bh);
            }
        }
    }

    // epilogue: bias + store
    size_t p0 = (size_t)row*SEQ + ibase + g;
    size_t p1 = p0 + 8;
    #pragma unroll
    for (int n = 0; n < 15; n++) {
        int c = 8*n + 2*tt;
        float bb0 = b2s[c], bb1 = b2s[c+1];
        *(float2*)&g_lie[p0*SO + c] = make_float2(acc[n][0] + bb0, acc[n][1] + bb1);
        *(float2*)&g_lie[p1*SO + c] = make_float2(acc[n][2] + bb0, acc[n][3] + bb1);
    }
}

// ---------------- tf32 mask-split MMA helpers for expm ---------------------
struct AFrag { unsigned h[2][4]; unsigned l[2][4]; };

__device__ __forceinline__ void load_af(const float* M, int g, int t, AFrag& f) {
    #pragma unroll
    for (int s = 0; s < 2; s++) {
        float v[4];
        v[0] = M[(g  )*20 + t     + 8*s];
        v[1] = M[(g+8)*20 + t     + 8*s];
        v[2] = M[(g  )*20 + t + 4 + 8*s];
        v[3] = M[(g+8)*20 + t + 4 + 8*s];
        #pragma unroll
        for (int q = 0; q < 4; q++)
            tfsplit(v[q], f.h[s][q], f.l[s][q]);
    }
}

// D[2][4] += Afrag * Y (Y in smem row-major stride 20), mask-split 3xTF32.
__device__ __forceinline__ void mm16(float D[2][4], const AFrag& a,
                                     const float* Y, int g, int t) {
    #pragma unroll
    for (int j = 0; j < 2; j++)
        #pragma unroll
        for (int s = 0; s < 2; s++) {
            float v0 = Y[(t     + 8*s)*20 + g + 8*j];
            float v1 = Y[(t + 4 + 8*s)*20 + g + 8*j];
            unsigned bh[2], bl[2];
            tfsplit(v0, bh[0], bl[0]);
            tfsplit(v1, bh[1], bl[1]);
            mma8(D[j], a.h[s], bl);
            mma8(D[j], a.l[s], bh);
            mma8(D[j], a.h[s], bh);
        }
}

__device__ __forceinline__ void st_cr(float* M, const float D[2][4], int g, int t) {
    *(float2*)&M[(g  )*20 + 2*t    ] = make_float2(D[0][0], D[0][1]);
    *(float2*)&M[(g  )*20 + 2*t + 8] = make_float2(D[1][0], D[1][1]);
    *(float2*)&M[(g+8)*20 + 2*t    ] = make_float2(D[0][2], D[0][3]);
    *(float2*)&M[(g+8)*20 + 2*t + 8] = make_float2(D[1][2], D[1][3]);
}

// ---------------- kernel D: expm via mask-split 3xTF32 MMA -----------------
#define EXPM_BLOCKS 1024
#define NPAIRS (NB*SEQ*SEQ)      // 65536

__global__ void __launch_bounds__(128)
expm_kernel(const float* __restrict__ xm_g, float* __restrict__ Tout)
{
    __shared__ __align__(16) float mm[4*4*320];   // 4 warps x (A,A2,A3,T) x 320
    int tid = threadIdx.x, lane = tid & 31, w = tid >> 5;
    float* Ab  = mm + w*1280;
    float* A2b = Ab + 320;
    float* A3b = Ab + 640;
    float* Tb  = Ab + 960;

    int g = lane >> 2;       // row group 0..7 (rows g, g+8)
    int t = lane & 3;        // col group

    const float c3=1.f/6.f, c4=1.f/24.f, c5=1.f/120.f;
    const float c6=1.f/720.f, c7=1.f/5040.f, c8=1.f/40320.f, c9=1.f/362880.f;

    float dg[2][4];
    #pragma unroll
    for (int j = 0; j < 2; j++)
        #pragma unroll
        for (int q = 0; q < 4; q++)
            dg[j][q] = ((g + 8*(q>>1)) == (2*t + (q&1) + 8*j)) ? 1.f : 0.f;

    for (int p = blockIdx.x*4 + w; p < NPAIRS; p += EXPM_BLOCKS*4) {
        int row = p >> 7;
        int i   = p & 127;
        int b   = row >> 7;

        // ---- scatter lie -> skew A ----
        const float* lr = g_lie + (size_t)p*SO;
        if (lane < 16) Ab[lane*20 + lane] = 0.f;
        #pragma unroll
        for (int q = 0; q < 4; q++) {
            int l = lane + 32*q;
            if (l < SO) {
                float v = lr[l];
                int rI = c_tri_r[l], cI = c_tri_c[l];
                Ab[rI*20 + cI] =  v;
                Ab[cI*20 + rI] = -v;
            }
        }
        __syncwarp();

        // ---- load A C-layout, norm, scale ----
        float Acr[2][4];
        {
            float2 v;
            v = *(float2*)&Ab[(g  )*20 + 2*t    ]; Acr[0][0]=v.x; Acr[0][1]=v.y;
            v = *(float2*)&Ab[(g  )*20 + 2*t + 8]; Acr[1][0]=v.x; Acr[1][1]=v.y;
            v = *(float2*)&Ab[(g+8)*20 + 2*t    ]; Acr[0][2]=v.x; Acr[0][3]=v.y;
            v = *(float2*)&Ab[(g+8)*20 + 2*t + 8]; Acr[1][2]=v.x; Acr[1][3]=v.y;
        }
        float rs0 = fabsf(Acr[0][0])+fabsf(Acr[0][1])+fabsf(Acr[1][0])+fabsf(Acr[1][1]);
        float rs1 = fabsf(Acr[0][2])+fabsf(Acr[0][3])+fabsf(Acr[1][2])+fabsf(Acr[1][3]);
        #pragma unroll
        for (int off = 1; off <= 2; off <<= 1) {
            rs0 += __shfl_xor_sync(0xffffffffu, rs0, off);
            rs1 += __shfl_xor_sync(0xffffffffu, rs1, off);
        }
        float mx = fmaxf(rs0, rs1);
        #pragma unroll
        for (int off = 4; off <= 16; off <<= 1)
            mx = fmaxf(mx, __shfl_xor_sync(0xffffffffu, mx, off));
        int sct = 0;
        if (mx > 1.f) { sct = (int)ceilf(log2f(mx)); if (sct > 12) sct = 12; }
        float scale = __uint_as_float((uint32_t)(127 - sct) << 23);
        #pragma unroll
        for (int j = 0; j < 2; j++)
            #pragma unroll
            for (int q = 0; q < 4; q++) Acr[j][q] *= scale;
        st_cr(Ab, Acr, g, t);
        __syncwarp();

        // ---- A2 = A*A ----
        AFrag fA;
        load_af(Ab, g, t, fA);
        float A2cr[2][4] = {{0.f,0.f,0.f,0.f},{0.f,0.f,0.f,0.f}};
        mm16(A2cr, fA, Ab, g, t);
        st_cr(A2b, A2cr, g, t);
        __syncwarp();

        // ---- A3 = A*A2 (A-frag reuse) ----
        float A3cr[2][4] = {{0.f,0.f,0.f,0.f},{0.f,0.f,0.f,0.f}};
        mm16(A3cr, fA, A2b, g, t);

        // ---- B2 = c6 I + c7 A + c8 A2 + c9 A3 -> Tb; store A3 -> A3b ----
        {
            float E[2][4];
            #pragma unroll
            for (int j = 0; j < 2; j++)
                #pragma unroll
                for (int q = 0; q < 4; q++)
                    E[j][q] = fmaf(c6, dg[j][q],
                              fmaf(c7, Acr[j][q],
                              fmaf(c8, A2cr[j][q], c9 * A3cr[j][q])));
            st_cr(Tb, E, g, t);
        }
        st_cr(A3b, A3cr, g, t);
        __syncwarp();

        // ---- M = A3*B2 + (c3 I + c4 A + c5 A2) ----
        AFrag f3;
        load_af(A3b, g, t, f3);
        float R[2][4];
        #pragma unroll
        for (int j = 0; j < 2; j++)
            #pragma unroll
            for (int q = 0; q < 4; q++)
                R[j][q] = fmaf(c3, dg[j][q],
                          fmaf(c4, Acr[j][q], c5 * A2cr[j][q]));
        mm16(R, f3, Tb, g, t);
        __syncwarp();
        st_cr(Tb, R, g, t);
        __syncwarp();

        // ---- R = A3*M + (I + A + A2/2) ----
        #pragma unroll
        for (int j = 0; j < 2; j++)
            #pragma unroll
            for (int q = 0; q < 4; q++)
                R[j][q] = fmaf(0.5f, A2cr[j][q], Acr[j][q]) + dg[j][q];
        mm16(R, f3, Tb, g, t);

        // ---- squarings ----
        for (int q = 0; q < sct; q++) {
            __syncwarp();
            st_cr(Tb, R, g, t);
            __syncwarp();
            AFrag fR;
            load_af(Tb, g, t, fR);
            float R2[2][4] = {{0.f,0.f,0.f,0.f},{0.f,0.f,0.f,0.f}};
            mm16(R2, fR, Tb, g, t);
            #pragma unroll
            for (int j = 0; j < 2; j++)
                #pragma unroll
                for (int qq = 0; qq < 4; qq++) R[j][qq] = R2[j][qq];
        }

        // ---- write T_all ----
        float* dst = Tout + (size_t)p*256;
        *(float2*)&dst[(g  )*16 + 2*t    ] = make_float2(R[0][0], R[0][1]);
        *(float2*)&dst[(g  )*16 + 2*t + 8] = make_float2(R[1][0], R[1][1]);
        *(float2*)&dst[(g+8)*16 + 2*t    ] = make_float2(R[0][2], R[0][3]);
        *(float2*)&dst[(g+8)*16 + 2*t + 8] = make_float2(R[1][2], R[1][3]);

        // ---- transported & settled ----
        const float* xv = xm_g + ((size_t)b*SEQ + i)*DM;
        float x0 = xv[2*t], x1 = xv[2*t+1], x2 = xv[2*t+8], x3 = xv[2*t+9];
        float pg  = R[0][0]*x0 + R[0][1]*x1 + R[1][0]*x2 + R[1][1]*x3;
        float pg8 = R[0][2]*x0 + R[0][3]*x1 + R[1][2]*x2 + R[1][3]*x3;
        #pragma unroll
        for (int off = 1; off <= 2; off <<= 1) {
            pg  += __shfl_xor_sync(0xffffffffu, pg,  off);
            pg8 += __shfl_xor_sync(0xffffffffu, pg8, off);
        }
        if (t == 0) {
            float wgt = g_attn[row*SEQ + i];
            atomicAdd(&g_settled[row*DM + g    ], wgt * pg);
            atomicAdd(&g_settled[row*DM + g + 8], wgt * pg8);
        }
        __syncwarp();
    }
}

// ---------------- kernel E: out projection ---------------------------------
__global__ void __launch_bounds__(256)
out_kernel(const float* __restrict__ Wo, const float* __restrict__ bo,
           float* __restrict__ out)
{
    int gid = blockIdx.x*256 + threadIdx.x;    // 8192
    int row = gid >> 4, d = gid & 15;
    float acc = bo[d];
    #pragma unroll
    for (int e = 0; e < DM; e++)
        acc = fmaf(Wo[d*DM + e], g_settled[row*DM + e], acc);
    out[gid] = acc;
}

// ---------------- launch ----------------------------------------------------
extern "C" void kernel_launch(void* const* d_in, const int* in_sizes, int n_in,
                              void* d_out, int out_size)
{
    const float* xl  = (const float*)d_in[0];
    const float* xmm = (const float*)d_in[1];
    const float* Wq  = (const float*)d_in[2];
    const float* bq  = (const float*)d_in[3];
    const float* Wk  = (const float*)d_in[4];
    const float* bk  = (const float*)d_in[5];
    const float* W1  = (const float*)d_in[6];
    const float* b1  = (const float*)d_in[7];
    const float* W2  = (const float*)d_in[8];
    const float* b2  = (const float*)d_in[9];
    const float* Wo  = (const float*)d_in[10];
    const float* bo  = (const float*)d_in[11];

    float* out  = (float*)d_out;
    float* Tout = out + NB*SEQ*DM;      // T_all follows out

    static bool attr_set = false;
    if (!attr_set) {
        cudaFuncSetAttribute(attn_kernel, cudaFuncAttributeMaxDynamicSharedMemorySize, AT_BYTES);
        cudaFuncSetAttribute(pair_kernel, cudaFuncAttributeMaxDynamicSharedMemorySize, PK_BYTES);
        attr_set = true;
    }

    prep_kernel<<<dim3(8,8), 256>>>(xl, Wq, bq, Wk, bk, W1);
    w2split_kernel<<<128, 256>>>(W2);
    attn_kernel<<<16, 256, AT_BYTES>>>();
    pair_kernel<<<ROWS, 256, PK_BYTES>>>(b1, b2);
    expm_kernel<<<EXPM_BLOCKS, 128>>>(xmm, Tout);
    out_kernel<<<32, 256>>>(Wo, bo, out);
}

// round 14
// speedup vs baseline: 1.5663x; 1.1698x over previous
#include <cuda_runtime.h>
#include <math.h>
#include <stdint.h>

#define NB 4
#define SEQ 128
#define DL 128
#define DM 16
#define SO 120
#define ROWS (NB*SEQ)        // 512

// ---------------- scratch ----------------------------------------------------
__device__ float g_Q[ROWS*DL];
__device__ float g_K[ROWS*DL];
__device__ float g_U[ROWS*256];
__device__ float g_attn[NB*SEQ*SEQ];
__device__ float g_lie[(size_t)NB*SEQ*SEQ*SO];   // 31.5 MB
__device__ float g_settled[ROWS*DM];
__device__ unsigned g_W2bh[128*128];             // W2^T bf16x2 hi words [kword][c]
__device__ unsigned g_W2bl[128*128];             // W2^T bf16x2 lo words [kword][c]

__constant__ int c_tri_r[120] = {
 0,0,0,0,0,0,0,0,0,0,0,0,0,0,0,
 1,1,1,1,1,1,1,1,1,1,1,1,1,1,
 2,2,2,2,2,2,2,2,2,2,2,2,2,
 3,3,3,3,3,3,3,3,3,3,3,3,
 4,4,4,4,4,4,4,4,4,4,4,
 5,5,5,5,5,5,5,5,5,5,
 6,6,6,6,6,6,6,6,6,
 7,7,7,7,7,7,7,7,
 8,8,8,8,8,8,8,
 9,9,9,9,9,9,
 10,10,10,10,10,
 11,11,11,11,
 12,12,12,
 13,13,
 14};
__constant__ int c_tri_c[120] = {
 1,2,3,4,5,6,7,8,9,10,11,12,13,14,15,
 2,3,4,5,6,7,8,9,10,11,12,13,14,15,
 3,4,5,6,7,8,9,10,11,12,13,14,15,
 4,5,6,7,8,9,10,11,12,13,14,15,
 5,6,7,8,9,10,11,12,13,14,15,
 6,7,8,9,10,11,12,13,14,15,
 7,8,9,10,11,12,13,14,15,
 8,9,10,11,12,13,14,15,
 9,10,11,12,13,14,15,
 10,11,12,13,14,15,
 11,12,13,14,15,
 12,13,14,15,
 13,14,15,
 14,15,
 15};

__device__ __forceinline__ float ftanh(float x) {
    float y;
    asm("tanh.approx.f32 %0, %1;" : "=f"(y) : "f"(x));
    return y;
}

// mask-based tf32 split (expm): 1 LOP3 + 1 FADD
__device__ __forceinline__ void tfsplit(float x, unsigned& hi, unsigned& lo) {
    hi = __float_as_uint(x) & 0xffffe000u;
    lo = __float_as_uint(x - __uint_as_float(hi));
}

// bf16x2 split-pack: word = {x1_bf16, x0_bf16}; hi = truncated top-16,
// lo = bf16 of exact remainder. Dropped error ~2^-16 per element.
__device__ __forceinline__ void bfsplit2(float x0, float x1, unsigned& hi, unsigned& lo) {
    unsigned h0 = __float_as_uint(x0) & 0xffff0000u;
    unsigned h1 = __float_as_uint(x1) & 0xffff0000u;
    hi = h1 | (h0 >> 16);
    float l0 = x0 - __uint_as_float(h0);
    float l1 = x1 - __uint_as_float(h1);
    lo = (__float_as_uint(l1) & 0xffff0000u) | (__float_as_uint(l0) >> 16);
}

__device__ __forceinline__ void mma8(float* d, const unsigned* a, const unsigned* b) {
    asm("mma.sync.aligned.m16n8k8.row.col.f32.tf32.tf32.f32 "
        "{%0,%1,%2,%3}, {%4,%5,%6,%7}, {%8,%9}, {%0,%1,%2,%3};"
        : "+f"(d[0]), "+f"(d[1]), "+f"(d[2]), "+f"(d[3])
        : "r"(a[0]), "r"(a[1]), "r"(a[2]), "r"(a[3]), "r"(b[0]), "r"(b[1]));
}

__device__ __forceinline__ void mma16(float* d, const unsigned* a, const unsigned* b) {
    asm("mma.sync.aligned.m16n8k16.row.col.f32.bf16.bf16.f32 "
        "{%0,%1,%2,%3}, {%4,%5,%6,%7}, {%8,%9}, {%0,%1,%2,%3};"
        : "+f"(d[0]), "+f"(d[1]), "+f"(d[2]), "+f"(d[3])
        : "r"(a[0]), "r"(a[1]), "r"(a[2]), "r"(a[3]), "r"(b[0]), "r"(b[1]));
}

// ---------------- kernel A: tiled GEMM  C[512 x 512] = X @ [Wq;Wk;W1]^T ----
__global__ void __launch_bounds__(256)
prep_kernel(const float* __restrict__ xl,
            const float* __restrict__ Wq, const float* __restrict__ bq,
            const float* __restrict__ Wk, const float* __restrict__ bk,
            const float* __restrict__ W1)
{
    __shared__ __align__(16) float Xs[64*64];
    __shared__ __align__(16) float Wt[64*68];

    int bx = blockIdx.x, by = blockIdx.y;
    int t  = threadIdx.x;
    int tx = t & 15, ty = t >> 4;

    const float* src;
    if      (by < 2) src = Wq + (by    )*64*DL;
    else if (by < 4) src = Wk + (by - 2)*64*DL;
    else             src = W1 + (by - 4)*64*DL;

    float acc[4][4];
    #pragma unroll
    for (int i = 0; i < 4; i++)
        #pragma unroll
        for (int j = 0; j < 4; j++) acc[i][j] = 0.f;

    for (int k0 = 0; k0 < DL; k0 += 64) {
        __syncthreads();
        #pragma unroll
        for (int s = 0; s < 16; s++) {
            int idx = t + 256*s;
            int r = idx >> 6, k = idx & 63;
            Xs[r*64 + k] = xl[(bx*64 + r)*DL + k0 + k];
            Wt[k*68 + r] = src[r*DL + k0 + k];
        }
        __syncthreads();

        #pragma unroll 8
        for (int k = 0; k < 64; k++) {
            float4 bv = *(const float4*)&Wt[k*68 + tx*4];
            #pragma unroll
            for (int i = 0; i < 4; i++) {
                float a = Xs[(ty*4 + i)*64 + k];
                acc[i][0] = fmaf(a, bv.x, acc[i][0]);
                acc[i][1] = fmaf(a, bv.y, acc[i][1]);
                acc[i][2] = fmaf(a, bv.z, acc[i][2]);
                acc[i][3] = fmaf(a, bv.w, acc[i][3]);
            }
        }
    }

    #pragma unroll
    for (int i = 0; i < 4; i++) {
        int rowg = bx*64 + ty*4 + i;
        int c0   = tx*4;
        if (by < 2) {
            int col = by*64 + c0;
            *(float4*)&g_Q[rowg*DL + col] =
                make_float4(acc[i][0]+bq[col], acc[i][1]+bq[col+1],
                            acc[i][2]+bq[col+2], acc[i][3]+bq[col+3]);
        } else if (by < 4) {
            int col = (by-2)*64 + c0;
            *(float4*)&g_K[rowg*DL + col] =
                make_float4(acc[i][0]+bk[col], acc[i][1]+bk[col+1],
                            acc[i][2]+bk[col+2], acc[i][3]+bk[col+3]);
        } else {
            int col = (by-4)*64 + c0;
            *(float4*)&g_U[rowg*256 + col] =
                make_float4(acc[i][0], acc[i][1], acc[i][2], acc[i][3]);
        }
    }
}

// ---------------- kernel A2: pack W2^T into bf16x2 hi/lo words [kword][c] --
__global__ void __launch_bounds__(256)
w2split_kernel(const float* __restrict__ W2)
{
    int idx = blockIdx.x*256 + threadIdx.x;   // 16384 = 128 kwords x 128 c
    int w = idx >> 7, c = idx & 127;
    float v0 = (c < SO) ? W2[c*256 + 2*w    ] : 0.f;
    float v1 = (c < SO) ? W2[c*256 + 2*w + 1] : 0.f;
    unsigned hi, lo;
    bfsplit2(v0, v1, hi, lo);
    g_W2bh[idx] = hi;
    g_W2bl[idx] = lo;
}

// ---------------- kernel B: attention softmax (+ zero g_settled) -----------
#define AT_QS 0
#define AT_KT (AT_QS + 32*128)
#define AT_S  (AT_KT + 128*132)
#define AT_FLOATS (AT_S + 32*132)
#define AT_BYTES  (AT_FLOATS*4)

__global__ void __launch_bounds__(256)
attn_kernel()
{
    extern __shared__ float sm[];
    float* Qs = sm + AT_QS;
    float* Kt = sm + AT_KT;
    float* S  = sm + AT_S;

    int b  = blockIdx.x >> 2;
    int jt = (blockIdx.x & 3) * 32;
    int t  = threadIdx.x;
    int tx = t & 15, ty = t >> 4;

    for (int z = t; z < 512; z += 256) g_settled[blockIdx.x*512 + z] = 0.f;

    for (int idx = t; idx < 32*128; idx += 256) {
        int j = idx >> 7, k = idx & 127;
        Qs[j*128 + k] = g_Q[(b*SEQ + jt + j)*DL + k];
    }
    for (int idx = t; idx < 128*128; idx += 256) {
        int i = idx >> 7, k = idx & 127;
        Kt[k*132 + i] = g_K[(b*SEQ + i)*DL + k];
    }
    __syncthreads();

    float acc[2][8];
    #pragma unroll
    for (int i = 0; i < 2; i++)
        #pragma unroll
        for (int j = 0; j < 8; j++) acc[i][j] = 0.f;

    int j0 = ty*2, i0 = tx*8;
    #pragma unroll 4
    for (int k = 0; k < 128; k++) {
        float q0 = Qs[(j0  )*128 + k];
        float q1 = Qs[(j0+1)*128 + k];
        float4 k0v = *(const float4*)&Kt[k*132 + i0];
        float4 k1v = *(const float4*)&Kt[k*132 + i0 + 4];
        acc[0][0]=fmaf(q0,k0v.x,acc[0][0]); acc[0][1]=fmaf(q0,k0v.y,acc[0][1]);
        acc[0][2]=fmaf(q0,k0v.z,acc[0][2]); acc[0][3]=fmaf(q0,k0v.w,acc[0][3]);
        acc[0][4]=fmaf(q0,k1v.x,acc[0][4]); acc[0][5]=fmaf(q0,k1v.y,acc[0][5]);
        acc[0][6]=fmaf(q0,k1v.z,acc[0][6]); acc[0][7]=fmaf(q0,k1v.w,acc[0][7]);
        acc[1][0]=fmaf(q1,k0v.x,acc[1][0]); acc[1][1]=fmaf(q1,k0v.y,acc[1][1]);
        acc[1][2]=fmaf(q1,k0v.z,acc[1][2]); acc[1][3]=fmaf(q1,k0v.w,acc[1][3]);
        acc[1][4]=fmaf(q1,k1v.x,acc[1][4]); acc[1][5]=fmaf(q1,k1v.y,acc[1][5]);
        acc[1][6]=fmaf(q1,k1v.z,acc[1][6]); acc[1][7]=fmaf(q1,k1v.w,acc[1][7]);
    }
    const float sc = 0.08838834764831845f;
    #pragma unroll
    for (int i = 0; i < 2; i++) {
        *(float4*)&S[(j0+i)*132 + i0] =
            make_float4(acc[i][0]*sc, acc[i][1]*sc, acc[i][2]*sc, acc[i][3]*sc);
        *(float4*)&S[(j0+i)*132 + i0 + 4] =
            make_float4(acc[i][4]*sc, acc[i][5]*sc, acc[i][6]*sc, acc[i][7]*sc);
    }
    __syncthreads();

    int w = t >> 5, lane = t & 31;
    for (int q = 0; q < 4; q++) {
        int r = w*4 + q;
        float v0 = S[r*132 + lane      ];
        float v1 = S[r*132 + lane + 32 ];
        float v2 = S[r*132 + lane + 64 ];
        float v3 = S[r*132 + lane + 96 ];
        float mx = fmaxf(fmaxf(v0,v1), fmaxf(v2,v3));
        #pragma unroll
        for (int off = 16; off; off >>= 1)
            mx = fmaxf(mx, __shfl_xor_sync(0xffffffffu, mx, off));
        float e0 = expf(v0-mx), e1 = expf(v1-mx), e2 = expf(v2-mx), e3 = expf(v3-mx);
        float sum = e0+e1+e2+e3;
        #pragma unroll
        for (int off = 16; off; off >>= 1)
            sum += __shfl_xor_sync(0xffffffffu, sum, off);
        float inv = 1.f/sum;
        float* dst = g_attn + (b*SEQ + jt + r)*SEQ;
        dst[lane     ] = e0*inv;
        dst[lane + 32] = e1*inv;
        dst[lane + 64] = e2*inv;
        dst[lane + 96] = e3*inv;
    }
}

// ---------------- kernel C: pairwise MLP GEMM via split-BF16 m16n8k16 ------
// Block = (b,j): C[128 i x 120 c]. 8 warps; warp w -> i-rows [16w,16w+16).
// Hw*: [i][kword] stride 20 words (16 data + 4 pad); Bw*: [kword][c] stride 136.
#define PK_UJB 0
#define PK_B2  (PK_UJB + 256)
#define PK_HWH (PK_B2 + 128)
#define PK_HWL (PK_HWH + 128*20)
#define PK_BWH (PK_HWL + 128*20)
#define PK_BWL (PK_BWH + 16*136)
#define PK_FLOATS (PK_BWL + 16*136)
#define PK_BYTES  (PK_FLOATS*4)

__global__ void __launch_bounds__(256, 2)
pair_kernel(const float* __restrict__ b1, const float* __restrict__ b2)
{
    extern __shared__ float psm[];
    float*    Ujb = psm + PK_UJB;
    float*    b2s = psm + PK_B2;
    unsigned* Hwh = (unsigned*)(psm + PK_HWH);
    unsigned* Hwl = (unsigned*)(psm + PK_HWL);
    unsigned* Bwh = (unsigned*)(psm + PK_BWH);
    unsigned* Bwl = (unsigned*)(psm + PK_BWL);

    int row = blockIdx.x;          // b*128 + j
    int b   = row >> 7;
    int t   = threadIdx.x;
    int lane = t & 31, w = t >> 5;
    int g = lane >> 2, tt = lane & 3;
    int ibase = w * 16;

    Ujb[t] = g_U[row*256 + t] + b1[t];
    if (t < 128) b2s[t] = (t < SO) ? b2[t] : 0.f;

    float acc[15][4];
    #pragma unroll
    for (int n = 0; n < 15; n++)
        #pragma unroll
        for (int q = 0; q < 4; q++) acc[n][q] = 0.f;

    for (int k0 = 0; k0 < 256; k0 += 32) {
        __syncthreads();
        // H: tanh + bf16 split-pack, 2048 words
        #pragma unroll
        for (int s = 0; s < 8; s++) {
            int idx = t + 256*s;
            int i = idx >> 4, kw = idx & 15;
            float2 u  = *(const float2*)&g_U[(b*SEQ + i)*256 + k0 + 2*kw];
            float2 uj = *(const float2*)&Ujb[k0 + 2*kw];
            float h0 = ftanh(uj.x - u.x);
            float h1 = ftanh(uj.y - u.y);
            unsigned hi, lo;
            bfsplit2(h0, h1, hi, lo);
            Hwh[i*20 + kw] = hi;
            Hwl[i*20 + kw] = lo;
        }
        // B: copy prepacked words, 2048 each
        #pragma unroll
        for (int s = 0; s < 8; s++) {
            int idx = t + 256*s;
            int kw = idx >> 7, c = idx & 127;
            Bwh[kw*136 + c] = g_W2bh[(k0/2 + kw)*128 + c];
            Bwl[kw*136 + c] = g_W2bl[(k0/2 + kw)*128 + c];
        }
        __syncthreads();

        #pragma unroll
        for (int s = 0; s < 2; s++) {
            int hb = (ibase + g)*20 + 8*s;
            unsigned ah[4], al[4];
            ah[0] = Hwh[hb + tt];           al[0] = Hwl[hb + tt];
            ah[1] = Hwh[hb + 160 + tt];     al[1] = Hwl[hb + 160 + tt];
            ah[2] = Hwh[hb + tt + 4];       al[2] = Hwl[hb + tt + 4];
            ah[3] = Hwh[hb + 160 + tt + 4]; al[3] = Hwl[hb + 160 + tt + 4];
            int kb0 = (8*s + tt    )*136;
            int kb1 = (8*s + tt + 4)*136;
            #pragma unroll
            for (int n = 0; n < 15; n++) {
                int cb = n*8 + g;
                unsigned bh[2] = { Bwh[kb0 + cb], Bwh[kb1 + cb] };
                unsigned bl[2] = { Bwl[kb0 + cb], Bwl[kb1 + cb] };
                mma16(acc[n], ah, bl);
                mma16(acc[n], al, bh);
                mma16(acc[n], ah, bh);
            }
        }
    }

    // epilogue: bias + store (C layout identical to k8 variant)
    size_t p0 = (size_t)row*SEQ + ibase + g;
    size_t p1 = p0 + 8;
    #pragma unroll
    for (int n = 0; n < 15; n++) {
        int c = 8*n + 2*tt;
        float bb0 = b2s[c], bb1 = b2s[c+1];
        *(float2*)&g_lie[p0*SO + c] = make_float2(acc[n][0] + bb0, acc[n][1] + bb1);
        *(float2*)&g_lie[p1*SO + c] = make_float2(acc[n][2] + bb0, acc[n][3] + bb1);
    }
}

// ---------------- tf32 mask-split MMA helpers for expm (R13 proven) --------
struct AFrag { unsigned h[2][4]; unsigned l[2][4]; };

__device__ __forceinline__ void load_af(const float* M, int g, int t, AFrag& f) {
    #pragma unroll
    for (int s = 0; s < 2; s++) {
        float v[4];
        v[0] = M[(g  )*20 + t     + 8*s];
        v[1] = M[(g+8)*20 + t     + 8*s];
        v[2] = M[(g  )*20 + t + 4 + 8*s];
        v[3] = M[(g+8)*20 + t + 4 + 8*s];
        #pragma unroll
        for (int q = 0; q < 4; q++)
            tfsplit(v[q], f.h[s][q], f.l[s][q]);
    }
}

__device__ __forceinline__ void mm16(float D[2][4], const AFrag& a,
                                     const float* Y, int g, int t) {
    #pragma unroll
    for (int j = 0; j < 2; j++)
        #pragma unroll
        for (int s = 0; s < 2; s++) {
            float v0 = Y[(t     + 8*s)*20 + g + 8*j];
            float v1 = Y[(t + 4 + 8*s)*20 + g + 8*j];
            unsigned bh[2], bl[2];
            tfsplit(v0, bh[0], bl[0]);
            tfsplit(v1, bh[1], bl[1]);
            mma8(D[j], a.h[s], bl);
            mma8(D[j], a.l[s], bh);
            mma8(D[j], a.h[s], bh);
        }
}

__device__ __forceinline__ void st_cr(float* M, const float D[2][4], int g, int t) {
    *(float2*)&M[(g  )*20 + 2*t    ] = make_float2(D[0][0], D[0][1]);
    *(float2*)&M[(g  )*20 + 2*t + 8] = make_float2(D[1][0], D[1][1]);
    *(float2*)&M[(g+8)*20 + 2*t    ] = make_float2(D[0][2], D[0][3]);
    *(float2*)&M[(g+8)*20 + 2*t + 8] = make_float2(D[1][2], D[1][3]);
}

// ---------------- kernel D: expm via mask-split 3xTF32 MMA (R13) -----------
#define EXPM_BLOCKS 1024
#define NPAIRS (NB*SEQ*SEQ)      // 65536

__global__ void __launch_bounds__(128)
expm_kernel(const float* __restrict__ xm_g, float* __restrict__ Tout)
{
    __shared__ __align__(16) float mm[4*4*320];   // 4 warps x (A,A2,A3,T) x 320
    int tid = threadIdx.x, lane = tid & 31, w = tid >> 5;
    float* Ab  = mm + w*1280;
    float* A2b = Ab + 320;
    float* A3b = Ab + 640;
    float* Tb  = Ab + 960;

    int g = lane >> 2;       // row group 0..7 (rows g, g+8)
    int t = lane & 3;        // col group

    const float c3=1.f/6.f, c4=1.f/24.f, c5=1.f/120.f;
    const float c6=1.f/720.f, c7=1.f/5040.f, c8=1.f/40320.f, c9=1.f/362880.f;

    float dg[2][4];
    #pragma unroll
    for (int j = 0; j < 2; j++)
        #pragma unroll
        for (int q = 0; q < 4; q++)
            dg[j][q] = ((g + 8*(q>>1)) == (2*t + (q&1) + 8*j)) ? 1.f : 0.f;

    for (int p = blockIdx.x*4 + w; p < NPAIRS; p += EXPM_BLOCKS*4) {
        int row = p >> 7;
        int i   = p & 127;
        int b   = row >> 7;

        // ---- scatter lie -> skew A ----
        const float* lr = g_lie + (size_t)p*SO;
        if (lane < 16) Ab[lane*20 + lane] = 0.f;
        #pragma unroll
        for (int q = 0; q < 4; q++) {
            int l = lane + 32*q;
            if (l < SO) {
                float v = lr[l];
                int rI = c_tri_r[l], cI = c_tri_c[l];
                Ab[rI*20 + cI] =  v;
                Ab[cI*20 + rI] = -v;
            }
        }
        __syncwarp();

        // ---- load A C-layout, norm, scale ----
        float Acr[2][4];
        {
            float2 v;
            v = *(float2*)&Ab[(g  )*20 + 2*t    ]; Acr[0][0]=v.x; Acr[0][1]=v.y;
            v = *(float2*)&Ab[(g  )*20 + 2*t + 8]; Acr[1][0]=v.x; Acr[1][1]=v.y;
            v = *(float2*)&Ab[(g+8)*20 + 2*t    ]; Acr[0][2]=v.x; Acr[0][3]=v.y;
            v = *(float2*)&Ab[(g+8)*20 + 2*t + 8]; Acr[1][2]=v.x; Acr[1][3]=v.y;
        }
        float rs0 = fabsf(Acr[0][0])+fabsf(Acr[0][1])+fabsf(Acr[1][0])+fabsf(Acr[1][1]);
        float rs1 = fabsf(Acr[0][2])+fabsf(Acr[0][3])+fabsf(Acr[1][2])+fabsf(Acr[1][3]);
        #pragma unroll
        for (int off = 1; off <= 2; off <<= 1) {
            rs0 += __shfl_xor_sync(0xffffffffu, rs0, off);
            rs1 += __shfl_xor_sync(0xffffffffu, rs1, off);
        }
        float mx = fmaxf(rs0, rs1);
        #pragma unroll
        for (int off = 4; off <= 16; off <<= 1)
            mx = fmaxf(mx, __shfl_xor_sync(0xffffffffu, mx, off));
        int sct = 0;
        if (mx > 1.f) { sct = (int)ceilf(log2f(mx)); if (sct > 12) sct = 12; }
        float scale = __uint_as_float((uint32_t)(127 - sct) << 23);
        #pragma unroll
        for (int j = 0; j < 2; j++)
            #pragma unroll
            for (int q = 0; q < 4; q++) Acr[j][q] *= scale;
        st_cr(Ab, Acr, g, t);
        __syncwarp();

        // ---- A2 = A*A ----
        AFrag fA;
        load_af(Ab, g, t, fA);
        float A2cr[2][4] = {{0.f,0.f,0.f,0.f},{0.f,0.f,0.f,0.f}};
        mm16(A2cr, fA, Ab, g, t);
        st_cr(A2b, A2cr, g, t);
        __syncwarp();

        // ---- A3 = A*A2 (A-frag reuse) ----
        float A3cr[2][4] = {{0.f,0.f,0.f,0.f},{0.f,0.f,0.f,0.f}};
        mm16(A3cr, fA, A2b, g, t);

        // ---- B2 = c6 I + c7 A + c8 A2 + c9 A3 -> Tb; store A3 -> A3b ----
        {
            float E[2][4];
            #pragma unroll
            for (int j = 0; j < 2; j++)
                #pragma unroll
                for (int q = 0; q < 4; q++)
                    E[j][q] = fmaf(c6, dg[j][q],
                              fmaf(c7, Acr[j][q],
                              fmaf(c8, A2cr[j][q], c9 * A3cr[j][q])));
            st_cr(Tb, E, g, t);
        }
        st_cr(A3b, A3cr, g, t);
        __syncwarp();

        // ---- M = A3*B2 + (c3 I + c4 A + c5 A2) ----
        AFrag f3;
        load_af(A3b, g, t, f3);
        float R[2][4];
        #pragma unroll
        for (int j = 0; j < 2; j++)
            #pragma unroll
            for (int q = 0; q < 4; q++)
                R[j][q] = fmaf(c3, dg[j][q],
                          fmaf(c4, Acr[j][q], c5 * A2cr[j][q]));
        mm16(R, f3, Tb, g, t);
        __syncwarp();
        st_cr(Tb, R, g, t);
        __syncwarp();

        // ---- R = A3*M + (I + A + A2/2) ----
        #pragma unroll
        for (int j = 0; j < 2; j++)
            #pragma unroll
            for (int q = 0; q < 4; q++)
                R[j][q] = fmaf(0.5f, A2cr[j][q], Acr[j][q]) + dg[j][q];
        mm16(R, f3, Tb, g, t);

        // ---- squarings ----
        for (int q = 0; q < sct; q++) {
            __syncwarp();
            st_cr(Tb, R, g, t);
            __syncwarp();
            AFrag fR;
            load_af(Tb, g, t, fR);
            float R2[2][4] = {{0.f,0.f,0.f,0.f},{0.f,0.f,0.f,0.f}};
            mm16(R2, fR, Tb, g, t);
            #pragma unroll
            for (int j = 0; j < 2; j++)
                #pragma unroll
                for (int qq = 0; qq < 4; qq++) R[j][qq] = R2[j][qq];
        }

        // ---- write T_all ----
        float* dst = Tout + (size_t)p*256;
        *(float2*)&dst[(g  )*16 + 2*t    ] = make_float2(R[0][0], R[0][1]);
        *(float2*)&dst[(g  )*16 + 2*t + 8] = make_float2(R[1][0], R[1][1]);
        *(float2*)&dst[(g+8)*16 + 2*t    ] = make_float2(R[0][2], R[0][3]);
        *(float2*)&dst[(g+8)*16 + 2*t + 8] = make_float2(R[1][2], R[1][3]);

        // ---- transported & settled ----
        const float* xv = xm_g + ((size_t)b*SEQ + i)*DM;
        float x0 = xv[2*t], x1 = xv[2*t+1], x2 = xv[2*t+8], x3 = xv[2*t+9];
        float pg  = R[0][0]*x0 + R[0][1]*x1 + R[1][0]*x2 + R[1][1]*x3;
        float pg8 = R[0][2]*x0 + R[0][3]*x1 + R[1][2]*x2 + R[1][3]*x3;
        #pragma unroll
        for (int off = 1; off <= 2; off <<= 1) {
            pg  += __shfl_xor_sync(0xffffffffu, pg,  off);
            pg8 += __shfl_xor_sync(0xffffffffu, pg8, off);
        }
        if (t == 0) {
            float wgt = g_attn[row*SEQ + i];
            atomicAdd(&g_settled[row*DM + g    ], wgt * pg);
            atomicAdd(&g_settled[row*DM + g + 8], wgt * pg8);
        }
        __syncwarp();
    }
}

// ---------------- kernel E: out projection ---------------------------------
__global__ void __launch_bounds__(256)
out_kernel(const float* __restrict__ Wo, const float* __restrict__ bo,
           float* __restrict__ out)
{
    int gid = blockIdx.x*256 + threadIdx.x;    // 8192
    int row = gid >> 4, d = gid & 15;
    float acc = bo[d];
    #pragma unroll
    for (int e = 0; e < DM; e++)
        acc = fmaf(Wo[d*DM + e], g_settled[row*DM + e], acc);
    out[gid] = acc;
}

// ---------------- launch ----------------------------------------------------
extern "C" void kernel_launch(void* const* d_in, const int* in_sizes, int n_in,
                              void* d_out, int out_size)
{
    const float* xl  = (const float*)d_in[0];
    const float* xmm = (const float*)d_in[1];
    const float* Wq  = (const float*)d_in[2];
    const float* bq  = (const float*)d_in[3];
    const float* Wk  = (const float*)d_in[4];
    const float* bk  = (const float*)d_in[5];
    const float* W1  = (const float*)d_in[6];
    const float* b1  = (const float*)d_in[7];
    const float* W2  = (const float*)d_in[8];
    const float* b2  = (const float*)d_in[9];
    const float* Wo  = (const float*)d_in[10];
    const float* bo  = (const float*)d_in[11];

    float* out  = (float*)d_out;
    float* Tout = out + NB*SEQ*DM;      // T_all follows out

    static bool attr_set = false;
    if (!attr_set) {
        cudaFuncSetAttribute(attn_kernel, cudaFuncAttributeMaxDynamicSharedMemorySize, AT_BYTES);
        cudaFuncSetAttribute(pair_kernel, cudaFuncAttributeMaxDynamicSharedMemorySize, PK_BYTES);
        attr_set = true;
    }

    prep_kernel<<<dim3(8,8), 256>>>(xl, Wq, bq, Wk, bk, W1);
    w2split_kernel<<<64, 256>>>(W2);
    attn_kernel<<<16, 256, AT_BYTES>>>();
    pair_kernel<<<ROWS, 256, PK_BYTES>>>(b1, b2);
    expm_kernel<<<EXPM_BLOCKS, 128>>>(xmm, Tout);
    out_kernel<<<32, 256>>>(Wo, bo, out);
}

// round 15
// speedup vs baseline: 1.7791x; 1.1359x over previous
#include <cuda_runtime.h>
#include <math.h>
#include <stdint.h>

#define NB 4
#define SEQ 128
#define DL 128
#define DM 16
#define SO 120
#define ROWS (NB*SEQ)        // 512

// ---------------- scratch ----------------------------------------------------
__device__ float g_Q[ROWS*DL];
__device__ float g_K[ROWS*DL];
__device__ float g_U[ROWS*256];
__device__ float g_attn[NB*SEQ*SEQ];
__device__ float g_lie[(size_t)NB*SEQ*SEQ*SO];   // 31.5 MB
__device__ float g_settled[ROWS*DM];
__device__ unsigned g_W2bh[128*128];             // W2^T bf16x2 hi words [kword][c]
__device__ unsigned g_W2bl[128*128];             // W2^T bf16x2 lo words [kword][c]

__constant__ int c_tri_r[120] = {
 0,0,0,0,0,0,0,0,0,0,0,0,0,0,0,
 1,1,1,1,1,1,1,1,1,1,1,1,1,1,
 2,2,2,2,2,2,2,2,2,2,2,2,2,
 3,3,3,3,3,3,3,3,3,3,3,3,
 4,4,4,4,4,4,4,4,4,4,4,
 5,5,5,5,5,5,5,5,5,5,
 6,6,6,6,6,6,6,6,6,
 7,7,7,7,7,7,7,7,
 8,8,8,8,8,8,8,
 9,9,9,9,9,9,
 10,10,10,10,10,
 11,11,11,11,
 12,12,12,
 13,13,
 14};
__constant__ int c_tri_c[120] = {
 1,2,3,4,5,6,7,8,9,10,11,12,13,14,15,
 2,3,4,5,6,7,8,9,10,11,12,13,14,15,
 3,4,5,6,7,8,9,10,11,12,13,14,15,
 4,5,6,7,8,9,10,11,12,13,14,15,
 5,6,7,8,9,10,11,12,13,14,15,
 6,7,8,9,10,11,12,13,14,15,
 7,8,9,10,11,12,13,14,15,
 8,9,10,11,12,13,14,15,
 9,10,11,12,13,14,15,
 10,11,12,13,14,15,
 11,12,13,14,15,
 12,13,14,15,
 13,14,15,
 14,15,
 15};

__device__ __forceinline__ float ftanh(float x) {
    float y;
    asm("tanh.approx.f32 %0, %1;" : "=f"(y) : "f"(x));
    return y;
}

// bf16x2 split-pack: word = {x1_bf16, x0_bf16}; hi = truncated top-16,
// lo = bf16 of exact remainder. Dropped error ~2^-16 per element.
__device__ __forceinline__ void bfsplit2(float x0, float x1, unsigned& hi, unsigned& lo) {
    unsigned h0 = __float_as_uint(x0) & 0xffff0000u;
    unsigned h1 = __float_as_uint(x1) & 0xffff0000u;
    hi = h1 | (h0 >> 16);
    float l0 = x0 - __uint_as_float(h0);
    float l1 = x1 - __uint_as_float(h1);
    lo = (__float_as_uint(l1) & 0xffff0000u) | (__float_as_uint(l0) >> 16);
}

__device__ __forceinline__ void mma16(float* d, const unsigned* a, const unsigned* b) {
    asm("mma.sync.aligned.m16n8k16.row.col.f32.bf16.bf16.f32 "
        "{%0,%1,%2,%3}, {%4,%5,%6,%7}, {%8,%9}, {%0,%1,%2,%3};"
        : "+f"(d[0]), "+f"(d[1]), "+f"(d[2]), "+f"(d[3])
        : "r"(a[0]), "r"(a[1]), "r"(a[2]), "r"(a[3]), "r"(b[0]), "r"(b[1]));
}

// ---------------- kernel A: tiled GEMM  C[512 x 512] = X @ [Wq;Wk;W1]^T ----
__global__ void __launch_bounds__(256)
prep_kernel(const float* __restrict__ xl,
            const float* __restrict__ Wq, const float* __restrict__ bq,
            const float* __restrict__ Wk, const float* __restrict__ bk,
            const float* __restrict__ W1)
{
    __shared__ __align__(16) float Xs[64*64];
    __shared__ __align__(16) float Wt[64*68];

    int bx = blockIdx.x, by = blockIdx.y;
    int t  = threadIdx.x;
    int tx = t & 15, ty = t >> 4;

    const float* src;
    if      (by < 2) src = Wq + (by    )*64*DL;
    else if (by < 4) src = Wk + (by - 2)*64*DL;
    else             src = W1 + (by - 4)*64*DL;

    float acc[4][4];
    #pragma unroll
    for (int i = 0; i < 4; i++)
        #pragma unroll
        for (int j = 0; j < 4; j++) acc[i][j] = 0.f;

    for (int k0 = 0; k0 < DL; k0 += 64) {
        __syncthreads();
        #pragma unroll
        for (int s = 0; s < 16; s++) {
            int idx = t + 256*s;
            int r = idx >> 6, k = idx & 63;
            Xs[r*64 + k] = xl[(bx*64 + r)*DL + k0 + k];
            Wt[k*68 + r] = src[r*DL + k0 + k];
        }
        __syncthreads();

        #pragma unroll 8
        for (int k = 0; k < 64; k++) {
            float4 bv = *(const float4*)&Wt[k*68 + tx*4];
            #pragma unroll
            for (int i = 0; i < 4; i++) {
                float a = Xs[(ty*4 + i)*64 + k];
                acc[i][0] = fmaf(a, bv.x, acc[i][0]);
                acc[i][1] = fmaf(a, bv.y, acc[i][1]);
                acc[i][2] = fmaf(a, bv.z, acc[i][2]);
                acc[i][3] = fmaf(a, bv.w, acc[i][3]);
            }
        }
    }

    #pragma unroll
    for (int i = 0; i < 4; i++) {
        int rowg = bx*64 + ty*4 + i;
        int c0   = tx*4;
        if (by < 2) {
            int col = by*64 + c0;
            *(float4*)&g_Q[rowg*DL + col] =
                make_float4(acc[i][0]+bq[col], acc[i][1]+bq[col+1],
                            acc[i][2]+bq[col+2], acc[i][3]+bq[col+3]);
        } else if (by < 4) {
            int col = (by-2)*64 + c0;
            *(float4*)&g_K[rowg*DL + col] =
                make_float4(acc[i][0]+bk[col], acc[i][1]+bk[col+1],
                            acc[i][2]+bk[col+2], acc[i][3]+bk[col+3]);
        } else {
            int col = (by-4)*64 + c0;
            *(float4*)&g_U[rowg*256 + col] =
                make_float4(acc[i][0], acc[i][1], acc[i][2], acc[i][3]);
        }
    }
}

// ---------------- kernel A2: pack W2^T into bf16x2 hi/lo words [kword][c] --
__global__ void __launch_bounds__(256)
w2split_kernel(const float* __restrict__ W2)
{
    int idx = blockIdx.x*256 + threadIdx.x;   // 16384 = 128 kwords x 128 c
    int w = idx >> 7, c = idx & 127;
    float v0 = (c < SO) ? W2[c*256 + 2*w    ] : 0.f;
    float v1 = (c < SO) ? W2[c*256 + 2*w + 1] : 0.f;
    unsigned hi, lo;
    bfsplit2(v0, v1, hi, lo);
    g_W2bh[idx] = hi;
    g_W2bl[idx] = lo;
}

// ---------------- kernel B: attention softmax (+ zero g_settled) -----------
#define AT_QS 0
#define AT_KT (AT_QS + 32*128)
#define AT_S  (AT_KT + 128*132)
#define AT_FLOATS (AT_S + 32*132)
#define AT_BYTES  (AT_FLOATS*4)

__global__ void __launch_bounds__(256)
attn_kernel()
{
    extern __shared__ float sm[];
    float* Qs = sm + AT_QS;
    float* Kt = sm + AT_KT;
    float* S  = sm + AT_S;

    int b  = blockIdx.x >> 2;
    int jt = (blockIdx.x & 3) * 32;
    int t  = threadIdx.x;
    int tx = t & 15, ty = t >> 4;

    for (int z = t; z < 512; z += 256) g_settled[blockIdx.x*512 + z] = 0.f;

    for (int idx = t; idx < 32*128; idx += 256) {
        int j = idx >> 7, k = idx & 127;
        Qs[j*128 + k] = g_Q[(b*SEQ + jt + j)*DL + k];
    }
    for (int idx = t; idx < 128*128; idx += 256) {
        int i = idx >> 7, k = idx & 127;
        Kt[k*132 + i] = g_K[(b*SEQ + i)*DL + k];
    }
    __syncthreads();

    float acc[2][8];
    #pragma unroll
    for (int i = 0; i < 2; i++)
        #pragma unroll
        for (int j = 0; j < 8; j++) acc[i][j] = 0.f;

    int j0 = ty*2, i0 = tx*8;
    #pragma unroll 4
    for (int k = 0; k < 128; k++) {
        float q0 = Qs[(j0  )*128 + k];
        float q1 = Qs[(j0+1)*128 + k];
        float4 k0v = *(const float4*)&Kt[k*132 + i0];
        float4 k1v = *(const float4*)&Kt[k*132 + i0 + 4];
        acc[0][0]=fmaf(q0,k0v.x,acc[0][0]); acc[0][1]=fmaf(q0,k0v.y,acc[0][1]);
        acc[0][2]=fmaf(q0,k0v.z,acc[0][2]); acc[0][3]=fmaf(q0,k0v.w,acc[0][3]);
        acc[0][4]=fmaf(q0,k1v.x,acc[0][4]); acc[0][5]=fmaf(q0,k1v.y,acc[0][5]);
        acc[0][6]=fmaf(q0,k1v.z,acc[0][6]); acc[0][7]=fmaf(q0,k1v.w,acc[0][7]);
        acc[1][0]=fmaf(q1,k0v.x,acc[1][0]); acc[1][1]=fmaf(q1,k0v.y,acc[1][1]);
        acc[1][2]=fmaf(q1,k0v.z,acc[1][2]); acc[1][3]=fmaf(q1,k0v.w,acc[1][3]);
        acc[1][4]=fmaf(q1,k1v.x,acc[1][4]); acc[1][5]=fmaf(q1,k1v.y,acc[1][5]);
        acc[1][6]=fmaf(q1,k1v.z,acc[1][6]); acc[1][7]=fmaf(q1,k1v.w,acc[1][7]);
    }
    const float sc = 0.08838834764831845f;
    #pragma unroll
    for (int i = 0; i < 2; i++) {
        *(float4*)&S[(j0+i)*132 + i0] =
            make_float4(acc[i][0]*sc, acc[i][1]*sc, acc[i][2]*sc, acc[i][3]*sc);
        *(float4*)&S[(j0+i)*132 + i0 + 4] =
            make_float4(acc[i][4]*sc, acc[i][5]*sc, acc[i][6]*sc, acc[i][7]*sc);
    }
    __syncthreads();

    int w = t >> 5, lane = t & 31;
    for (int q = 0; q < 4; q++) {
        int r = w*4 + q;
        float v0 = S[r*132 + lane      ];
        float v1 = S[r*132 + lane + 32 ];
        float v2 = S[r*132 + lane + 64 ];
        float v3 = S[r*132 + lane + 96 ];
        float mx = fmaxf(fmaxf(v0,v1), fmaxf(v2,v3));
        #pragma unroll
        for (int off = 16; off; off >>= 1)
            mx = fmaxf(mx, __shfl_xor_sync(0xffffffffu, mx, off));
        float e0 = expf(v0-mx), e1 = expf(v1-mx), e2 = expf(v2-mx), e3 = expf(v3-mx);
        float sum = e0+e1+e2+e3;
        #pragma unroll
        for (int off = 16; off; off >>= 1)
            sum += __shfl_xor_sync(0xffffffffu, sum, off);
        float inv = 1.f/sum;
        float* dst = g_attn + (b*SEQ + jt + r)*SEQ;
        dst[lane     ] = e0*inv;
        dst[lane + 32] = e1*inv;
        dst[lane + 64] = e2*inv;
        dst[lane + 96] = e3*inv;
    }
}

// ---------------- kernel C: pairwise MLP GEMM via split-BF16 m16n8k16 ------
// (R14 proven, unchanged)
#define PK_UJB 0
#define PK_B2  (PK_UJB + 256)
#define PK_HWH (PK_B2 + 128)
#define PK_HWL (PK_HWH + 128*20)
#define PK_BWH (PK_HWL + 128*20)
#define PK_BWL (PK_BWH + 16*136)
#define PK_FLOATS (PK_BWL + 16*136)
#define PK_BYTES  (PK_FLOATS*4)

__global__ void __launch_bounds__(256, 2)
pair_kernel(const float* __restrict__ b1, const float* __restrict__ b2)
{
    extern __shared__ float psm[];
    float*    Ujb = psm + PK_UJB;
    float*    b2s = psm + PK_B2;
    unsigned* Hwh = (unsigned*)(psm + PK_HWH);
    unsigned* Hwl = (unsigned*)(psm + PK_HWL);
    unsigned* Bwh = (unsigned*)(psm + PK_BWH);
    unsigned* Bwl = (unsigned*)(psm + PK_BWL);

    int row = blockIdx.x;          // b*128 + j
    int b   = row >> 7;
    int t   = threadIdx.x;
    int lane = t & 31, w = t >> 5;
    int g = lane >> 2, tt = lane & 3;
    int ibase = w * 16;

    Ujb[t] = g_U[row*256 + t] + b1[t];
    if (t < 128) b2s[t] = (t < SO) ? b2[t] : 0.f;

    float acc[15][4];
    #pragma unroll
    for (int n = 0; n < 15; n++)
        #pragma unroll
        for (int q = 0; q < 4; q++) acc[n][q] = 0.f;

    for (int k0 = 0; k0 < 256; k0 += 32) {
        __syncthreads();
        #pragma unroll
        for (int s = 0; s < 8; s++) {
            int idx = t + 256*s;
            int i = idx >> 4, kw = idx & 15;
            float2 u  = *(const float2*)&g_U[(b*SEQ + i)*256 + k0 + 2*kw];
            float2 uj = *(const float2*)&Ujb[k0 + 2*kw];
            float h0 = ftanh(uj.x - u.x);
            float h1 = ftanh(uj.y - u.y);
            unsigned hi, lo;
            bfsplit2(h0, h1, hi, lo);
            Hwh[i*20 + kw] = hi;
            Hwl[i*20 + kw] = lo;
        }
        #pragma unroll
        for (int s = 0; s < 8; s++) {
            int idx = t + 256*s;
            int kw = idx >> 7, c = idx & 127;
            Bwh[kw*136 + c] = g_W2bh[(k0/2 + kw)*128 + c];
            Bwl[kw*136 + c] = g_W2bl[(k0/2 + kw)*128 + c];
        }
        __syncthreads();

        #pragma unroll
        for (int s = 0; s < 2; s++) {
            int hb = (ibase + g)*20 + 8*s;
            unsigned ah[4], al[4];
            ah[0] = Hwh[hb + tt];           al[0] = Hwl[hb + tt];
            ah[1] = Hwh[hb + 160 + tt];     al[1] = Hwl[hb + 160 + tt];
            ah[2] = Hwh[hb + tt + 4];       al[2] = Hwl[hb + tt + 4];
            ah[3] = Hwh[hb + 160 + tt + 4]; al[3] = Hwl[hb + 160 + tt + 4];
            int kb0 = (8*s + tt    )*136;
            int kb1 = (8*s + tt + 4)*136;
            #pragma unroll
            for (int n = 0; n < 15; n++) {
                int cb = n*8 + g;
                unsigned bh[2] = { Bwh[kb0 + cb], Bwh[kb1 + cb] };
                unsigned bl[2] = { Bwl[kb0 + cb], Bwl[kb1 + cb] };
                mma16(acc[n], ah, bl);
                mma16(acc[n], al, bh);
                mma16(acc[n], ah, bh);
            }
        }
    }

    size_t p0 = (size_t)row*SEQ + ibase + g;
    size_t p1 = p0 + 8;
    #pragma unroll
    for (int n = 0; n < 15; n++) {
        int c = 8*n + 2*tt;
        float bb0 = b2s[c], bb1 = b2s[c+1];
        *(float2*)&g_lie[p0*SO + c] = make_float2(acc[n][0] + bb0, acc[n][1] + bb1);
        *(float2*)&g_lie[p1*SO + c] = make_float2(acc[n][2] + bb0, acc[n][3] + bb1);
    }
}

// ---------------- expm bf16 helpers ----------------------------------------
// pack A-fragment (m16n8k16 layout) from C-layout regs D[2][4]
__device__ __forceinline__ void packA(const float D[2][4], unsigned ah[4], unsigned al[4]) {
    bfsplit2(D[0][0], D[0][1], ah[0], al[0]);   // row g,   k=2t,2t+1
    bfsplit2(D[0][2], D[0][3], ah[1], al[1]);   // row g+8, k=2t,2t+1
    bfsplit2(D[1][0], D[1][1], ah[2], al[2]);   // row g,   k=2t+8,2t+9
    bfsplit2(D[1][2], D[1][3], ah[3], al[3]);   // row g+8, k=2t+8,2t+9
}

// D += X * Y with X A-frag given, Y as packed B-buffer (outer*12 + word idx)
__device__ __forceinline__ void mm16b(float D[2][4],
                                      const unsigned ah[4], const unsigned al[4],
                                      const unsigned* Yh, const unsigned* Yl,
                                      int g, int t) {
    #pragma unroll
    for (int j = 0; j < 2; j++) {
        int base = (8*j + g)*12;
        unsigned bh[2] = { Yh[base + t], Yh[base + t + 4] };
        unsigned bl[2] = { Yl[base + t], Yl[base + t + 4] };
        mma16(D[j], ah, bl);
        mma16(D[j], al, bh);
        mma16(D[j], ah, bh);
    }
}

// true k-pack store (for general matrices used as B operand): element (r,c)
// -> halfword (c*12 + (r>>1))*2 + (r&1) in hi/lo u16 arrays
__device__ __forceinline__ void kpack_store(unsigned short* Yh, unsigned short* Yl,
                                            const float D[2][4], int g, int t) {
    #pragma unroll
    for (int j = 0; j < 2; j++)
        #pragma unroll
        for (int q = 0; q < 4; q++) {
            int r = g + 8*(q >> 1);
            int c = 2*t + (q & 1) + 8*j;
            float x = D[j][q];
            unsigned hb = __float_as_uint(x) & 0xffff0000u;
            float lof = x - __uint_as_float(hb);
            unsigned lb = __float_as_uint(lof);
            int hw = (c*12 + (r >> 1))*2 + (r & 1);
            Yh[hw] = (unsigned short)(hb >> 16);
            Yl[hw] = (unsigned short)(lb >> 16);
        }
}

// ---------------- kernel D: expm via split-BF16 m16n8k16 -------------------
#define EXPM_BLOCKS 1024
#define NPAIRS (NB*SEQ*SEQ)      // 65536

__global__ void __launch_bounds__(128)
expm_kernel(const float* __restrict__ xm_g, float* __restrict__ Tout)
{
    // per warp: scratch[320] f32 | A2h[192] | A2l[192] | Tbh[192] | Tbl[192]
    __shared__ __align__(16) float mm[4*(320 + 4*192)];
    int tid = threadIdx.x, lane = tid & 31, w = tid >> 5;
    float* scr = mm + w*(320 + 768);
    unsigned* A2hB = (unsigned*)(scr + 320);
    unsigned* A2lB = A2hB + 192;
    unsigned* TbhB = A2lB + 192;
    unsigned* TblB = TbhB + 192;
    unsigned short* Tbh16 = (unsigned short*)TbhB;
    unsigned short* Tbl16 = (unsigned short*)TblB;

    int g = lane >> 2;       // row group 0..7 (rows g, g+8)
    int t = lane & 3;        // col group

    const float c3=1.f/6.f, c4=1.f/24.f, c5=1.f/120.f;
    const float c6=1.f/720.f, c7=1.f/5040.f, c8=1.f/40320.f, c9=1.f/362880.f;
    const unsigned FLIP = 0x80008000u;

    float dg[2][4];
    #pragma unroll
    for (int j = 0; j < 2; j++)
        #pragma unroll
        for (int q = 0; q < 4; q++)
            dg[j][q] = ((g + 8*(q>>1)) == (2*t + (q&1) + 8*j)) ? 1.f : 0.f;

    for (int p = blockIdx.x*4 + w; p < NPAIRS; p += EXPM_BLOCKS*4) {
        int row = p >> 7;
        int i   = p & 127;
        int b   = row >> 7;

        // ---- scatter lie -> skew A (fp32 scratch, stride 20) ----
        const float* lr = g_lie + (size_t)p*SO;
        if (lane < 16) scr[lane*20 + lane] = 0.f;
        #pragma unroll
        for (int q = 0; q < 4; q++) {
            int l = lane + 32*q;
            if (l < SO) {
                float v = lr[l];
                int rI = c_tri_r[l], cI = c_tri_c[l];
                scr[rI*20 + cI] =  v;
                scr[cI*20 + rI] = -v;
            }
        }
        __syncwarp();

        // ---- load A C-layout, norm, scale ----
        float Acr[2][4];
        {
            float2 v;
            v = *(float2*)&scr[(g  )*20 + 2*t    ]; Acr[0][0]=v.x; Acr[0][1]=v.y;
            v = *(float2*)&scr[(g  )*20 + 2*t + 8]; Acr[1][0]=v.x; Acr[1][1]=v.y;
            v = *(float2*)&scr[(g+8)*20 + 2*t    ]; Acr[0][2]=v.x; Acr[0][3]=v.y;
            v = *(float2*)&scr[(g+8)*20 + 2*t + 8]; Acr[1][2]=v.x; Acr[1][3]=v.y;
        }
        float rs0 = fabsf(Acr[0][0])+fabsf(Acr[0][1])+fabsf(Acr[1][0])+fabsf(Acr[1][1]);
        float rs1 = fabsf(Acr[0][2])+fabsf(Acr[0][3])+fabsf(Acr[1][2])+fabsf(Acr[1][3]);
        #pragma unroll
        for (int off = 1; off <= 2; off <<= 1) {
            rs0 += __shfl_xor_sync(0xffffffffu, rs0, off);
            rs1 += __shfl_xor_sync(0xffffffffu, rs1, off);
        }
        float mx = fmaxf(rs0, rs1);
        #pragma unroll
        for (int off = 4; off <= 16; off <<= 1)
            mx = fmaxf(mx, __shfl_xor_sync(0xffffffffu, mx, off));
        int sct = 0;
        if (mx > 1.f) { sct = (int)ceilf(log2f(mx)); if (sct > 12) sct = 12; }
        float scale = __uint_as_float((uint32_t)(127 - sct) << 23);
        #pragma unroll
        for (int j = 0; j < 2; j++)
            #pragma unroll
            for (int q = 0; q < 4; q++) Acr[j][q] *= scale;

        // ---- A-frag of A (registers only) ----
        unsigned aAh[4], aAl[4];
        packA(Acr, aAh, aAl);

        // ---- A2 = A*A ; B-operand = -A = flip of own A-frag words ----
        float A2cr[2][4] = {{0.f,0.f,0.f,0.f},{0.f,0.f,0.f,0.f}};
        {
            unsigned bh0[2] = { aAh[0]^FLIP, aAh[2]^FLIP };
            unsigned bl0[2] = { aAl[0]^FLIP, aAl[2]^FLIP };
            mma16(A2cr[0], aAh, bl0); mma16(A2cr[0], aAl, bh0); mma16(A2cr[0], aAh, bh0);
            unsigned bh1[2] = { aAh[1]^FLIP, aAh[3]^FLIP };
            unsigned bl1[2] = { aAl[1]^FLIP, aAl[3]^FLIP };
            mma16(A2cr[1], aAh, bl1); mma16(A2cr[1], aAl, bh1); mma16(A2cr[1], aAh, bh1);
        }

        // ---- store A2 row-pack (== its B-pack: A2 exactly symmetric) ----
        {
            unsigned w0h,w0l,w1h,w1l,w2h,w2l,w3h,w3l;
            bfsplit2(A2cr[0][0], A2cr[0][1], w0h, w0l);
            bfsplit2(A2cr[0][2], A2cr[0][3], w1h, w1l);
            bfsplit2(A2cr[1][0], A2cr[1][1], w2h, w2l);
            bfsplit2(A2cr[1][2], A2cr[1][3], w3h, w3l);
            A2hB[(g  )*12 + t    ] = w0h;  A2lB[(g  )*12 + t    ] = w0l;
            A2hB[(g+8)*12 + t    ] = w1h;  A2lB[(g+8)*12 + t    ] = w1l;
            A2hB[(g  )*12 + t + 4] = w2h;  A2lB[(g  )*12 + t + 4] = w2l;
            A2hB[(g+8)*12 + t + 4] = w3h;  A2lB[(g+8)*12 + t + 4] = w3l;
        }
        __syncwarp();

        // ---- A3 = A*A2 ----
        float A3cr[2][4] = {{0.f,0.f,0.f,0.f},{0.f,0.f,0.f,0.f}};
        mm16b(A3cr, aAh, aAl, A2hB, A2lB, g, t);

        // ---- B2 = c6 I + c7 A + c8 A2 + c9 A3 -> Tb (k-pack) ----
        {
            float E[2][4];
            #pragma unroll
            for (int j = 0; j < 2; j++)
                #pragma unroll
                for (int q = 0; q < 4; q++)
                    E[j][q] = fmaf(c6, dg[j][q],
                              fmaf(c7, Acr[j][q],
                              fmaf(c8, A2cr[j][q], c9 * A3cr[j][q])));
            kpack_store(Tbh16, Tbl16, E, g, t);
        }
        unsigned a3h[4], a3l[4];
        packA(A3cr, a3h, a3l);
        __syncwarp();

        // ---- M = A3*B2 + (c3 I + c4 A + c5 A2) ----
        float R[2][4];
        #pragma unroll
        for (int j = 0; j < 2; j++)
            #pragma unroll
            for (int q = 0; q < 4; q++)
                R[j][q] = fmaf(c3, dg[j][q],
                          fmaf(c4, Acr[j][q], c5 * A2cr[j][q]));
        mm16b(R, a3h, a3l, TbhB, TblB, g, t);
        __syncwarp();                 // all lanes done reading B2
        kpack_store(Tbh16, Tbl16, R, g, t);
        __syncwarp();

        // ---- R = A3*M + (I + A + A2/2) ----
        #pragma unroll
        for (int j = 0; j < 2; j++)
            #pragma unroll
            for (int q = 0; q < 4; q++)
                R[j][q] = fmaf(0.5f, A2cr[j][q], Acr[j][q]) + dg[j][q];
        mm16b(R, a3h, a3l, TbhB, TblB, g, t);

        // ---- squarings: A-frag from regs, B from k-pack ----
        for (int q = 0; q < sct; q++) {
            __syncwarp();
            kpack_store(Tbh16, Tbl16, R, g, t);
            unsigned rh[4], rl[4];
            packA(R, rh, rl);
            __syncwarp();
            float Rn[2][4] = {{0.f,0.f,0.f,0.f},{0.f,0.f,0.f,0.f}};
            mm16b(Rn, rh, rl, TbhB, TblB, g, t);
            #pragma unroll
            for (int j = 0; j < 2; j++)
                #pragma unroll
                for (int qq = 0; qq < 4; qq++) R[j][qq] = Rn[j][qq];
        }

        // ---- write T_all ----
        float* dst = Tout + (size_t)p*256;
        *(float2*)&dst[(g  )*16 + 2*t    ] = make_float2(R[0][0], R[0][1]);
        *(float2*)&dst[(g  )*16 + 2*t + 8] = make_float2(R[1][0], R[1][1]);
        *(float2*)&dst[(g+8)*16 + 2*t    ] = make_float2(R[0][2], R[0][3]);
        *(float2*)&dst[(g+8)*16 + 2*t + 8] = make_float2(R[1][2], R[1][3]);

        // ---- transported & settled ----
        const float* xv = xm_g + ((size_t)b*SEQ + i)*DM;
        float x0 = xv[2*t], x1 = xv[2*t+1], x2 = xv[2*t+8], x3 = xv[2*t+9];
        float pg  = R[0][0]*x0 + R[0][1]*x1 + R[1][0]*x2 + R[1][1]*x3;
        float pg8 = R[0][2]*x0 + R[0][3]*x1 + R[1][2]*x2 + R[1][3]*x3;
        #pragma unroll
        for (int off = 1; off <= 2; off <<= 1) {
            pg  += __shfl_xor_sync(0xffffffffu, pg,  off);
            pg8 += __shfl_xor_sync(0xffffffffu, pg8, off);
        }
        if (t == 0) {
            float wgt = g_attn[row*SEQ + i];
            atomicAdd(&g_settled[row*DM + g    ], wgt * pg);
            atomicAdd(&g_settled[row*DM + g + 8], wgt * pg8);
        }
        __syncwarp();
    }
}

// ---------------- kernel E: out projection ---------------------------------
__global__ void __launch_bounds__(256)
out_kernel(const float* __restrict__ Wo, const float* __restrict__ bo,
           float* __restrict__ out)
{
    int gid = blockIdx.x*256 + threadIdx.x;    // 8192
    int row = gid >> 4, d = gid & 15;
    float acc = bo[d];
    #pragma unroll
    for (int e = 0; e < DM; e++)
        acc = fmaf(Wo[d*DM + e], g_settled[row*DM + e], acc);
    out[gid] = acc;
}

// ---------------- launch ----------------------------------------------------
extern "C" void kernel_launch(void* const* d_in, const int* in_sizes, int n_in,
                              void* d_out, int out_size)
{
    const float* xl  = (const float*)d_in[0];
    const float* xmm = (const float*)d_in[1];
    const float* Wq  = (const float*)d_in[2];
    const float* bq  = (const float*)d_in[3];
    const float* Wk  = (const float*)d_in[4];
    const float* bk  = (const float*)d_in[5];
    const float* W1  = (const float*)d_in[6];
    const float* b1  = (const float*)d_in[7];
    const float* W2  = (const float*)d_in[8];
    const float* b2  = (const float*)d_in[9];
    const float* Wo  = (const float*)d_in[10];
    const float* bo  = (const float*)d_in[11];

    float* out  = (float*)d_out;
    float* Tout = out + NB*SEQ*DM;      // T_all follows out

    static bool attr_set = false;
    if (!attr_set) {
        cudaFuncSetAttribute(attn_kernel, cudaFuncAttributeMaxDynamicSharedMemorySize, AT_BYTES);
        cudaFuncSetAttribute(pair_kernel, cudaFuncAttributeMaxDynamicSharedMemorySize, PK_BYTES);
        attr_set = true;
    }

    prep_kernel<<<dim3(8,8), 256>>>(xl, Wq, bq, Wk, bk, W1);
    w2split_kernel<<<64, 256>>>(W2);
    attn_kernel<<<16, 256, AT_BYTES>>>();
    pair_kernel<<<ROWS, 256, PK_BYTES>>>(b1, b2);
    expm_kernel<<<EXPM_BLOCKS, 128>>>(xmm, Tout);
    out_kernel<<<32, 256>>>(Wo, bo, out);
}

// round 16
// speedup vs baseline: 1.8429x; 1.0358x over previous
#include <cuda_runtime.h>
#include <math.h>
#include <stdint.h>

#define NB 4
#define SEQ 128
#define DL 128
#define DM 16
#define SO 120
#define ROWS (NB*SEQ)        // 512

// ---------------- scratch ----------------------------------------------------
__device__ float g_Q[ROWS*DL];
__device__ float g_K[ROWS*DL];
__device__ float g_U[ROWS*256];
__device__ float g_attn[NB*SEQ*SEQ];
__device__ float g_lie[(size_t)NB*SEQ*SEQ*SO];   // 31.5 MB
__device__ float g_settled[ROWS*DM];
__device__ unsigned g_W2bh[128*128];             // W2^T bf16x2 hi words [kword][c]
__device__ unsigned g_W2bl[128*128];             // W2^T bf16x2 lo words [kword][c]

__device__ __forceinline__ float ftanh(float x) {
    float y;
    asm("tanh.approx.f32 %0, %1;" : "=f"(y) : "f"(x));
    return y;
}

// bf16x2 split-pack: word = {x1_bf16, x0_bf16}; hi = truncated top-16,
// lo = bf16 of exact remainder. Dropped error ~2^-16 per element.
__device__ __forceinline__ void bfsplit2(float x0, float x1, unsigned& hi, unsigned& lo) {
    unsigned h0 = __float_as_uint(x0) & 0xffff0000u;
    unsigned h1 = __float_as_uint(x1) & 0xffff0000u;
    hi = h1 | (h0 >> 16);
    float l0 = x0 - __uint_as_float(h0);
    float l1 = x1 - __uint_as_float(h1);
    lo = (__float_as_uint(l1) & 0xffff0000u) | (__float_as_uint(l0) >> 16);
}

__device__ __forceinline__ void mma16(float* d, const unsigned* a, const unsigned* b) {
    asm("mma.sync.aligned.m16n8k16.row.col.f32.bf16.bf16.f32 "
        "{%0,%1,%2,%3}, {%4,%5,%6,%7}, {%8,%9}, {%0,%1,%2,%3};"
        : "+f"(d[0]), "+f"(d[1]), "+f"(d[2]), "+f"(d[3])
        : "r"(a[0]), "r"(a[1]), "r"(a[2]), "r"(a[3]), "r"(b[0]), "r"(b[1]));
}

// ---------------- kernel A: tiled GEMM  C[512 x 512] = X @ [Wq;Wk;W1]^T ----
__global__ void __launch_bounds__(256)
prep_kernel(const float* __restrict__ xl,
            const float* __restrict__ Wq, const float* __restrict__ bq,
            const float* __restrict__ Wk, const float* __restrict__ bk,
            const float* __restrict__ W1)
{
    __shared__ __align__(16) float Xs[64*64];
    __shared__ __align__(16) float Wt[64*68];

    int bx = blockIdx.x, by = blockIdx.y;
    int t  = threadIdx.x;
    int tx = t & 15, ty = t >> 4;

    const float* src;
    if      (by < 2) src = Wq + (by    )*64*DL;
    else if (by < 4) src = Wk + (by - 2)*64*DL;
    else             src = W1 + (by - 4)*64*DL;

    float acc[4][4];
    #pragma unroll
    for (int i = 0; i < 4; i++)
        #pragma unroll
        for (int j = 0; j < 4; j++) acc[i][j] = 0.f;

    for (int k0 = 0; k0 < DL; k0 += 64) {
        __syncthreads();
        #pragma unroll
        for (int s = 0; s < 16; s++) {
            int idx = t + 256*s;
            int r = idx >> 6, k = idx & 63;
            Xs[r*64 + k] = xl[(bx*64 + r)*DL + k0 + k];
            Wt[k*68 + r] = src[r*DL + k0 + k];
        }
        __syncthreads();

        #pragma unroll 8
        for (int k = 0; k < 64; k++) {
            float4 bv = *(const float4*)&Wt[k*68 + tx*4];
            #pragma unroll
            for (int i = 0; i < 4; i++) {
                float a = Xs[(ty*4 + i)*64 + k];
                acc[i][0] = fmaf(a, bv.x, acc[i][0]);
                acc[i][1] = fmaf(a, bv.y, acc[i][1]);
                acc[i][2] = fmaf(a, bv.z, acc[i][2]);
                acc[i][3] = fmaf(a, bv.w, acc[i][3]);
            }
        }
    }

    #pragma unroll
    for (int i = 0; i < 4; i++) {
        int rowg = bx*64 + ty*4 + i;
        int c0   = tx*4;
        if (by < 2) {
            int col = by*64 + c0;
            *(float4*)&g_Q[rowg*DL + col] =
                make_float4(acc[i][0]+bq[col], acc[i][1]+bq[col+1],
                            acc[i][2]+bq[col+2], acc[i][3]+bq[col+3]);
        } else if (by < 4) {
            int col = (by-2)*64 + c0;
            *(float4*)&g_K[rowg*DL + col] =
                make_float4(acc[i][0]+bk[col], acc[i][1]+bk[col+1],
                            acc[i][2]+bk[col+2], acc[i][3]+bk[col+3]);
        } else {
            int col = (by-4)*64 + c0;
            *(float4*)&g_U[rowg*256 + col] =
                make_float4(acc[i][0], acc[i][1], acc[i][2], acc[i][3]);
        }
    }
}

// ---------------- kernel A2: pack W2^T into bf16x2 hi/lo words [kword][c] --
__global__ void __launch_bounds__(256)
w2split_kernel(const float* __restrict__ W2)
{
    int idx = blockIdx.x*256 + threadIdx.x;   // 16384 = 128 kwords x 128 c
    int w = idx >> 7, c = idx & 127;
    float v0 = (c < SO) ? W2[c*256 + 2*w    ] : 0.f;
    float v1 = (c < SO) ? W2[c*256 + 2*w + 1] : 0.f;
    unsigned hi, lo;
    bfsplit2(v0, v1, hi, lo);
    g_W2bh[idx] = hi;
    g_W2bl[idx] = lo;
}

// ---------------- kernel B: attention softmax (+ zero g_settled) -----------
#define AT_QS 0
#define AT_KT (AT_QS + 32*128)
#define AT_S  (AT_KT + 128*132)
#define AT_FLOATS (AT_S + 32*132)
#define AT_BYTES  (AT_FLOATS*4)

__global__ void __launch_bounds__(256)
attn_kernel()
{
    extern __shared__ float sm[];
    float* Qs = sm + AT_QS;
    float* Kt = sm + AT_KT;
    float* S  = sm + AT_S;

    int b  = blockIdx.x >> 2;
    int jt = (blockIdx.x & 3) * 32;
    int t  = threadIdx.x;
    int tx = t & 15, ty = t >> 4;

    for (int z = t; z < 512; z += 256) g_settled[blockIdx.x*512 + z] = 0.f;

    for (int idx = t; idx < 32*128; idx += 256) {
        int j = idx >> 7, k = idx & 127;
        Qs[j*128 + k] = g_Q[(b*SEQ + jt + j)*DL + k];
    }
    for (int idx = t; idx < 128*128; idx += 256) {
        int i = idx >> 7, k = idx & 127;
        Kt[k*132 + i] = g_K[(b*SEQ + i)*DL + k];
    }
    __syncthreads();

    float acc[2][8];
    #pragma unroll
    for (int i = 0; i < 2; i++)
        #pragma unroll
        for (int j = 0; j < 8; j++) acc[i][j] = 0.f;

    int j0 = ty*2, i0 = tx*8;
    #pragma unroll 4
    for (int k = 0; k < 128; k++) {
        float q0 = Qs[(j0  )*128 + k];
        float q1 = Qs[(j0+1)*128 + k];
        float4 k0v = *(const float4*)&Kt[k*132 + i0];
        float4 k1v = *(const float4*)&Kt[k*132 + i0 + 4];
        acc[0][0]=fmaf(q0,k0v.x,acc[0][0]); acc[0][1]=fmaf(q0,k0v.y,acc[0][1]);
        acc[0][2]=fmaf(q0,k0v.z,acc[0][2]); acc[0][3]=fmaf(q0,k0v.w,acc[0][3]);
        acc[0][4]=fmaf(q0,k1v.x,acc[0][4]); acc[0][5]=fmaf(q0,k1v.y,acc[0][5]);
        acc[0][6]=fmaf(q0,k1v.z,acc[0][6]); acc[0][7]=fmaf(q0,k1v.w,acc[0][7]);
        acc[1][0]=fmaf(q1,k0v.x,acc[1][0]); acc[1][1]=fmaf(q1,k0v.y,acc[1][1]);
        acc[1][2]=fmaf(q1,k0v.z,acc[1][2]); acc[1][3]=fmaf(q1,k0v.w,acc[1][3]);
        acc[1][4]=fmaf(q1,k1v.x,acc[1][4]); acc[1][5]=fmaf(q1,k1v.y,acc[1][5]);
        acc[1][6]=fmaf(q1,k1v.z,acc[1][6]); acc[1][7]=fmaf(q1,k1v.w,acc[1][7]);
    }
    const float sc = 0.08838834764831845f;
    #pragma unroll
    for (int i = 0; i < 2; i++) {
        *(float4*)&S[(j0+i)*132 + i0] =
            make_float4(acc[i][0]*sc, acc[i][1]*sc, acc[i][2]*sc, acc[i][3]*sc);
        *(float4*)&S[(j0+i)*132 + i0 + 4] =
            make_float4(acc[i][4]*sc, acc[i][5]*sc, acc[i][6]*sc, acc[i][7]*sc);
    }
    __syncthreads();

    int w = t >> 5, lane = t & 31;
    for (int q = 0; q < 4; q++) {
        int r = w*4 + q;
        float v0 = S[r*132 + lane      ];
        float v1 = S[r*132 + lane + 32 ];
        float v2 = S[r*132 + lane + 64 ];
        float v3 = S[r*132 + lane + 96 ];
        float mx = fmaxf(fmaxf(v0,v1), fmaxf(v2,v3));
        #pragma unroll
        for (int off = 16; off; off >>= 1)
            mx = fmaxf(mx, __shfl_xor_sync(0xffffffffu, mx, off));
        float e0 = expf(v0-mx), e1 = expf(v1-mx), e2 = expf(v2-mx), e3 = expf(v3-mx);
        float sum = e0+e1+e2+e3;
        #pragma unroll
        for (int off = 16; off; off >>= 1)
            sum += __shfl_xor_sync(0xffffffffu, sum, off);
        float inv = 1.f/sum;
        float* dst = g_attn + (b*SEQ + jt + r)*SEQ;
        dst[lane     ] = e0*inv;
        dst[lane + 32] = e1*inv;
        dst[lane + 64] = e2*inv;
        dst[lane + 96] = e3*inv;
    }
}

// ---------------- kernel C: pairwise MLP GEMM via split-BF16 m16n8k16 ------
// (R14 proven, unchanged)
#define PK_UJB 0
#define PK_B2  (PK_UJB + 256)
#define PK_HWH (PK_B2 + 128)
#define PK_HWL (PK_HWH + 128*20)
#define PK_BWH (PK_HWL + 128*20)
#define PK_BWL (PK_BWH + 16*136)
#define PK_FLOATS (PK_BWL + 16*136)
#define PK_BYTES  (PK_FLOATS*4)

__global__ void __launch_bounds__(256, 2)
pair_kernel(const float* __restrict__ b1, const float* __restrict__ b2)
{
    extern __shared__ float psm[];
    float*    Ujb = psm + PK_UJB;
    float*    b2s = psm + PK_B2;
    unsigned* Hwh = (unsigned*)(psm + PK_HWH);
    unsigned* Hwl = (unsigned*)(psm + PK_HWL);
    unsigned* Bwh = (unsigned*)(psm + PK_BWH);
    unsigned* Bwl = (unsigned*)(psm + PK_BWL);

    int row = blockIdx.x;          // b*128 + j
    int b   = row >> 7;
    int t   = threadIdx.x;
    int lane = t & 31, w = t >> 5;
    int g = lane >> 2, tt = lane & 3;
    int ibase = w * 16;

    Ujb[t] = g_U[row*256 + t] + b1[t];
    if (t < 128) b2s[t] = (t < SO) ? b2[t] : 0.f;

    float acc[15][4];
    #pragma unroll
    for (int n = 0; n < 15; n++)
        #pragma unroll
        for (int q = 0; q < 4; q++) acc[n][q] = 0.f;

    for (int k0 = 0; k0 < 256; k0 += 32) {
        __syncthreads();
        #pragma unroll
        for (int s = 0; s < 8; s++) {
            int idx = t + 256*s;
            int i = idx >> 4, kw = idx & 15;
            float2 u  = *(const float2*)&g_U[(b*SEQ + i)*256 + k0 + 2*kw];
            float2 uj = *(const float2*)&Ujb[k0 + 2*kw];
            float h0 = ftanh(uj.x - u.x);
            float h1 = ftanh(uj.y - u.y);
            unsigned hi, lo;
            bfsplit2(h0, h1, hi, lo);
            Hwh[i*20 + kw] = hi;
            Hwl[i*20 + kw] = lo;
        }
        #pragma unroll
        for (int s = 0; s < 8; s++) {
            int idx = t + 256*s;
            int kw = idx >> 7, c = idx & 127;
            Bwh[kw*136 + c] = g_W2bh[(k0/2 + kw)*128 + c];
            Bwl[kw*136 + c] = g_W2bl[(k0/2 + kw)*128 + c];
        }
        __syncthreads();

        #pragma unroll
        for (int s = 0; s < 2; s++) {
            int hb = (ibase + g)*20 + 8*s;
            unsigned ah[4], al[4];
            ah[0] = Hwh[hb + tt];           al[0] = Hwl[hb + tt];
            ah[1] = Hwh[hb + 160 + tt];     al[1] = Hwl[hb + 160 + tt];
            ah[2] = Hwh[hb + tt + 4];       al[2] = Hwl[hb + tt + 4];
            ah[3] = Hwh[hb + 160 + tt + 4]; al[3] = Hwl[hb + 160 + tt + 4];
            int kb0 = (8*s + tt    )*136;
            int kb1 = (8*s + tt + 4)*136;
            #pragma unroll
            for (int n = 0; n < 15; n++) {
                int cb = n*8 + g;
                unsigned bh[2] = { Bwh[kb0 + cb], Bwh[kb1 + cb] };
                unsigned bl[2] = { Bwl[kb0 + cb], Bwl[kb1 + cb] };
                mma16(acc[n], ah, bl);
                mma16(acc[n], al, bh);
                mma16(acc[n], ah, bh);
            }
        }
    }

    size_t p0 = (size_t)row*SEQ + ibase + g;
    size_t p1 = p0 + 8;
    #pragma unroll
    for (int n = 0; n < 15; n++) {
        int c = 8*n + 2*tt;
        float bb0 = b2s[c], bb1 = b2s[c+1];
        *(float2*)&g_lie[p0*SO + c] = make_float2(acc[n][0] + bb0, acc[n][1] + bb1);
        *(float2*)&g_lie[p1*SO + c] = make_float2(acc[n][2] + bb0, acc[n][3] + bb1);
    }
}

// ---------------- expm bf16 helpers ----------------------------------------
// pack A-fragment (m16n8k16 layout) from C-layout regs D[2][4]
__device__ __forceinline__ void packA(const float D[2][4], unsigned ah[4], unsigned al[4]) {
    bfsplit2(D[0][0], D[0][1], ah[0], al[0]);   // row g,   k=2t,2t+1
    bfsplit2(D[0][2], D[0][3], ah[1], al[1]);   // row g+8, k=2t,2t+1
    bfsplit2(D[1][0], D[1][1], ah[2], al[2]);   // row g,   k=2t+8,2t+9
    bfsplit2(D[1][2], D[1][3], ah[3], al[3]);   // row g+8, k=2t+8,2t+9
}

// D += X * Y with X A-frag given, Y as packed B-buffer (outer*12 + word idx)
__device__ __forceinline__ void mm16b(float D[2][4],
                                      const unsigned ah[4], const unsigned al[4],
                                      const unsigned* Yh, const unsigned* Yl,
                                      int g, int t) {
    #pragma unroll
    for (int j = 0; j < 2; j++) {
        int base = (8*j + g)*12;
        unsigned bh[2] = { Yh[base + t], Yh[base + t + 4] };
        unsigned bl[2] = { Yl[base + t], Yl[base + t + 4] };
        mma16(D[j], ah, bl);
        mma16(D[j], al, bh);
        mma16(D[j], ah, bh);
    }
}

// true k-pack store (for general matrices used as B operand): element (r,c)
// -> halfword (c*12 + (r>>1))*2 + (r&1) in hi/lo u16 arrays
__device__ __forceinline__ void kpack_store(unsigned short* Yh, unsigned short* Yl,
                                            const float D[2][4], int g, int t) {
    #pragma unroll
    for (int j = 0; j < 2; j++)
        #pragma unroll
        for (int q = 0; q < 4; q++) {
            int r = g + 8*(q >> 1);
            int c = 2*t + (q & 1) + 8*j;
            float x = D[j][q];
            unsigned hb = __float_as_uint(x) & 0xffff0000u;
            float lof = x - __uint_as_float(hb);
            unsigned lb = __float_as_uint(lof);
            int hw = (c*12 + (r >> 1))*2 + (r & 1);
            Yh[hw] = (unsigned short)(hb >> 16);
            Yl[hw] = (unsigned short)(lb >> 16);
        }
}

// ---------------- kernel D: expm via split-BF16 m16n8k16 (reg-gather) ------
#define EXPM_BLOCKS 1024
#define NPAIRS (NB*SEQ*SEQ)      // 65536

__global__ void __launch_bounds__(128)
expm_kernel(const float* __restrict__ xm_g, float* __restrict__ Tout)
{
    // per warp: A2h[192] | A2l[192] | Tbh[192] | Tbl[192]  (12 KB/block)
    __shared__ __align__(16) unsigned mmB[4*4*192];
    int tid = threadIdx.x, lane = tid & 31, w = tid >> 5;
    unsigned* A2hB = mmB + w*768;
    unsigned* A2lB = A2hB + 192;
    unsigned* TbhB = A2lB + 192;
    unsigned* TblB = TbhB + 192;
    unsigned short* Tbh16 = (unsigned short*)TbhB;
    unsigned short* Tbl16 = (unsigned short*)TblB;

    int g = lane >> 2;       // row group 0..7 (rows g, g+8)
    int t = lane & 3;        // col group

    const float c3=1.f/6.f, c4=1.f/24.f, c5=1.f/120.f;
    const float c6=1.f/720.f, c7=1.f/5040.f, c8=1.f/40320.f, c9=1.f/362880.f;
    const unsigned FLIP = 0x80008000u;

    float dg[2][4];
    int   goff[2][4];
    float gsgn[2][4];
    #pragma unroll
    for (int j = 0; j < 2; j++)
        #pragma unroll
        for (int q = 0; q < 4; q++) {
            int r = g + 8*(q >> 1);
            int c = 2*t + (q & 1) + 8*j;
            dg[j][q] = (r == c) ? 1.f : 0.f;
            if (r == c) { goff[j][q] = 0; gsgn[j][q] = 0.f; }
            else {
                int lo_ = r < c ? r : c;
                int hi_ = r < c ? c : r;
                // triangular index: base(lo) + (hi - lo - 1), base(r)=15r - r(r-1)/2
                goff[j][q] = lo_*15 - (lo_*(lo_-1))/2 + (hi_ - lo_ - 1);
                gsgn[j][q] = (r < c) ? 1.f : -1.f;
            }
        }

    for (int p = blockIdx.x*4 + w; p < NPAIRS; p += EXPM_BLOCKS*4) {
        int row = p >> 7;
        int i   = p & 127;
        int b   = row >> 7;

        // ---- gather lie -> A C-layout directly in registers ----
        const float* lr = g_lie + (size_t)p*SO;
        float Acr[2][4];
        #pragma unroll
        for (int j = 0; j < 2; j++)
            #pragma unroll
            for (int q = 0; q < 4; q++)
                Acr[j][q] = gsgn[j][q] * __ldg(&lr[goff[j][q]]);

        // ---- norm, scale ----
        float rs0 = fabsf(Acr[0][0])+fabsf(Acr[0][1])+fabsf(Acr[1][0])+fabsf(Acr[1][1]);
        float rs1 = fabsf(Acr[0][2])+fabsf(Acr[0][3])+fabsf(Acr[1][2])+fabsf(Acr[1][3]);
        #pragma unroll
        for (int off = 1; off <= 2; off <<= 1) {
            rs0 += __shfl_xor_sync(0xffffffffu, rs0, off);
            rs1 += __shfl_xor_sync(0xffffffffu, rs1, off);
        }
        float mx = fmaxf(rs0, rs1);
        #pragma unroll
        for (int off = 4; off <= 16; off <<= 1)
            mx = fmaxf(mx, __shfl_xor_sync(0xffffffffu, mx, off));
        int sct = 0;
        if (mx > 1.f) { sct = (int)ceilf(log2f(mx)); if (sct > 12) sct = 12; }
        float scale = __uint_as_float((uint32_t)(127 - sct) << 23);
        #pragma unroll
        for (int j = 0; j < 2; j++)
            #pragma unroll
            for (int q = 0; q < 4; q++) Acr[j][q] *= scale;

        // ---- A-frag of A (registers only) ----
        unsigned aAh[4], aAl[4];
        packA(Acr, aAh, aAl);

        // ---- A2 = A*A ; B-operand = -A = flip of own A-frag words ----
        float A2cr[2][4] = {{0.f,0.f,0.f,0.f},{0.f,0.f,0.f,0.f}};
        {
            unsigned bh0[2] = { aAh[0]^FLIP, aAh[2]^FLIP };
            unsigned bl0[2] = { aAl[0]^FLIP, aAl[2]^FLIP };
            mma16(A2cr[0], aAh, bl0); mma16(A2cr[0], aAl, bh0); mma16(A2cr[0], aAh, bh0);
            unsigned bh1[2] = { aAh[1]^FLIP, aAh[3]^FLIP };
            unsigned bl1[2] = { aAl[1]^FLIP, aAl[3]^FLIP };
            mma16(A2cr[1], aAh, bl1); mma16(A2cr[1], aAl, bh1); mma16(A2cr[1], aAh, bh1);
        }

        // ---- store A2 row-pack (== its B-pack: A2 exactly symmetric) ----
        {
            unsigned w0h,w0l,w1h,w1l,w2h,w2l,w3h,w3l;
            bfsplit2(A2cr[0][0], A2cr[0][1], w0h, w0l);
            bfsplit2(A2cr[0][2], A2cr[0][3], w1h, w1l);
            bfsplit2(A2cr[1][0], A2cr[1][1], w2h, w2l);
            bfsplit2(A2cr[1][2], A2cr[1][3], w3h, w3l);
            A2hB[(g  )*12 + t    ] = w0h;  A2lB[(g  )*12 + t    ] = w0l;
            A2hB[(g+8)*12 + t    ] = w1h;  A2lB[(g+8)*12 + t    ] = w1l;
            A2hB[(g  )*12 + t + 4] = w2h;  A2lB[(g  )*12 + t + 4] = w2l;
            A2hB[(g+8)*12 + t + 4] = w3h;  A2lB[(g+8)*12 + t + 4] = w3l;
        }
        __syncwarp();

        // ---- A3 = A*A2 ----
        float A3cr[2][4] = {{0.f,0.f,0.f,0.f},{0.f,0.f,0.f,0.f}};
        mm16b(A3cr, aAh, aAl, A2hB, A2lB, g, t);

        // ---- B2 = c6 I + c7 A + c8 A2 + c9 A3 -> Tb (k-pack) ----
        {
            float E[2][4];
            #pragma unroll
            for (int j = 0; j < 2; j++)
                #pragma unroll
                for (int q = 0; q < 4; q++)
                    E[j][q] = fmaf(c6, dg[j][q],
                              fmaf(c7, Acr[j][q],
                              fmaf(c8, A2cr[j][q], c9 * A3cr[j][q])));
            kpack_store(Tbh16, Tbl16, E, g, t);
        }
        unsigned a3h[4], a3l[4];
        packA(A3cr, a3h, a3l);
        __syncwarp();

        // ---- M = A3*B2 + (c3 I + c4 A + c5 A2) ----
        float R[2][4];
        #pragma unroll
        for (int j = 0; j < 2; j++)
            #pragma unroll
            for (int q = 0; q < 4; q++)
                R[j][q] = fmaf(c3, dg[j][q],
                          fmaf(c4, Acr[j][q], c5 * A2cr[j][q]));
        mm16b(R, a3h, a3l, TbhB, TblB, g, t);
        __syncwarp();                 // all lanes done reading B2
        kpack_store(Tbh16, Tbl16, R, g, t);
        __syncwarp();

        // ---- R = A3*M + (I + A + A2/2) ----
        #pragma unroll
        for (int j = 0; j < 2; j++)
            #pragma unroll
            for (int q = 0; q < 4; q++)
                R[j][q] = fmaf(0.5f, A2cr[j][q], Acr[j][q]) + dg[j][q];
        mm16b(R, a3h, a3l, TbhB, TblB, g, t);

        // ---- squarings: A-frag from regs, B from k-pack ----
        for (int q = 0; q < sct; q++) {
            __syncwarp();
            kpack_store(Tbh16, Tbl16, R, g, t);
            unsigned rh[4], rl[4];
            packA(R, rh, rl);
            __syncwarp();
            float Rn[2][4] = {{0.f,0.f,0.f,0.f},{0.f,0.f,0.f,0.f}};
            mm16b(Rn, rh, rl, TbhB, TblB, g, t);
            #pragma unroll
            for (int j = 0; j < 2; j++)
                #pragma unroll
                for (int qq = 0; qq < 4; qq++) R[j][qq] = Rn[j][qq];
        }

        // ---- write T_all ----
        float* dst = Tout + (size_t)p*256;
        *(float2*)&dst[(g  )*16 + 2*t    ] = make_float2(R[0][0], R[0][1]);
        *(float2*)&dst[(g  )*16 + 2*t + 8] = make_float2(R[1][0], R[1][1]);
        *(float2*)&dst[(g+8)*16 + 2*t    ] = make_float2(R[0][2], R[0][3]);
        *(float2*)&dst[(g+8)*16 + 2*t + 8] = make_float2(R[1][2], R[1][3]);

        // ---- transported & settled ----
        const float* xv = xm_g + ((size_t)b*SEQ + i)*DM;
        float x0 = xv[2*t], x1 = xv[2*t+1], x2 = xv[2*t+8], x3 = xv[2*t+9];
        float pg  = R[0][0]*x0 + R[0][1]*x1 + R[1][0]*x2 + R[1][1]*x3;
        float pg8 = R[0][2]*x0 + R[0][3]*x1 + R[1][2]*x2 + R[1][3]*x3;
        #pragma unroll
        for (int off = 1; off <= 2; off <<= 1) {
            pg  += __shfl_xor_sync(0xffffffffu, pg,  off);
            pg8 += __shfl_xor_sync(0xffffffffu, pg8, off);
        }
        if (t == 0) {
            float wgt = g_attn[row*SEQ + i];
            atomicAdd(&g_settled[row*DM + g    ], wgt * pg);
            atomicAdd(&g_settled[row*DM + g + 8], wgt * pg8);
        }
        __syncwarp();
    }
}

// ---------------- kernel E: out projection ---------------------------------
__global__ void __launch_bounds__(256)
out_kernel(const float* __restrict__ Wo, const float* __restrict__ bo,
           float* __restrict__ out)
{
    int gid = blockIdx.x*256 + threadIdx.x;    // 8192
    int row = gid >> 4, d = gid & 15;
    float acc = bo[d];
    #pragma unroll
    for (int e = 0; e < DM; e++)
        acc = fmaf(Wo[d*DM + e], g_settled[row*DM + e], acc);
    out[gid] = acc;
}

// ---------------- launch ----------------------------------------------------
extern "C" void kernel_launch(void* const* d_in, const int* in_sizes, int n_in,
                              void* d_out, int out_size)
{
    const float* xl  = (const float*)d_in[0];
    const float* xmm = (const float*)d_in[1];
    const float* Wq  = (const float*)d_in[2];
    const float* bq  = (const float*)d_in[3];
    const float* Wk  = (const float*)d_in[4];
    const float* bk  = (const float*)d_in[5];
    const float* W1  = (const float*)d_in[6];
    const float* b1  = (const float*)d_in[7];
    const float* W2  = (const float*)d_in[8];
    const float* b2  = (const float*)d_in[9];
    const float* Wo  = (const float*)d_in[10];
    const float* bo  = (const float*)d_in[11];

    float* out  = (float*)d_out;
    float* Tout = out + NB*SEQ*DM;      // T_all follows out

    static bool attr_set = false;
    if (!attr_set) {
        cudaFuncSetAttribute(attn_kernel, cudaFuncAttributeMaxDynamicSharedMemorySize, AT_BYTES);
        cudaFuncSetAttribute(pair_kernel, cudaFuncAttributeMaxDynamicSharedMemorySize, PK_BYTES);
        attr_set = true;
    }

    prep_kernel<<<dim3(8,8), 256>>>(xl, Wq, bq, Wk, bk, W1);
    w2split_kernel<<<64, 256>>>(W2);
    attn_kernel<<<16, 256, AT_BYTES>>>();
    pair_kernel<<<ROWS, 256, PK_BYTES>>>(b1, b2);
    expm_kernel<<<EXPM_BLOCKS, 128>>>(xmm, Tout);
    out_kernel<<<32, 256>>>(Wo, bo, out);
}

// round 17
// speedup vs baseline: 1.8932x; 1.0273x over previous
#include <cuda_runtime.h>
#include <math.h>
#include <stdint.h>

#define NB 4
#define SEQ 128
#define DL 128
#define DM 16
#define SO 120
#define ROWS (NB*SEQ)        // 512

// ---------------- scratch ----------------------------------------------------
__device__ float g_Q[ROWS*DL];
__device__ float g_K[ROWS*DL];
__device__ float g_U[ROWS*256];
__device__ float g_attn[NB*SEQ*SEQ];
__device__ float g_lie[(size_t)NB*SEQ*SEQ*SO];   // 31.5 MB
__device__ float g_settled[ROWS*DM];
__device__ unsigned g_W2bh[128*128];             // W2^T bf16x2 hi words [kword][c]
__device__ unsigned g_W2bl[128*128];             // W2^T bf16x2 lo words [kword][c]

__device__ __forceinline__ float ftanh(float x) {
    float y;
    asm("tanh.approx.f32 %0, %1;" : "=f"(y) : "f"(x));
    return y;
}

// bf16x2 split-pack: word = {x1_bf16, x0_bf16}; hi = truncated top-16,
// lo = bf16 of exact remainder. Dropped error ~2^-16 per element.
__device__ __forceinline__ void bfsplit2(float x0, float x1, unsigned& hi, unsigned& lo) {
    unsigned h0 = __float_as_uint(x0) & 0xffff0000u;
    unsigned h1 = __float_as_uint(x1) & 0xffff0000u;
    hi = h1 | (h0 >> 16);
    float l0 = x0 - __uint_as_float(h0);
    float l1 = x1 - __uint_as_float(h1);
    lo = (__float_as_uint(l1) & 0xffff0000u) | (__float_as_uint(l0) >> 16);
}

__device__ __forceinline__ void mma16(float* d, const unsigned* a, const unsigned* b) {
    asm("mma.sync.aligned.m16n8k16.row.col.f32.bf16.bf16.f32 "
        "{%0,%1,%2,%3}, {%4,%5,%6,%7}, {%8,%9}, {%0,%1,%2,%3};"
        : "+f"(d[0]), "+f"(d[1]), "+f"(d[2]), "+f"(d[3])
        : "r"(a[0]), "r"(a[1]), "r"(a[2]), "r"(a[3]), "r"(b[0]), "r"(b[1]));
}

// ---------------- kernel A: tiled GEMM  C[512 x 512] = X @ [Wq;Wk;W1]^T ----
__global__ void __launch_bounds__(256)
prep_kernel(const float* __restrict__ xl,
            const float* __restrict__ Wq, const float* __restrict__ bq,
            const float* __restrict__ Wk, const float* __restrict__ bk,
            const float* __restrict__ W1)
{
    __shared__ __align__(16) float Xs[64*64];
    __shared__ __align__(16) float Wt[64*68];

    int bx = blockIdx.x, by = blockIdx.y;
    int t  = threadIdx.x;
    int tx = t & 15, ty = t >> 4;

    const float* src;
    if      (by < 2) src = Wq + (by    )*64*DL;
    else if (by < 4) src = Wk + (by - 2)*64*DL;
    else             src = W1 + (by - 4)*64*DL;

    float acc[4][4];
    #pragma unroll
    for (int i = 0; i < 4; i++)
        #pragma unroll
        for (int j = 0; j < 4; j++) acc[i][j] = 0.f;

    for (int k0 = 0; k0 < DL; k0 += 64) {
        __syncthreads();
        #pragma unroll
        for (int s = 0; s < 16; s++) {
            int idx = t + 256*s;
            int r = idx >> 6, k = idx & 63;
            Xs[r*64 + k] = xl[(bx*64 + r)*DL + k0 + k];
            Wt[k*68 + r] = src[r*DL + k0 + k];
        }
        __syncthreads();

        #pragma unroll 8
        for (int k = 0; k < 64; k++) {
            float4 bv = *(const float4*)&Wt[k*68 + tx*4];
            #pragma unroll
            for (int i = 0; i < 4; i++) {
                float a = Xs[(ty*4 + i)*64 + k];
                acc[i][0] = fmaf(a, bv.x, acc[i][0]);
                acc[i][1] = fmaf(a, bv.y, acc[i][1]);
                acc[i][2] = fmaf(a, bv.z, acc[i][2]);
                acc[i][3] = fmaf(a, bv.w, acc[i][3]);
            }
        }
    }

    #pragma unroll
    for (int i = 0; i < 4; i++) {
        int rowg = bx*64 + ty*4 + i;
        int c0   = tx*4;
        if (by < 2) {
            int col = by*64 + c0;
            *(float4*)&g_Q[rowg*DL + col] =
                make_float4(acc[i][0]+bq[col], acc[i][1]+bq[col+1],
                            acc[i][2]+bq[col+2], acc[i][3]+bq[col+3]);
        } else if (by < 4) {
            int col = (by-2)*64 + c0;
            *(float4*)&g_K[rowg*DL + col] =
                make_float4(acc[i][0]+bk[col], acc[i][1]+bk[col+1],
                            acc[i][2]+bk[col+2], acc[i][3]+bk[col+3]);
        } else {
            int col = (by-4)*64 + c0;
            *(float4*)&g_U[rowg*256 + col] =
                make_float4(acc[i][0], acc[i][1], acc[i][2], acc[i][3]);
        }
    }
}

// ---------------- kernel B: attention softmax + W2 pack + settled zero -----
#define AT_QS 0
#define AT_KT (AT_QS + 32*128)
#define AT_S  (AT_KT + 128*132)
#define AT_FLOATS (AT_S + 32*132)
#define AT_BYTES  (AT_FLOATS*4)

__global__ void __launch_bounds__(256)
attn_kernel(const float* __restrict__ W2)
{
    extern __shared__ float sm[];
    float* Qs = sm + AT_QS;
    float* Kt = sm + AT_KT;
    float* S  = sm + AT_S;

    int b  = blockIdx.x >> 2;
    int jt = (blockIdx.x & 3) * 32;
    int t  = threadIdx.x;
    int tx = t & 15, ty = t >> 4;

    for (int z = t; z < 512; z += 256) g_settled[blockIdx.x*512 + z] = 0.f;

    // fold W2 bf16 split-pack here (independent of Q/K)
    for (int z = t; z < 1024; z += 256) {
        int idx = blockIdx.x*1024 + z;       // 16 blocks x 1024 = 16384
        int wv = idx >> 7, c = idx & 127;
        float v0 = (c < SO) ? W2[c*256 + 2*wv    ] : 0.f;
        float v1 = (c < SO) ? W2[c*256 + 2*wv + 1] : 0.f;
        unsigned hi, lo;
        bfsplit2(v0, v1, hi, lo);
        g_W2bh[idx] = hi;
        g_W2bl[idx] = lo;
    }

    for (int idx = t; idx < 32*128; idx += 256) {
        int j = idx >> 7, k = idx & 127;
        Qs[j*128 + k] = g_Q[(b*SEQ + jt + j)*DL + k];
    }
    for (int idx = t; idx < 128*128; idx += 256) {
        int i = idx >> 7, k = idx & 127;
        Kt[k*132 + i] = g_K[(b*SEQ + i)*DL + k];
    }
    __syncthreads();

    float acc[2][8];
    #pragma unroll
    for (int i = 0; i < 2; i++)
        #pragma unroll
        for (int j = 0; j < 8; j++) acc[i][j] = 0.f;

    int j0 = ty*2, i0 = tx*8;
    #pragma unroll 4
    for (int k = 0; k < 128; k++) {
        float q0 = Qs[(j0  )*128 + k];
        float q1 = Qs[(j0+1)*128 + k];
        float4 k0v = *(const float4*)&Kt[k*132 + i0];
        float4 k1v = *(const float4*)&Kt[k*132 + i0 + 4];
        acc[0][0]=fmaf(q0,k0v.x,acc[0][0]); acc[0][1]=fmaf(q0,k0v.y,acc[0][1]);
        acc[0][2]=fmaf(q0,k0v.z,acc[0][2]); acc[0][3]=fmaf(q0,k0v.w,acc[0][3]);
        acc[0][4]=fmaf(q0,k1v.x,acc[0][4]); acc[0][5]=fmaf(q0,k1v.y,acc[0][5]);
        acc[0][6]=fmaf(q0,k1v.z,acc[0][6]); acc[0][7]=fmaf(q0,k1v.w,acc[0][7]);
        acc[1][0]=fmaf(q1,k0v.x,acc[1][0]); acc[1][1]=fmaf(q1,k0v.y,acc[1][1]);
        acc[1][2]=fmaf(q1,k0v.z,acc[1][2]); acc[1][3]=fmaf(q1,k0v.w,acc[1][3]);
        acc[1][4]=fmaf(q1,k1v.x,acc[1][4]); acc[1][5]=fmaf(q1,k1v.y,acc[1][5]);
        acc[1][6]=fmaf(q1,k1v.z,acc[1][6]); acc[1][7]=fmaf(q1,k1v.w,acc[1][7]);
    }
    const float sc = 0.08838834764831845f;
    #pragma unroll
    for (int i = 0; i < 2; i++) {
        *(float4*)&S[(j0+i)*132 + i0] =
            make_float4(acc[i][0]*sc, acc[i][1]*sc, acc[i][2]*sc, acc[i][3]*sc);
        *(float4*)&S[(j0+i)*132 + i0 + 4] =
            make_float4(acc[i][4]*sc, acc[i][5]*sc, acc[i][6]*sc, acc[i][7]*sc);
    }
    __syncthreads();

    int w = t >> 5, lane = t & 31;
    for (int q = 0; q < 4; q++) {
        int r = w*4 + q;
        float v0 = S[r*132 + lane      ];
        float v1 = S[r*132 + lane + 32 ];
        float v2 = S[r*132 + lane + 64 ];
        float v3 = S[r*132 + lane + 96 ];
        float mx = fmaxf(fmaxf(v0,v1), fmaxf(v2,v3));
        #pragma unroll
        for (int off = 16; off; off >>= 1)
            mx = fmaxf(mx, __shfl_xor_sync(0xffffffffu, mx, off));
        float e0 = expf(v0-mx), e1 = expf(v1-mx), e2 = expf(v2-mx), e3 = expf(v3-mx);
        float sum = e0+e1+e2+e3;
        #pragma unroll
        for (int off = 16; off; off >>= 1)
            sum += __shfl_xor_sync(0xffffffffu, sum, off);
        float inv = 1.f/sum;
        float* dst = g_attn + (b*SEQ + jt + r)*SEQ;
        dst[lane     ] = e0*inv;
        dst[lane + 32] = e1*inv;
        dst[lane + 64] = e2*inv;
        dst[lane + 96] = e3*inv;
    }
}

// ---------------- kernel C: pairwise MLP GEMM via split-BF16 m16n8k16 ------
// (R14 proven, unchanged)
#define PK_UJB 0
#define PK_B2  (PK_UJB + 256)
#define PK_HWH (PK_B2 + 128)
#define PK_HWL (PK_HWH + 128*20)
#define PK_BWH (PK_HWL + 128*20)
#define PK_BWL (PK_BWH + 16*136)
#define PK_FLOATS (PK_BWL + 16*136)
#define PK_BYTES  (PK_FLOATS*4)

__global__ void __launch_bounds__(256, 2)
pair_kernel(const float* __restrict__ b1, const float* __restrict__ b2)
{
    extern __shared__ float psm[];
    float*    Ujb = psm + PK_UJB;
    float*    b2s = psm + PK_B2;
    unsigned* Hwh = (unsigned*)(psm + PK_HWH);
    unsigned* Hwl = (unsigned*)(psm + PK_HWL);
    unsigned* Bwh = (unsigned*)(psm + PK_BWH);
    unsigned* Bwl = (unsigned*)(psm + PK_BWL);

    int row = blockIdx.x;          // b*128 + j
    int b   = row >> 7;
    int t   = threadIdx.x;
    int lane = t & 31, w = t >> 5;
    int g = lane >> 2, tt = lane & 3;
    int ibase = w * 16;

    Ujb[t] = g_U[row*256 + t] + b1[t];
    if (t < 128) b2s[t] = (t < SO) ? b2[t] : 0.f;

    float acc[15][4];
    #pragma unroll
    for (int n = 0; n < 15; n++)
        #pragma unroll
        for (int q = 0; q < 4; q++) acc[n][q] = 0.f;

    for (int k0 = 0; k0 < 256; k0 += 32) {
        __syncthreads();
        #pragma unroll
        for (int s = 0; s < 8; s++) {
            int idx = t + 256*s;
            int i = idx >> 4, kw = idx & 15;
            float2 u  = *(const float2*)&g_U[(b*SEQ + i)*256 + k0 + 2*kw];
            float2 uj = *(const float2*)&Ujb[k0 + 2*kw];
            float h0 = ftanh(uj.x - u.x);
            float h1 = ftanh(uj.y - u.y);
            unsigned hi, lo;
            bfsplit2(h0, h1, hi, lo);
            Hwh[i*20 + kw] = hi;
            Hwl[i*20 + kw] = lo;
        }
        #pragma unroll
        for (int s = 0; s < 8; s++) {
            int idx = t + 256*s;
            int kw = idx >> 7, c = idx & 127;
            Bwh[kw*136 + c] = g_W2bh[(k0/2 + kw)*128 + c];
            Bwl[kw*136 + c] = g_W2bl[(k0/2 + kw)*128 + c];
        }
        __syncthreads();

        #pragma unroll
        for (int s = 0; s < 2; s++) {
            int hb = (ibase + g)*20 + 8*s;
            unsigned ah[4], al[4];
            ah[0] = Hwh[hb + tt];           al[0] = Hwl[hb + tt];
            ah[1] = Hwh[hb + 160 + tt];     al[1] = Hwl[hb + 160 + tt];
            ah[2] = Hwh[hb + tt + 4];       al[2] = Hwl[hb + tt + 4];
            ah[3] = Hwh[hb + 160 + tt + 4]; al[3] = Hwl[hb + 160 + tt + 4];
            int kb0 = (8*s + tt    )*136;
            int kb1 = (8*s + tt + 4)*136;
            #pragma unroll
            for (int n = 0; n < 15; n++) {
                int cb = n*8 + g;
                unsigned bh[2] = { Bwh[kb0 + cb], Bwh[kb1 + cb] };
                unsigned bl[2] = { Bwl[kb0 + cb], Bwl[kb1 + cb] };
                mma16(acc[n], ah, bl);
                mma16(acc[n], al, bh);
                mma16(acc[n], ah, bh);
            }
        }
    }

    size_t p0 = (size_t)row*SEQ + ibase + g;
    size_t p1 = p0 + 8;
    #pragma unroll
    for (int n = 0; n < 15; n++) {
        int c = 8*n + 2*tt;
        float bb0 = b2s[c], bb1 = b2s[c+1];
        *(float2*)&g_lie[p0*SO + c] = make_float2(acc[n][0] + bb0, acc[n][1] + bb1);
        *(float2*)&g_lie[p1*SO + c] = make_float2(acc[n][2] + bb0, acc[n][3] + bb1);
    }
}

// ---------------- expm bf16 helpers ----------------------------------------
// pack A-fragment (m16n8k16 layout) from C-layout regs D[2][4]
__device__ __forceinline__ void packA(const float D[2][4], unsigned ah[4], unsigned al[4]) {
    bfsplit2(D[0][0], D[0][1], ah[0], al[0]);   // row g,   k=2t,2t+1
    bfsplit2(D[0][2], D[0][3], ah[1], al[1]);   // row g+8, k=2t,2t+1
    bfsplit2(D[1][0], D[1][1], ah[2], al[2]);   // row g,   k=2t+8,2t+9
    bfsplit2(D[1][2], D[1][3], ah[3], al[3]);   // row g+8, k=2t+8,2t+9
}

// D += X * Y with X A-frag given, Y as packed B-buffer (outer*12 + word idx)
__device__ __forceinline__ void mm16b(float D[2][4],
                                      const unsigned ah[4], const unsigned al[4],
                                      const unsigned* Yh, const unsigned* Yl,
                                      int g, int t) {
    #pragma unroll
    for (int j = 0; j < 2; j++) {
        int base = (8*j + g)*12;
        unsigned bh[2] = { Yh[base + t], Yh[base + t + 4] };
        unsigned bl[2] = { Yl[base + t], Yl[base + t + 4] };
        mma16(D[j], ah, bl);
        mma16(D[j], al, bh);
        mma16(D[j], ah, bh);
    }
}

// true k-pack store (for general matrices used as B operand): element (r,c)
// -> halfword (c*12 + (r>>1))*2 + (r&1) in hi/lo u16 arrays
__device__ __forceinline__ void kpack_store(unsigned short* Yh, unsigned short* Yl,
                                            const float D[2][4], int g, int t) {
    #pragma unroll
    for (int j = 0; j < 2; j++)
        #pragma unroll
        for (int q = 0; q < 4; q++) {
            int r = g + 8*(q >> 1);
            int c = 2*t + (q & 1) + 8*j;
            float x = D[j][q];
            unsigned hb = __float_as_uint(x) & 0xffff0000u;
            float lof = x - __uint_as_float(hb);
            unsigned lb = __float_as_uint(lof);
            int hw = (c*12 + (r >> 1))*2 + (r & 1);
            Yh[hw] = (unsigned short)(hb >> 16);
            Yl[hw] = (unsigned short)(lb >> 16);
        }
}

// ---------------- kernel D: expm via split-BF16 m16n8k16 (reg-gather) ------
#define EXPM_BLOCKS 1024
#define NPAIRS (NB*SEQ*SEQ)      // 65536

__global__ void __launch_bounds__(128)
expm_kernel(const float* __restrict__ xm_g, float* __restrict__ Tout)
{
    // per warp: A2h[192] | A2l[192] | Tbh[192] | Tbl[192]  (12 KB/block)
    __shared__ __align__(16) unsigned mmB[4*4*192];
    int tid = threadIdx.x, lane = tid & 31, w = tid >> 5;
    unsigned* A2hB = mmB + w*768;
    unsigned* A2lB = A2hB + 192;
    unsigned* TbhB = A2lB + 192;
    unsigned* TblB = TbhB + 192;
    unsigned short* Tbh16 = (unsigned short*)TbhB;
    unsigned short* Tbl16 = (unsigned short*)TblB;

    int g = lane >> 2;       // row group 0..7 (rows g, g+8)
    int t = lane & 3;        // col group

    const float c3=1.f/6.f, c4=1.f/24.f, c5=1.f/120.f;
    const float c6=1.f/720.f, c7=1.f/5040.f, c8=1.f/40320.f, c9=1.f/362880.f;
    const unsigned FLIP = 0x80008000u;

    float dg[2][4];
    int   goff[2][4];
    float gsgn[2][4];
    #pragma unroll
    for (int j = 0; j < 2; j++)
        #pragma unroll
        for (int q = 0; q < 4; q++) {
            int r = g + 8*(q >> 1);
            int c = 2*t + (q & 1) + 8*j;
            dg[j][q] = (r == c) ? 1.f : 0.f;
            if (r == c) { goff[j][q] = 0; gsgn[j][q] = 0.f; }
            else {
                int lo_ = r < c ? r : c;
                int hi_ = r < c ? c : r;
                goff[j][q] = lo_*15 - (lo_*(lo_-1))/2 + (hi_ - lo_ - 1);
                gsgn[j][q] = (r < c) ? 1.f : -1.f;
            }
        }

    for (int p = blockIdx.x*4 + w; p < NPAIRS; p += EXPM_BLOCKS*4) {
        int row = p >> 7;
        int i   = p & 127;
        int b   = row >> 7;

        // ---- gather lie -> A C-layout directly in registers (unscaled) ----
        const float* lr = g_lie + (size_t)p*SO;
        float Acr[2][4];
        #pragma unroll
        for (int j = 0; j < 2; j++)
            #pragma unroll
            for (int q = 0; q < 4; q++)
                Acr[j][q] = gsgn[j][q] * __ldg(&lr[goff[j][q]]);

        // ---- A-frag of unscaled A ----
        unsigned aAh[4], aAl[4];
        packA(Acr, aAh, aAl);

        // ---- A2 = A*A (unscaled); B-operand = -A via sign flip ----
        float A2cr[2][4] = {{0.f,0.f,0.f,0.f},{0.f,0.f,0.f,0.f}};
        {
            unsigned bh0[2] = { aAh[0]^FLIP, aAh[2]^FLIP };
            unsigned bl0[2] = { aAl[0]^FLIP, aAl[2]^FLIP };
            mma16(A2cr[0], aAh, bl0); mma16(A2cr[0], aAl, bh0); mma16(A2cr[0], aAh, bh0);
            unsigned bh1[2] = { aAh[1]^FLIP, aAh[3]^FLIP };
            unsigned bl1[2] = { aAl[1]^FLIP, aAl[3]^FLIP };
            mma16(A2cr[1], aAh, bl1); mma16(A2cr[1], aAl, bh1); mma16(A2cr[1], aAh, bh1);
        }

        // ---- spectral-norm bound from A2: ||A||_2 <= sqrt(||A^2||_inf) ----
        // (A^2 symmetric => ||A^2||_2 <= ||A^2||_inf; A normal.)
        float rs0 = fabsf(A2cr[0][0])+fabsf(A2cr[0][1])+fabsf(A2cr[1][0])+fabsf(A2cr[1][1]);
        float rs1 = fabsf(A2cr[0][2])+fabsf(A2cr[0][3])+fabsf(A2cr[1][2])+fabsf(A2cr[1][3]);
        #pragma unroll
        for (int off = 1; off <= 2; off <<= 1) {
            rs0 += __shfl_xor_sync(0xffffffffu, rs0, off);
            rs1 += __shfl_xor_sync(0xffffffffu, rs1, off);
        }
        float mx = fmaxf(rs0, rs1);
        #pragma unroll
        for (int off = 4; off <= 16; off <<= 1)
            mx = fmaxf(mx, __shfl_xor_sync(0xffffffffu, mx, off));
        int sct = 0;
        if (mx > 1.f) { sct = (int)ceilf(0.5f * log2f(mx)); if (sct > 12) sct = 12; }
        float scale  = __uint_as_float((uint32_t)(127 - sct) << 23);
        float scale2 = scale * scale;

        // exact power-of-2 rescale (commutes with bf16 split and fp32 MMA)
        #pragma unroll
        for (int j = 0; j < 2; j++)
            #pragma unroll
            for (int q = 0; q < 4; q++) {
                Acr[j][q]  *= scale;
                A2cr[j][q] *= scale2;
            }
        packA(Acr, aAh, aAl);     // repack scaled A-frag

        // ---- store A2 row-pack (== its B-pack: A2 exactly symmetric) ----
        {
            unsigned w0h,w0l,w1h,w1l,w2h,w2l,w3h,w3l;
            bfsplit2(A2cr[0][0], A2cr[0][1], w0h, w0l);
            bfsplit2(A2cr[0][2], A2cr[0][3], w1h, w1l);
            bfsplit2(A2cr[1][0], A2cr[1][1], w2h, w2l);
            bfsplit2(A2cr[1][2], A2cr[1][3], w3h, w3l);
            A2hB[(g  )*12 + t    ] = w0h;  A2lB[(g  )*12 + t    ] = w0l;
            A2hB[(g+8)*12 + t    ] = w1h;  A2lB[(g+8)*12 + t    ] = w1l;
            A2hB[(g  )*12 + t + 4] = w2h;  A2lB[(g  )*12 + t + 4] = w2l;
            A2hB[(g+8)*12 + t + 4] = w3h;  A2lB[(g+8)*12 + t + 4] = w3l;
        }
        __syncwarp();

        // ---- A3 = A*A2 ----
        float A3cr[2][4] = {{0.f,0.f,0.f,0.f},{0.f,0.f,0.f,0.f}};
        mm16b(A3cr, aAh, aAl, A2hB, A2lB, g, t);

        // ---- B2 = c6 I + c7 A + c8 A2 + c9 A3 -> Tb (k-pack) ----
        {
            float E[2][4];
            #pragma unroll
            for (int j = 0; j < 2; j++)
                #pragma unroll
                for (int q = 0; q < 4; q++)
                    E[j][q] = fmaf(c6, dg[j][q],
                              fmaf(c7, Acr[j][q],
                              fmaf(c8, A2cr[j][q], c9 * A3cr[j][q])));
            kpack_store(Tbh16, Tbl16, E, g, t);
        }
        unsigned a3h[4], a3l[4];
        packA(A3cr, a3h, a3l);
        __syncwarp();

        // ---- M = A3*B2 + (c3 I + c4 A + c5 A2) ----
        float R[2][4];
        #pragma unroll
        for (int j = 0; j < 2; j++)
            #pragma unroll
            for (int q = 0; q < 4; q++)
                R[j][q] = fmaf(c3, dg[j][q],
                          fmaf(c4, Acr[j][q], c5 * A2cr[j][q]));
        mm16b(R, a3h, a3l, TbhB, TblB, g, t);
        __syncwarp();                 // all lanes done reading B2
        kpack_store(Tbh16, Tbl16, R, g, t);
        __syncwarp();

        // ---- R = A3*M + (I + A + A2/2) ----
        #pragma unroll
        for (int j = 0; j < 2; j++)
            #pragma unroll
            for (int q = 0; q < 4; q++)
                R[j][q] = fmaf(0.5f, A2cr[j][q], Acr[j][q]) + dg[j][q];
        mm16b(R, a3h, a3l, TbhB, TblB, g, t);

        // ---- squarings: A-frag from regs, B from k-pack ----
        for (int q = 0; q < sct; q++) {
            __syncwarp();
            kpack_store(Tbh16, Tbl16, R, g, t);
            unsigned rh[4], rl[4];
            packA(R, rh, rl);
            __syncwarp();
            float Rn[2][4] = {{0.f,0.f,0.f,0.f},{0.f,0.f,0.f,0.f}};
            mm16b(Rn, rh, rl, TbhB, TblB, g, t);
            #pragma unroll
            for (int j = 0; j < 2; j++)
                #pragma unroll
                for (int qq = 0; qq < 4; qq++) R[j][qq] = Rn[j][qq];
        }

        // ---- write T_all ----
        float* dst = Tout + (size_t)p*256;
        *(float2*)&dst[(g  )*16 + 2*t    ] = make_float2(R[0][0], R[0][1]);
        *(float2*)&dst[(g  )*16 + 2*t + 8] = make_float2(R[1][0], R[1][1]);
        *(float2*)&dst[(g+8)*16 + 2*t    ] = make_float2(R[0][2], R[0][3]);
        *(float2*)&dst[(g+8)*16 + 2*t + 8] = make_float2(R[1][2], R[1][3]);

        // ---- transported & settled ----
        const float* xv = xm_g + ((size_t)b*SEQ + i)*DM;
        float x0 = xv[2*t], x1 = xv[2*t+1], x2 = xv[2*t+8], x3 = xv[2*t+9];
        float pg  = R[0][0]*x0 + R[0][1]*x1 + R[1][0]*x2 + R[1][1]*x3;
        float pg8 = R[0][2]*x0 + R[0][3]*x1 + R[1][2]*x2 + R[1][3]*x3;
        #pragma unroll
        for (int off = 1; off <= 2; off <<= 1) {
            pg  += __shfl_xor_sync(0xffffffffu, pg,  off);
            pg8 += __shfl_xor_sync(0xffffffffu, pg8, off);
        }
        if (t == 0) {
            float wgt = g_attn[row*SEQ + i];
            atomicAdd(&g_settled[row*DM + g    ], wgt * pg);
            atomicAdd(&g_settled[row*DM + g + 8], wgt * pg8);
        }
        __syncwarp();
    }
}

// ---------------- kernel E: out projection ---------------------------------
__global__ void __launch_bounds__(256)
out_kernel(const float* __restrict__ Wo, const float* __restrict__ bo,
           float* __restrict__ out)
{
    int gid = blockIdx.x*256 + threadIdx.x;    // 8192
    int row = gid >> 4, d = gid & 15;
    float acc = bo[d];
    #pragma unroll
    for (int e = 0; e < DM; e++)
        acc = fmaf(Wo[d*DM + e], g_settled[row*DM + e], acc);
    out[gid] = acc;
}

// ---------------- launch ----------------------------------------------------
extern "C" void kernel_launch(void* const* d_in, const int* in_sizes, int n_in,
                              void* d_out, int out_size)
{
    const float* xl  = (const float*)d_in[0];
    const float* xmm = (const float*)d_in[1];
    const float* Wq  = (const float*)d_in[2];
    const float* bq  = (const float*)d_in[3];
    const float* Wk  = (const float*)d_in[4];
    const float* bk  = (const float*)d_in[5];
    const float* W1  = (const float*)d_in[6];
    const float* b1  = (const float*)d_in[7];
    const float* W2  = (const float*)d_in[8];
    const float* b2  = (const float*)d_in[9];
    const float* Wo  = (const float*)d_in[10];
    const float* bo  = (const float*)d_in[11];

    float* out  = (float*)d_out;
    float* Tout = out + NB*SEQ*DM;      // T_all follows out

    static bool attr_set = false;
    if (!attr_set) {
        cudaFuncSetAttribute(attn_kernel, cudaFuncAttributeMaxDynamicSharedMemorySize, AT_BYTES);
        cudaFuncSetAttribute(pair_kernel, cudaFuncAttributeMaxDynamicSharedMemorySize, PK_BYTES);
        attr_set = true;
    }

    prep_kernel<<<dim3(8,8), 256>>>(xl, Wq, bq, Wk, bk, W1);
    attn_kernel<<<16, 256, AT_BYTES>>>(W2);
    pair_kernel<<<ROWS, 256, PK_BYTES>>>(b1, b2);
    expm_kernel<<<EXPM_BLOCKS, 128>>>(xmm, Tout);
    out_kernel<<<32, 256>>>(Wo, bo, out);
}